// round 3
// baseline (speedup 1.0000x reference)
#include <cuda_runtime.h>
#include <math.h>

#define S_LEN   2048
#define DMODEL  1024
#define NHEADS  16
#define HDIM    64
#define WINDOW  256
#define LN_EPS  1e-5f

// ---------------- scratch (no allocations allowed) ----------------
__device__ float g_qkv[(size_t)S_LEN * 3 * DMODEL];   // [S, 3*D]  (q | k | v)
__device__ float g_attn[(size_t)S_LEN * DMODEL];      // attention output [S, D]
__device__ float g_res[(size_t)S_LEN * DMODEL];       // residual pre-LN [S, D]

// =====================================================================
// SGEMM: C[M,N] = A[M,K] @ B[K,N] (+ Cadd), row-major, 128x128x16 tile,
// 256 threads, 8x8 per-thread microtile.
// =====================================================================
__global__ void __launch_bounds__(256) sgemm_kernel(
    const float* __restrict__ A, const float* __restrict__ B,
    float* __restrict__ C, const float* __restrict__ Cadd,
    int M, int N, int K)
{
    __shared__ float As[16][128];
    __shared__ float Bs[16][128];

    const int tid = threadIdx.x;
    const int m0 = blockIdx.y * 128;
    const int n0 = blockIdx.x * 128;
    const int tx = tid & 15;
    const int ty = tid >> 4;

    float acc[8][8];
#pragma unroll
    for (int i = 0; i < 8; i++)
#pragma unroll
        for (int j = 0; j < 8; j++) acc[i][j] = 0.f;

    const int aRow = tid >> 2;          // 0..63 (and +64)
    const int aCol = (tid & 3) << 2;    // 0,4,8,12
    const int bRow = tid >> 5;          // 0..7 (and +8)
    const int bCol = (tid & 31) << 2;   // 0..124

    const float* Aptr = A + (size_t)(m0 + aRow) * K + aCol;
    const float* Bptr = B + (size_t)bRow * N + n0 + bCol;

    for (int k0 = 0; k0 < K; k0 += 16) {
        float4 a0 = *(const float4*)(Aptr + k0);
        float4 a1 = *(const float4*)(Aptr + (size_t)64 * K + k0);
        float4 b0 = *(const float4*)(Bptr + (size_t)k0 * N);
        float4 b1 = *(const float4*)(Bptr + (size_t)(k0 + 8) * N);

        __syncthreads();
        As[aCol + 0][aRow] = a0.x;
        As[aCol + 1][aRow] = a0.y;
        As[aCol + 2][aRow] = a0.z;
        As[aCol + 3][aRow] = a0.w;
        As[aCol + 0][aRow + 64] = a1.x;
        As[aCol + 1][aRow + 64] = a1.y;
        As[aCol + 2][aRow + 64] = a1.z;
        As[aCol + 3][aRow + 64] = a1.w;
        *(float4*)&Bs[bRow][bCol]     = b0;
        *(float4*)&Bs[bRow + 8][bCol] = b1;
        __syncthreads();

#pragma unroll
        for (int k = 0; k < 16; k++) {
            float4 av0 = *(const float4*)&As[k][ty * 8];
            float4 av1 = *(const float4*)&As[k][ty * 8 + 4];
            float4 bv0 = *(const float4*)&Bs[k][tx * 8];
            float4 bv1 = *(const float4*)&Bs[k][tx * 8 + 4];
            float a[8] = {av0.x, av0.y, av0.z, av0.w, av1.x, av1.y, av1.z, av1.w};
            float b[8] = {bv0.x, bv0.y, bv0.z, bv0.w, bv1.x, bv1.y, bv1.z, bv1.w};
#pragma unroll
            for (int i = 0; i < 8; i++)
#pragma unroll
                for (int j = 0; j < 8; j++)
                    acc[i][j] = fmaf(a[i], b[j], acc[i][j]);
        }
    }

#pragma unroll
    for (int i = 0; i < 8; i++) {
        size_t row = (size_t)(m0 + ty * 8 + i);
        float* cp = C + row * N + n0 + tx * 8;
        if (Cadd) {
            const float* ap = Cadd + row * N + n0 + tx * 8;
            float4 x0 = *(const float4*)ap;
            float4 x1 = *(const float4*)(ap + 4);
            acc[i][0] += x0.x; acc[i][1] += x0.y; acc[i][2] += x0.z; acc[i][3] += x0.w;
            acc[i][4] += x1.x; acc[i][5] += x1.y; acc[i][6] += x1.z; acc[i][7] += x1.w;
        }
        float4 o0 = make_float4(acc[i][0], acc[i][1], acc[i][2], acc[i][3]);
        float4 o1 = make_float4(acc[i][4], acc[i][5], acc[i][6], acc[i][7]);
        *(float4*)cp = o0;
        *(float4*)(cp + 4) = o1;
    }
}

// =====================================================================
// RoPE in-place on q,k parts of g_qkv. grid=S, block=512 (16 heads x 32)
// =====================================================================
__global__ void __launch_bounds__(512) rope_kernel()
{
    const int s = blockIdx.x;
    const int h = threadIdx.x >> 5;
    const int j = threadIdx.x & 31;

    // inv_freq = 10000^(-j/32) = 2^(-j*log2(10000)/32)
    const float LOG2_1E4 = 13.28771237954945f;
    float inv = exp2f(-(float)j * (LOG2_1E4 / 32.0f));
    float ang = (float)s * inv;
    float sn, cs;
    sincosf(ang, &sn, &cs);   // accurate version (full range reduction)

    float* q = g_qkv + (size_t)s * 3072 + h * 64;
    float* k = q + 1024;

    float q0 = q[j], q1 = q[j + 32];
    q[j]      = q0 * cs - q1 * sn;
    q[j + 32] = q1 * cs + q0 * sn;

    float k0 = k[j], k1 = k[j + 32];
    k[j]      = k0 * cs - k1 * sn;
    k[j + 32] = k1 * cs + k0 * sn;
}

// =====================================================================
// Windowed causal flash attention.
// grid = (NHEADS, S/64), block = 256 (16x16), 4x4 microtile, online softmax.
// =====================================================================
#define APITCH 68

__global__ void __launch_bounds__(256) attn_kernel()
{
    extern __shared__ float sm[];
    float* QT = sm;                   // [64][APITCH]  Q^T: [d][q], pre-scaled by 1/8
    float* KT = sm + 64 * APITCH;     // [64][APITCH]  K^T: [d][k]
    float* Vs = sm + 2 * 64 * APITCH; // [64][APITCH]  V:   [k][d]
    float* PT = sm + 3 * 64 * APITCH; // [64][APITCH]  P^T: [k][q]

    const int h  = blockIdx.x;
    const int q0 = blockIdx.y * 64;
    const int tid = threadIdx.x;
    const int tx = tid & 15;
    const int ty = tid >> 4;

    // ---- load Q tile (transposed, scaled by 1/sqrt(64)) ----
    {
        const int r  = tid >> 2;
        const int c0 = (tid & 3) * 16;
        const float* src = g_qkv + (size_t)(q0 + r) * 3072 + h * 64 + c0;
#pragma unroll
        for (int i = 0; i < 16; i += 4) {
            float4 v = *(const float4*)(src + i);
            QT[(c0 + i + 0) * APITCH + r] = v.x * 0.125f;
            QT[(c0 + i + 1) * APITCH + r] = v.y * 0.125f;
            QT[(c0 + i + 2) * APITCH + r] = v.z * 0.125f;
            QT[(c0 + i + 3) * APITCH + r] = v.w * 0.125f;
        }
    }

    float m_[4], l_[4], O[4][4];
#pragma unroll
    for (int i = 0; i < 4; i++) {
        m_[i] = -1e30f;
        l_[i] = 0.f;
#pragma unroll
        for (int j = 0; j < 4; j++) O[i][j] = 0.f;
    }

    int kstart = q0 - WINDOW;
    if (kstart < 0) kstart = 0;

    for (int kc = kstart; kc <= q0; kc += 64) {
        __syncthreads();   // previous chunk's P@V done before overwriting KT/Vs
        // ---- load K chunk (transposed) and V chunk (natural) ----
        {
            const int r  = tid >> 2;
            const int c0 = (tid & 3) * 16;
            const float* ks = g_qkv + (size_t)(kc + r) * 3072 + 1024 + h * 64 + c0;
            const float* vs = g_qkv + (size_t)(kc + r) * 3072 + 2048 + h * 64 + c0;
#pragma unroll
            for (int i = 0; i < 16; i += 4) {
                float4 kv = *(const float4*)(ks + i);
                KT[(c0 + i + 0) * APITCH + r] = kv.x;
                KT[(c0 + i + 1) * APITCH + r] = kv.y;
                KT[(c0 + i + 2) * APITCH + r] = kv.z;
                KT[(c0 + i + 3) * APITCH + r] = kv.w;
                float4 vv = *(const float4*)(vs + i);
                *(float4*)(Vs + (size_t)r * APITCH + c0 + i) = vv;
            }
        }
        __syncthreads();

        // ---- S = Q @ K^T (4x4 per thread) ----
        float acc[4][4];
#pragma unroll
        for (int i = 0; i < 4; i++)
#pragma unroll
            for (int j = 0; j < 4; j++) acc[i][j] = 0.f;

#pragma unroll 8
        for (int d = 0; d < 64; d++) {
            float4 a = *(const float4*)(QT + d * APITCH + ty * 4);
            float4 b = *(const float4*)(KT + d * APITCH + tx * 4);
            float av[4] = {a.x, a.y, a.z, a.w};
            float bv[4] = {b.x, b.y, b.z, b.w};
#pragma unroll
            for (int i = 0; i < 4; i++)
#pragma unroll
                for (int j = 0; j < 4; j++)
                    acc[i][j] = fmaf(av[i], bv[j], acc[i][j]);
        }

        // ---- mask + online softmax ----
#pragma unroll
        for (int i = 0; i < 4; i++) {
            const int q = q0 + ty * 4 + i;
            float rmax = -1e30f;
#pragma unroll
            for (int j = 0; j < 4; j++) {
                const int key = kc + tx * 4 + j;
                const bool ok = (key <= q) && (q - key <= WINDOW);
                if (!ok) acc[i][j] = -1e30f;
                rmax = fmaxf(rmax, acc[i][j]);
            }
#pragma unroll
            for (int o = 8; o >= 1; o >>= 1)
                rmax = fmaxf(rmax, __shfl_xor_sync(0xffffffffu, rmax, o));
            const float mnew = fmaxf(m_[i], rmax);
            const float scale = __expf(m_[i] - mnew);
            float rsum = 0.f;
#pragma unroll
            for (int j = 0; j < 4; j++) {
                const float p = __expf(acc[i][j] - mnew);
                PT[(size_t)(tx * 4 + j) * APITCH + ty * 4 + i] = p;
                rsum += p;
            }
#pragma unroll
            for (int o = 8; o >= 1; o >>= 1)
                rsum += __shfl_xor_sync(0xffffffffu, rsum, o);
            l_[i] = l_[i] * scale + rsum;
            m_[i] = mnew;
#pragma unroll
            for (int j = 0; j < 4; j++) O[i][j] *= scale;
        }
        __syncthreads();   // PT visible to all

        // ---- O += P @ V ----
#pragma unroll 8
        for (int k = 0; k < 64; k++) {
            float4 p = *(const float4*)(PT + (size_t)k * APITCH + ty * 4);
            float4 v = *(const float4*)(Vs + (size_t)k * APITCH + tx * 4);
            float pv[4] = {p.x, p.y, p.z, p.w};
            float vv[4] = {v.x, v.y, v.z, v.w};
#pragma unroll
            for (int i = 0; i < 4; i++)
#pragma unroll
                for (int j = 0; j < 4; j++)
                    O[i][j] = fmaf(pv[i], vv[j], O[i][j]);
        }
    }

    // ---- normalize + write [S, H*64] ----
#pragma unroll
    for (int i = 0; i < 4; i++) {
        const int s = q0 + ty * 4 + i;
        const float inv = 1.f / l_[i];
        float4 o = make_float4(O[i][0] * inv, O[i][1] * inv, O[i][2] * inv, O[i][3] * inv);
        *(float4*)(g_attn + (size_t)s * DMODEL + h * 64 + tx * 4) = o;
    }
}

// =====================================================================
// LayerNorm: grid=S, block=256 (4 floats per thread)
// =====================================================================
__global__ void __launch_bounds__(256) ln_kernel(
    const float* __restrict__ gamma, const float* __restrict__ beta,
    float* __restrict__ y)
{
    const int s = blockIdx.x;
    const int tid = threadIdx.x;
    const float* r = g_res + (size_t)s * DMODEL;

    float4 xv = *(const float4*)(r + tid * 4);
    float s1 = xv.x + xv.y + xv.z + xv.w;
    float s2 = xv.x * xv.x + xv.y * xv.y + xv.z * xv.z + xv.w * xv.w;
#pragma unroll
    for (int o = 16; o >= 1; o >>= 1) {
        s1 += __shfl_xor_sync(0xffffffffu, s1, o);
        s2 += __shfl_xor_sync(0xffffffffu, s2, o);
    }
    __shared__ float a1[8], a2[8];
    const int w = tid >> 5, lane = tid & 31;
    if (lane == 0) { a1[w] = s1; a2[w] = s2; }
    __syncthreads();
    float t1 = 0.f, t2 = 0.f;
#pragma unroll
    for (int i = 0; i < 8; i++) { t1 += a1[i]; t2 += a2[i]; }

    const float mu  = t1 * (1.0f / DMODEL);
    const float var = t2 * (1.0f / DMODEL) - mu * mu;
    const float rstd = rsqrtf(var + LN_EPS);

    const int c = tid * 4;
    float4 g = *(const float4*)(gamma + c);
    float4 b = *(const float4*)(beta + c);
    float4 o;
    o.x = (xv.x - mu) * rstd * g.x + b.x;
    o.y = (xv.y - mu) * rstd * g.y + b.y;
    o.z = (xv.z - mu) * rstd * g.z + b.z;
    o.w = (xv.w - mu) * rstd * g.w + b.w;
    *(float4*)(y + (size_t)s * DMODEL + c) = o;
}

// =====================================================================
// launch
// =====================================================================
extern "C" void kernel_launch(void* const* d_in, const int* in_sizes, int n_in,
                              void* d_out, int out_size)
{
    const float* x     = (const float*)d_in[0];
    const float* state = (const float*)d_in[1];
    const float* Wqkv  = (const float*)d_in[2];
    const float* Wout  = (const float*)d_in[3];
    const float* gamma = (const float*)d_in[4];
    const float* beta  = (const float*)d_in[5];
    float* y = (float*)d_out;

    float *qkv, *attn, *res;
    cudaGetSymbolAddress((void**)&qkv,  g_qkv);
    cudaGetSymbolAddress((void**)&attn, g_attn);
    cudaGetSymbolAddress((void**)&res,  g_res);

    // 1) QKV projection: [2048,1024] @ [1024,3072]
    sgemm_kernel<<<dim3(3 * DMODEL / 128, S_LEN / 128), 256>>>(
        x, Wqkv, qkv, nullptr, S_LEN, 3 * DMODEL, DMODEL);

    // 2) RoPE in place on q,k
    rope_kernel<<<S_LEN, 512>>>();

    // 3) windowed attention
    const int smem_bytes = 4 * 64 * APITCH * (int)sizeof(float);
    cudaFuncSetAttribute(attn_kernel, cudaFuncAttributeMaxDynamicSharedMemorySize, smem_bytes);
    attn_kernel<<<dim3(NHEADS, S_LEN / 64), 256, smem_bytes>>>();

    // 4) output projection + residual: res = x + attn @ W_out
    sgemm_kernel<<<dim3(DMODEL / 128, S_LEN / 128), 256>>>(
        attn, Wout, res, x, S_LEN, DMODEL, DMODEL);

    // 5) LayerNorm -> y
    ln_kernel<<<S_LEN, 256>>>(gamma, beta, y);

    // 6) pass-through state if the output buffer includes it
    if (out_size >= S_LEN * DMODEL + DMODEL) {
        cudaMemcpyAsync(y + (size_t)S_LEN * DMODEL, state,
                        DMODEL * sizeof(float), cudaMemcpyDeviceToDevice);
    }
}

// round 5
// speedup vs baseline: 1.6085x; 1.6085x over previous
#include <cuda_runtime.h>
#include <cuda_bf16.h>
#include <math.h>
#include <stdint.h>

#define S_LEN   2048
#define DMODEL  1024
#define NHEADS  16
#define WINDOW  256
#define LN_EPS  1e-5f

// ---------------- scratch (no allocations allowed) ----------------
__device__ float g_qkv[(size_t)S_LEN * 3 * DMODEL];   // [S, 3*D] fp32 (q | k | v)
__device__ float g_res[(size_t)S_LEN * DMODEL];       // residual pre-LN

// split-bf16 operands
__device__ __nv_bfloat16 g_xhi[(size_t)S_LEN * DMODEL];
__device__ __nv_bfloat16 g_xlo[(size_t)S_LEN * DMODEL];
__device__ __nv_bfloat16 g_ahi[(size_t)S_LEN * DMODEL];   // attention out hi
__device__ __nv_bfloat16 g_alo[(size_t)S_LEN * DMODEL];   // attention out lo
__device__ __nv_bfloat16 g_wqhi[(size_t)3 * DMODEL * DMODEL];  // W_qkv^T [3072,1024]
__device__ __nv_bfloat16 g_wqlo[(size_t)3 * DMODEL * DMODEL];
__device__ __nv_bfloat16 g_wohi[(size_t)DMODEL * DMODEL];      // W_out^T [1024,1024]
__device__ __nv_bfloat16 g_wolo[(size_t)DMODEL * DMODEL];

// =====================================================================
// warp-level tensor-core helpers (sm_80+ baseline, no arch suffix needed)
// =====================================================================
__device__ __forceinline__ uint32_t smem_u32(const void* p) {
    uint32_t a;
    asm("{ .reg .u64 t; cvta.to.shared.u64 t, %1; cvt.u32.u64 %0, t; }" : "=r"(a) : "l"(p));
    return a;
}
__device__ __forceinline__ void ldsm_x4(uint32_t* r, uint32_t addr) {
    asm volatile("ldmatrix.sync.aligned.m8n8.x4.shared.b16 {%0,%1,%2,%3}, [%4];"
                 : "=r"(r[0]), "=r"(r[1]), "=r"(r[2]), "=r"(r[3]) : "r"(addr));
}
__device__ __forceinline__ void ldsm_x2(uint32_t* r, uint32_t addr) {
    asm volatile("ldmatrix.sync.aligned.m8n8.x2.shared.b16 {%0,%1}, [%2];"
                 : "=r"(r[0]), "=r"(r[1]) : "r"(addr));
}
__device__ __forceinline__ void mma_bf16(float* d, const uint32_t* a, const uint32_t* b) {
    asm volatile(
        "mma.sync.aligned.m16n8k16.row.col.f32.bf16.bf16.f32 "
        "{%0,%1,%2,%3}, {%4,%5,%6,%7}, {%8,%9}, {%0,%1,%2,%3};"
        : "+f"(d[0]), "+f"(d[1]), "+f"(d[2]), "+f"(d[3])
        : "r"(a[0]), "r"(a[1]), "r"(a[2]), "r"(a[3]), "r"(b[0]), "r"(b[1]));
}

#define SWZ128(bo) ((bo) ^ (((bo) >> 3) & 0x70))

// =====================================================================
// split x -> bf16 hi/lo (elementwise, row-major preserved)
// =====================================================================
__global__ void __launch_bounds__(256) split_kernel(
    const float4* __restrict__ in, uint2* __restrict__ hi, uint2* __restrict__ lo, int n4)
{
    for (int i = blockIdx.x * blockDim.x + threadIdx.x; i < n4; i += gridDim.x * blockDim.x) {
        float4 v = in[i];
        __nv_bfloat16 h0 = __float2bfloat16(v.x), h1 = __float2bfloat16(v.y);
        __nv_bfloat16 h2 = __float2bfloat16(v.z), h3 = __float2bfloat16(v.w);
        __nv_bfloat16 l0 = __float2bfloat16(v.x - __bfloat162float(h0));
        __nv_bfloat16 l1 = __float2bfloat16(v.y - __bfloat162float(h1));
        __nv_bfloat16 l2 = __float2bfloat16(v.z - __bfloat162float(h2));
        __nv_bfloat16 l3 = __float2bfloat16(v.w - __bfloat162float(h3));
        __nv_bfloat162 hp0 = {h0, h1}, hp1 = {h2, h3};
        __nv_bfloat162 lp0 = {l0, l1}, lp1 = {l2, l3};
        hi[i] = make_uint2(*(uint32_t*)&hp0, *(uint32_t*)&hp1);
        lo[i] = make_uint2(*(uint32_t*)&lp0, *(uint32_t*)&lp1);
    }
}

// =====================================================================
// transpose + split: W [K,N] fp32 -> Wt hi/lo [N,K] bf16
// =====================================================================
__global__ void __launch_bounds__(256) wsplit_kernel(
    const float* __restrict__ W, __nv_bfloat16* __restrict__ hi,
    __nv_bfloat16* __restrict__ lo, int K, int N)
{
    __shared__ float t[32][33];
    const int tx = threadIdx.x & 31;
    const int ty = threadIdx.x >> 5;
    const int bn = blockIdx.x * 32;
    const int bk = blockIdx.y * 32;
#pragma unroll
    for (int i = 0; i < 32; i += 8)
        t[ty + i][tx] = W[(size_t)(bk + ty + i) * N + bn + tx];
    __syncthreads();
#pragma unroll
    for (int i = 0; i < 32; i += 8) {
        float v = t[tx][ty + i];
        __nv_bfloat16 h = __float2bfloat16(v);
        __nv_bfloat16 l = __float2bfloat16(v - __bfloat162float(h));
        size_t o = (size_t)(bn + ty + i) * K + bk + tx;
        hi[o] = h;
        lo[o] = l;
    }
}

// =====================================================================
// split-bf16 tensor-core GEMM via mma.sync:
//   C[m,n] (+= Cadd) = sum_k A[m,k]*B[n,k],  A = Ahi+Alo, B = Bhi+Blo
//   (3 MMA products: AhBh + AhBl + AlBh)
// CTA tile 128x128, K-chunk 64. 8 warps in 2x4 (each warp 64x32).
// SMEM: 4 tiles of [128 rows][64 bf16] = 128B/row, SW128 swizzled.
// =====================================================================
#define GEMM_SMEM (4 * 128 * 128)

__global__ void __launch_bounds__(256) gemm_bf16s(
    const __nv_bfloat16* __restrict__ Ahi, const __nv_bfloat16* __restrict__ Alo,
    const __nv_bfloat16* __restrict__ Bhi, const __nv_bfloat16* __restrict__ Blo,
    float* __restrict__ C, const float* __restrict__ Cadd, int ldC)
{
    extern __shared__ char smem[];
    char* sAhi = smem;
    char* sAlo = smem + 16384;
    char* sBhi = smem + 32768;
    char* sBlo = smem + 49152;
    const uint32_t bAhi = smem_u32(sAhi);
    const uint32_t bAlo = bAhi + 16384;
    const uint32_t bBhi = bAhi + 32768;
    const uint32_t bBlo = bAhi + 49152;

    const int tid  = threadIdx.x;
    const int wid  = tid >> 5;
    const int lane = tid & 31;
    const int wm   = wid & 1;            // warp row  (2)
    const int wn   = wid >> 1;           // warp col  (4)
    const int m0 = blockIdx.y * 128;
    const int n0 = blockIdx.x * 128;

    float acc[4][4][4];
#pragma unroll
    for (int i = 0; i < 4; i++)
#pragma unroll
        for (int j = 0; j < 4; j++)
#pragma unroll
            for (int c = 0; c < 4; c++) acc[i][j][c] = 0.f;

    // g2s layout: each thread owns one row-half (4 x 16B) per tile
    const int r   = tid >> 1;
    const int sg0 = (tid & 1) * 4;

    // ldmatrix base offsets (per lane)
    const int aRow = wm * 64 + (lane & 15);
    const int aKb  = (lane >> 4) << 3;           // k half: 0 or 8
    const int bRow = wn * 32 + (lane & 7);
    const int bKb  = ((lane >> 3) & 1) << 3;     // k half: 0 or 8

    for (int kc = 0; kc < DMODEL; kc += 64) {
        const __nv_bfloat16* ga_h = Ahi + (size_t)(m0 + r) * DMODEL + kc + sg0 * 8;
        const __nv_bfloat16* ga_l = Alo + (size_t)(m0 + r) * DMODEL + kc + sg0 * 8;
        const __nv_bfloat16* gb_h = Bhi + (size_t)(n0 + r) * DMODEL + kc + sg0 * 8;
        const __nv_bfloat16* gb_l = Blo + (size_t)(n0 + r) * DMODEL + kc + sg0 * 8;
        __syncthreads();   // previous iteration's MMAs done before overwrite
#pragma unroll
        for (int s = 0; s < 4; s++) {
            const uint32_t bo = SWZ128((uint32_t)(r * 128 + (sg0 + s) * 16));
            *(uint4*)(sAhi + bo) = *(const uint4*)(ga_h + s * 8);
            *(uint4*)(sAlo + bo) = *(const uint4*)(ga_l + s * 8);
            *(uint4*)(sBhi + bo) = *(const uint4*)(gb_h + s * 8);
            *(uint4*)(sBlo + bo) = *(const uint4*)(gb_l + s * 8);
        }
        __syncthreads();

#pragma unroll
        for (int kk = 0; kk < 64; kk += 16) {
            uint32_t ah[4][4], al[4][4];
#pragma unroll
            for (int mt = 0; mt < 4; mt++) {
                const uint32_t bo =
                    SWZ128((uint32_t)((aRow + mt * 16) * 128 + (kk + aKb) * 2));
                ldsm_x4(ah[mt], bAhi + bo);
                ldsm_x4(al[mt], bAlo + bo);
            }
#pragma unroll
            for (int nt = 0; nt < 4; nt++) {
                const uint32_t bo =
                    SWZ128((uint32_t)((bRow + nt * 8) * 128 + (kk + bKb) * 2));
                uint32_t bh[2], bl[2];
                ldsm_x2(bh, bBhi + bo);
                ldsm_x2(bl, bBlo + bo);
#pragma unroll
                for (int mt = 0; mt < 4; mt++) {
                    mma_bf16(acc[mt][nt], ah[mt], bh);
                    mma_bf16(acc[mt][nt], ah[mt], bl);
                    mma_bf16(acc[mt][nt], al[mt], bh);
                }
            }
        }
    }

    // ---- epilogue: c fragment -> global (float2 per d-pair) ----
    const int g   = lane >> 2;
    const int tg  = lane & 3;
#pragma unroll
    for (int mt = 0; mt < 4; mt++) {
#pragma unroll
        for (int half = 0; half < 2; half++) {
            const int m = m0 + wm * 64 + mt * 16 + g + half * 8;
            float* cp = C + (size_t)m * ldC + n0 + wn * 32;
            const float* ap = Cadd ? (Cadd + (size_t)m * ldC + n0 + wn * 32) : nullptr;
#pragma unroll
            for (int nt = 0; nt < 4; nt++) {
                const int col = nt * 8 + tg * 2;
                float2 v = make_float2(acc[mt][nt][half * 2], acc[mt][nt][half * 2 + 1]);
                if (ap) {
                    float2 c = *(const float2*)(ap + col);
                    v.x += c.x; v.y += c.y;
                }
                *(float2*)(cp + col) = v;
            }
        }
    }
}

// =====================================================================
// RoPE in-place on q,k parts of g_qkv. grid=S, block=512 (16 heads x 32)
// =====================================================================
__global__ void __launch_bounds__(512) rope_kernel()
{
    const int s = blockIdx.x;
    const int h = threadIdx.x >> 5;
    const int j = threadIdx.x & 31;

    const float LOG2_1E4 = 13.28771237954945f;
    float inv = exp2f(-(float)j * (LOG2_1E4 / 32.0f));
    float ang = (float)s * inv;
    float sn, cs;
    sincosf(ang, &sn, &cs);

    float* q = g_qkv + (size_t)s * 3072 + h * 64;
    float* k = q + 1024;

    float q0 = q[j], q1 = q[j + 32];
    q[j]      = q0 * cs - q1 * sn;
    q[j + 32] = q1 * cs + q0 * sn;

    float k0 = k[j], k1 = k[j + 32];
    k[j]      = k0 * cs - k1 * sn;
    k[j + 32] = k1 * cs + k0 * sn;
}

// =====================================================================
// Windowed causal flash attention (fp32 FFMA). Output -> bf16 hi/lo.
// grid = (NHEADS, S/64), block = 256 (16x16), 4x4 microtile.
// =====================================================================
#define APITCH 68

__global__ void __launch_bounds__(256) attn_kernel()
{
    extern __shared__ float sm[];
    float* QT = sm;
    float* KT = sm + 64 * APITCH;
    float* Vs = sm + 2 * 64 * APITCH;
    float* PT = sm + 3 * 64 * APITCH;

    const int h  = blockIdx.x;
    const int q0 = blockIdx.y * 64;
    const int tid = threadIdx.x;
    const int tx = tid & 15;
    const int ty = tid >> 4;

    {
        const int r  = tid >> 2;
        const int c0 = (tid & 3) * 16;
        const float* src = g_qkv + (size_t)(q0 + r) * 3072 + h * 64 + c0;
#pragma unroll
        for (int i = 0; i < 16; i += 4) {
            float4 v = *(const float4*)(src + i);
            QT[(c0 + i + 0) * APITCH + r] = v.x * 0.125f;
            QT[(c0 + i + 1) * APITCH + r] = v.y * 0.125f;
            QT[(c0 + i + 2) * APITCH + r] = v.z * 0.125f;
            QT[(c0 + i + 3) * APITCH + r] = v.w * 0.125f;
        }
    }

    float m_[4], l_[4], O[4][4];
#pragma unroll
    for (int i = 0; i < 4; i++) {
        m_[i] = -1e30f;
        l_[i] = 0.f;
#pragma unroll
        for (int j = 0; j < 4; j++) O[i][j] = 0.f;
    }

    int kstart = q0 - WINDOW;
    if (kstart < 0) kstart = 0;

    for (int kc = kstart; kc <= q0; kc += 64) {
        __syncthreads();
        {
            const int r  = tid >> 2;
            const int c0 = (tid & 3) * 16;
            const float* ks = g_qkv + (size_t)(kc + r) * 3072 + 1024 + h * 64 + c0;
            const float* vs = g_qkv + (size_t)(kc + r) * 3072 + 2048 + h * 64 + c0;
#pragma unroll
            for (int i = 0; i < 16; i += 4) {
                float4 kv = *(const float4*)(ks + i);
                KT[(c0 + i + 0) * APITCH + r] = kv.x;
                KT[(c0 + i + 1) * APITCH + r] = kv.y;
                KT[(c0 + i + 2) * APITCH + r] = kv.z;
                KT[(c0 + i + 3) * APITCH + r] = kv.w;
                float4 vv = *(const float4*)(vs + i);
                *(float4*)(Vs + (size_t)r * APITCH + c0 + i) = vv;
            }
        }
        __syncthreads();

        float acc[4][4];
#pragma unroll
        for (int i = 0; i < 4; i++)
#pragma unroll
            for (int j = 0; j < 4; j++) acc[i][j] = 0.f;

#pragma unroll 8
        for (int d = 0; d < 64; d++) {
            float4 a = *(const float4*)(QT + d * APITCH + ty * 4);
            float4 b = *(const float4*)(KT + d * APITCH + tx * 4);
            float av[4] = {a.x, a.y, a.z, a.w};
            float bv[4] = {b.x, b.y, b.z, b.w};
#pragma unroll
            for (int i = 0; i < 4; i++)
#pragma unroll
                for (int j = 0; j < 4; j++)
                    acc[i][j] = fmaf(av[i], bv[j], acc[i][j]);
        }

#pragma unroll
        for (int i = 0; i < 4; i++) {
            const int q = q0 + ty * 4 + i;
            float rmax = -1e30f;
#pragma unroll
            for (int j = 0; j < 4; j++) {
                const int key = kc + tx * 4 + j;
                const bool ok = (key <= q) && (q - key <= WINDOW);
                if (!ok) acc[i][j] = -1e30f;
                rmax = fmaxf(rmax, acc[i][j]);
            }
#pragma unroll
            for (int o = 8; o >= 1; o >>= 1)
                rmax = fmaxf(rmax, __shfl_xor_sync(0xffffffffu, rmax, o));
            const float mnew = fmaxf(m_[i], rmax);
            const float scale = __expf(m_[i] - mnew);
            float rsum = 0.f;
#pragma unroll
            for (int j = 0; j < 4; j++) {
                const float p = __expf(acc[i][j] - mnew);
                PT[(size_t)(tx * 4 + j) * APITCH + ty * 4 + i] = p;
                rsum += p;
            }
#pragma unroll
            for (int o = 8; o >= 1; o >>= 1)
                rsum += __shfl_xor_sync(0xffffffffu, rsum, o);
            l_[i] = l_[i] * scale + rsum;
            m_[i] = mnew;
#pragma unroll
            for (int j = 0; j < 4; j++) O[i][j] *= scale;
        }
        __syncthreads();

#pragma unroll 8
        for (int k = 0; k < 64; k++) {
            float4 p = *(const float4*)(PT + (size_t)k * APITCH + ty * 4);
            float4 v = *(const float4*)(Vs + (size_t)k * APITCH + tx * 4);
            float pv[4] = {p.x, p.y, p.z, p.w};
            float vv[4] = {v.x, v.y, v.z, v.w};
#pragma unroll
            for (int i = 0; i < 4; i++)
#pragma unroll
                for (int j = 0; j < 4; j++)
                    O[i][j] = fmaf(pv[i], vv[j], O[i][j]);
        }
    }

    // ---- normalize + write split-bf16 [S, H*64] ----
#pragma unroll
    for (int i = 0; i < 4; i++) {
        const int s = q0 + ty * 4 + i;
        const float inv = 1.f / l_[i];
        __nv_bfloat16 hh[4], ll[4];
#pragma unroll
        for (int j = 0; j < 4; j++) {
            float v = O[i][j] * inv;
            hh[j] = __float2bfloat16(v);
            ll[j] = __float2bfloat16(v - __bfloat162float(hh[j]));
        }
        const size_t off = (size_t)s * DMODEL + h * 64 + tx * 4;
        *(uint2*)(g_ahi + off) = *(uint2*)hh;
        *(uint2*)(g_alo + off) = *(uint2*)ll;
    }
}

// =====================================================================
// LayerNorm: grid=S, block=256
// =====================================================================
__global__ void __launch_bounds__(256) ln_kernel(
    const float* __restrict__ gamma, const float* __restrict__ beta,
    float* __restrict__ y)
{
    const int s = blockIdx.x;
    const int tid = threadIdx.x;
    const float* r = g_res + (size_t)s * DMODEL;

    float4 xv = *(const float4*)(r + tid * 4);
    float s1 = xv.x + xv.y + xv.z + xv.w;
    float s2 = xv.x * xv.x + xv.y * xv.y + xv.z * xv.z + xv.w * xv.w;
#pragma unroll
    for (int o = 16; o >= 1; o >>= 1) {
        s1 += __shfl_xor_sync(0xffffffffu, s1, o);
        s2 += __shfl_xor_sync(0xffffffffu, s2, o);
    }
    __shared__ float a1[8], a2[8];
    const int w = tid >> 5, lane = tid & 31;
    if (lane == 0) { a1[w] = s1; a2[w] = s2; }
    __syncthreads();
    float t1 = 0.f, t2 = 0.f;
#pragma unroll
    for (int i = 0; i < 8; i++) { t1 += a1[i]; t2 += a2[i]; }

    const float mu  = t1 * (1.0f / DMODEL);
    const float var = t2 * (1.0f / DMODEL) - mu * mu;
    const float rstd = rsqrtf(var + LN_EPS);

    const int c = tid * 4;
    float4 g = *(const float4*)(gamma + c);
    float4 b = *(const float4*)(beta + c);
    float4 o;
    o.x = (xv.x - mu) * rstd * g.x + b.x;
    o.y = (xv.y - mu) * rstd * g.y + b.y;
    o.z = (xv.z - mu) * rstd * g.z + b.z;
    o.w = (xv.w - mu) * rstd * g.w + b.w;
    *(float4*)(y + (size_t)s * DMODEL + c) = o;
}

// =====================================================================
// launch
// =====================================================================
extern "C" void kernel_launch(void* const* d_in, const int* in_sizes, int n_in,
                              void* d_out, int out_size)
{
    const float* x     = (const float*)d_in[0];
    const float* state = (const float*)d_in[1];
    const float* Wqkv  = (const float*)d_in[2];
    const float* Wout  = (const float*)d_in[3];
    const float* gamma = (const float*)d_in[4];
    const float* beta  = (const float*)d_in[5];
    float* y = (float*)d_out;

    float *qkv, *res;
    __nv_bfloat16 *xhi, *xlo, *ahi, *alo, *wqhi, *wqlo, *wohi, *wolo;
    cudaGetSymbolAddress((void**)&qkv,  g_qkv);
    cudaGetSymbolAddress((void**)&res,  g_res);
    cudaGetSymbolAddress((void**)&xhi,  g_xhi);
    cudaGetSymbolAddress((void**)&xlo,  g_xlo);
    cudaGetSymbolAddress((void**)&ahi,  g_ahi);
    cudaGetSymbolAddress((void**)&alo,  g_alo);
    cudaGetSymbolAddress((void**)&wqhi, g_wqhi);
    cudaGetSymbolAddress((void**)&wqlo, g_wqlo);
    cudaGetSymbolAddress((void**)&wohi, g_wohi);
    cudaGetSymbolAddress((void**)&wolo, g_wolo);

    cudaFuncSetAttribute(gemm_bf16s, cudaFuncAttributeMaxDynamicSharedMemorySize, GEMM_SMEM);
    cudaFuncSetAttribute(attn_kernel, cudaFuncAttributeMaxDynamicSharedMemorySize,
                         4 * 64 * APITCH * (int)sizeof(float));

    // 0) operand prep: split x, transpose+split weights
    split_kernel<<<512, 256>>>((const float4*)x, (uint2*)xhi, (uint2*)xlo,
                               S_LEN * DMODEL / 4);
    wsplit_kernel<<<dim3(3 * DMODEL / 32, DMODEL / 32), 256>>>(Wqkv, wqhi, wqlo,
                                                               DMODEL, 3 * DMODEL);
    wsplit_kernel<<<dim3(DMODEL / 32, DMODEL / 32), 256>>>(Wout, wohi, wolo,
                                                           DMODEL, DMODEL);

    // 1) QKV projection (mma.sync split-bf16): [2048,1024] @ [1024,3072]
    gemm_bf16s<<<dim3(3 * DMODEL / 128, S_LEN / 128), 256, GEMM_SMEM>>>(
        xhi, xlo, wqhi, wqlo, qkv, nullptr, 3 * DMODEL);

    // 2) RoPE in place on q,k
    rope_kernel<<<S_LEN, 512>>>();

    // 3) windowed attention (writes split-bf16 output)
    attn_kernel<<<dim3(NHEADS, S_LEN / 64), 256, 4 * 64 * APITCH * sizeof(float)>>>();

    // 4) output projection + residual (mma.sync split-bf16): res = x + attn @ W_out
    gemm_bf16s<<<dim3(DMODEL / 128, S_LEN / 128), 256, GEMM_SMEM>>>(
        ahi, alo, wohi, wolo, res, x, DMODEL);

    // 5) LayerNorm -> y
    ln_kernel<<<S_LEN, 256>>>(gamma, beta, y);

    // 6) pass-through state if the output buffer includes it
    if (out_size >= S_LEN * DMODEL + DMODEL) {
        cudaMemcpyAsync(y + (size_t)S_LEN * DMODEL, state,
                        DMODEL * sizeof(float), cudaMemcpyDeviceToDevice);
    }
}

// round 6
// speedup vs baseline: 1.6740x; 1.0407x over previous
#include <cuda_runtime.h>
#include <cuda_bf16.h>
#include <math.h>
#include <stdint.h>

#define S_LEN   2048
#define DMODEL  1024
#define NHEADS  16
#define WINDOW  256
#define LN_EPS  1e-5f

// ---------------- scratch (no allocations allowed) ----------------
__device__ float g_qkv[(size_t)S_LEN * 3 * DMODEL];   // [S, 3*D] fp32 (q | k | v)
__device__ float g_res[(size_t)S_LEN * DMODEL];       // residual pre-LN

// split-bf16 operands
__device__ __nv_bfloat16 g_xhi[(size_t)S_LEN * DMODEL];
__device__ __nv_bfloat16 g_xlo[(size_t)S_LEN * DMODEL];
__device__ __nv_bfloat16 g_ahi[(size_t)S_LEN * DMODEL];   // attention out hi
__device__ __nv_bfloat16 g_alo[(size_t)S_LEN * DMODEL];   // attention out lo
__device__ __nv_bfloat16 g_wqhi[(size_t)3 * DMODEL * DMODEL];  // W_qkv^T [3072,1024]
__device__ __nv_bfloat16 g_wqlo[(size_t)3 * DMODEL * DMODEL];
__device__ __nv_bfloat16 g_wohi[(size_t)DMODEL * DMODEL];      // W_out^T [1024,1024]
__device__ __nv_bfloat16 g_wolo[(size_t)DMODEL * DMODEL];

// =====================================================================
// warp-level tensor-core helpers (sm_80+ baseline, no arch suffix needed)
// =====================================================================
__device__ __forceinline__ uint32_t smem_u32(const void* p) {
    uint32_t a;
    asm("{ .reg .u64 t; cvta.to.shared.u64 t, %1; cvt.u32.u64 %0, t; }" : "=r"(a) : "l"(p));
    return a;
}
__device__ __forceinline__ void ldsm_x4(uint32_t* r, uint32_t addr) {
    asm volatile("ldmatrix.sync.aligned.m8n8.x4.shared.b16 {%0,%1,%2,%3}, [%4];"
                 : "=r"(r[0]), "=r"(r[1]), "=r"(r[2]), "=r"(r[3]) : "r"(addr));
}
__device__ __forceinline__ void mma_bf16(float* d, const uint32_t* a, const uint32_t* b) {
    asm volatile(
        "mma.sync.aligned.m16n8k16.row.col.f32.bf16.bf16.f32 "
        "{%0,%1,%2,%3}, {%4,%5,%6,%7}, {%8,%9}, {%0,%1,%2,%3};"
        : "+f"(d[0]), "+f"(d[1]), "+f"(d[2]), "+f"(d[3])
        : "r"(a[0]), "r"(a[1]), "r"(a[2]), "r"(a[3]), "r"(b[0]), "r"(b[1]));
}
__device__ __forceinline__ void cp16(uint32_t dst, const void* src) {
    asm volatile("cp.async.cg.shared.global [%0], [%1], 16;" :: "r"(dst), "l"(src));
}
__device__ __forceinline__ void cp_commit() {
    asm volatile("cp.async.commit_group;" ::: "memory");
}
template <int N>
__device__ __forceinline__ void cp_wait() {
    asm volatile("cp.async.wait_group %0;" :: "n"(N) : "memory");
}

#define SWZ128(bo) ((bo) ^ (((bo) >> 3) & 0x70))

// =====================================================================
// split x -> bf16 hi/lo (elementwise, row-major preserved)
// =====================================================================
__global__ void __launch_bounds__(256) split_kernel(
    const float4* __restrict__ in, uint2* __restrict__ hi, uint2* __restrict__ lo, int n4)
{
    for (int i = blockIdx.x * blockDim.x + threadIdx.x; i < n4; i += gridDim.x * blockDim.x) {
        float4 v = in[i];
        __nv_bfloat16 h0 = __float2bfloat16(v.x), h1 = __float2bfloat16(v.y);
        __nv_bfloat16 h2 = __float2bfloat16(v.z), h3 = __float2bfloat16(v.w);
        __nv_bfloat16 l0 = __float2bfloat16(v.x - __bfloat162float(h0));
        __nv_bfloat16 l1 = __float2bfloat16(v.y - __bfloat162float(h1));
        __nv_bfloat16 l2 = __float2bfloat16(v.z - __bfloat162float(h2));
        __nv_bfloat16 l3 = __float2bfloat16(v.w - __bfloat162float(h3));
        __nv_bfloat162 hp0 = {h0, h1}, hp1 = {h2, h3};
        __nv_bfloat162 lp0 = {l0, l1}, lp1 = {l2, l3};
        hi[i] = make_uint2(*(uint32_t*)&hp0, *(uint32_t*)&hp1);
        lo[i] = make_uint2(*(uint32_t*)&lp0, *(uint32_t*)&lp1);
    }
}

// =====================================================================
// transpose + split: W [K,N] fp32 -> Wt hi/lo [N,K] bf16
// =====================================================================
__global__ void __launch_bounds__(256) wsplit_kernel(
    const float* __restrict__ W, __nv_bfloat16* __restrict__ hi,
    __nv_bfloat16* __restrict__ lo, int K, int N)
{
    __shared__ float t[32][33];
    const int tx = threadIdx.x & 31;
    const int ty = threadIdx.x >> 5;
    const int bn = blockIdx.x * 32;
    const int bk = blockIdx.y * 32;
#pragma unroll
    for (int i = 0; i < 32; i += 8)
        t[ty + i][tx] = W[(size_t)(bk + ty + i) * N + bn + tx];
    __syncthreads();
#pragma unroll
    for (int i = 0; i < 32; i += 8) {
        float v = t[tx][ty + i];
        __nv_bfloat16 h = __float2bfloat16(v);
        __nv_bfloat16 l = __float2bfloat16(v - __bfloat162float(h));
        size_t o = (size_t)(bn + ty + i) * K + bk + tx;
        hi[o] = h;
        lo[o] = l;
    }
}

// =====================================================================
// split-bf16 tensor-core GEMM via mma.sync + cp.async double buffering:
//   C[m,n] (+= Cadd) = sum_k A[m,k]*B[n,k],  A = Ahi+Alo, B = Bhi+Blo
//   (3 MMA products: AhBh + AhBl + AlBh)
// CTA tile 128x128, K-chunk 32, 2 stages. 8 warps in 2x4 (each 64x32).
// SMEM row (128B, SW128): [hi 64B | lo 64B] per logical row.
// Stage: sA 16KB + sB 16KB = 32KB; 2 stages = 64KB; 2 CTAs/SM.
// =====================================================================
#define GEMM_SMEM (2 * 32768)

__global__ void __launch_bounds__(256, 2) gemm_bf16s(
    const __nv_bfloat16* __restrict__ Ahi, const __nv_bfloat16* __restrict__ Alo,
    const __nv_bfloat16* __restrict__ Bhi, const __nv_bfloat16* __restrict__ Blo,
    float* __restrict__ C, const float* __restrict__ Cadd, int ldC)
{
    extern __shared__ char smem[];
    const uint32_t sb = smem_u32(smem);

    const int tid  = threadIdx.x;
    const int wid  = tid >> 5;
    const int lane = tid & 31;
    const int wm   = wid & 1;            // warp row  (2)
    const int wn   = wid >> 1;           // warp col  (4)
    const int m0 = blockIdx.y * 128;
    const int n0 = blockIdx.x * 128;

    float acc[4][4][4];
#pragma unroll
    for (int i = 0; i < 4; i++)
#pragma unroll
        for (int j = 0; j < 4; j++)
#pragma unroll
            for (int c = 0; c < 4; c++) acc[i][j][c] = 0.f;

    // ---- g2s mapping: thread -> row r, half h (2 x 16B hi + 2 x 16B lo per tile)
    const int r = tid >> 1;
    const int h = tid & 1;
    const __nv_bfloat16* gAh = Ahi + (size_t)(m0 + r) * DMODEL + h * 16;
    const __nv_bfloat16* gAl = Alo + (size_t)(m0 + r) * DMODEL + h * 16;
    const __nv_bfloat16* gBh = Bhi + (size_t)(n0 + r) * DMODEL + h * 16;
    const __nv_bfloat16* gBl = Blo + (size_t)(n0 + r) * DMODEL + h * 16;
    const uint32_t dhi0 = SWZ128((uint32_t)(r * 128 + h * 32));
    const uint32_t dhi1 = SWZ128((uint32_t)(r * 128 + h * 32 + 16));
    const uint32_t dlo0 = SWZ128((uint32_t)(r * 128 + 64 + h * 32));
    const uint32_t dlo1 = SWZ128((uint32_t)(r * 128 + 64 + h * 32 + 16));

    // ---- ldmatrix lane addressing
    const int aRow = wm * 64 + (lane & 15);
    const int aKb  = (lane >> 4) << 4;               // byte offset of k-half (0/16)
    const int bRow = wn * 32 + (lane & 15);          // covers 2 n-tiles per x4

    // ---------------- pipeline ----------------
    const int NCH = DMODEL / 32;   // 32 chunks

#define LOAD_STAGE(kc, s)                                                   \
    do {                                                                    \
        const uint32_t bA = sb + (s) * 32768;                               \
        const uint32_t bB = bA + 16384;                                     \
        cp16(bA + dhi0, gAh + (kc));                                        \
        cp16(bA + dhi1, gAh + (kc) + 8);                                    \
        cp16(bA + dlo0, gAl + (kc));                                        \
        cp16(bA + dlo1, gAl + (kc) + 8);                                    \
        cp16(bB + dhi0, gBh + (kc));                                        \
        cp16(bB + dhi1, gBh + (kc) + 8);                                    \
        cp16(bB + dlo0, gBl + (kc));                                        \
        cp16(bB + dlo1, gBl + (kc) + 8);                                    \
    } while (0)

    LOAD_STAGE(0, 0);
    cp_commit();

    for (int it = 0; it < NCH; it++) {
        const int buf = it & 1;
        if (it + 1 < NCH) {
            LOAD_STAGE((it + 1) * 32, buf ^ 1);
            cp_commit();
            cp_wait<1>();
        } else {
            cp_wait<0>();
        }
        __syncthreads();

        const uint32_t bA = sb + buf * 32768;
        const uint32_t bB = bA + 16384;

#pragma unroll
        for (int kk = 0; kk < 32; kk += 16) {
            uint32_t ah[4][4], al[4][4];
#pragma unroll
            for (int mt = 0; mt < 4; mt++) {
                const uint32_t row = (uint32_t)(aRow + mt * 16) * 128;
                ldsm_x4(ah[mt], bA + SWZ128(row + kk * 2 + aKb));
                ldsm_x4(al[mt], bA + SWZ128(row + 64 + kk * 2 + aKb));
            }
#pragma unroll
            for (int ntp = 0; ntp < 2; ntp++) {
                const uint32_t row = (uint32_t)(bRow + ntp * 16) * 128;
                uint32_t bh[4], bl[4];
                ldsm_x4(bh, bB + SWZ128(row + kk * 2 + aKb));
                ldsm_x4(bl, bB + SWZ128(row + 64 + kk * 2 + aKb));
#pragma unroll
                for (int half = 0; half < 2; half++) {
                    const int nt = ntp * 2 + half;
                    uint32_t bhf[2] = {bh[half], bh[half + 2]};
                    uint32_t blf[2] = {bl[half], bl[half + 2]};
#pragma unroll
                    for (int mt = 0; mt < 4; mt++) {
                        mma_bf16(acc[mt][nt], ah[mt], bhf);
                        mma_bf16(acc[mt][nt], ah[mt], blf);
                        mma_bf16(acc[mt][nt], al[mt], bhf);
                    }
                }
            }
        }
        __syncthreads();
    }

    // ---- epilogue: c fragment -> global (float2 per d-pair) ----
    const int g  = lane >> 2;
    const int tg = lane & 3;
#pragma unroll
    for (int mt = 0; mt < 4; mt++) {
#pragma unroll
        for (int half = 0; half < 2; half++) {
            const int m = m0 + wm * 64 + mt * 16 + g + half * 8;
            float* cp = C + (size_t)m * ldC + n0 + wn * 32;
            const float* ap = Cadd ? (Cadd + (size_t)m * ldC + n0 + wn * 32) : nullptr;
#pragma unroll
            for (int nt = 0; nt < 4; nt++) {
                const int col = nt * 8 + tg * 2;
                float2 v = make_float2(acc[mt][nt][half * 2], acc[mt][nt][half * 2 + 1]);
                if (ap) {
                    float2 c = *(const float2*)(ap + col);
                    v.x += c.x; v.y += c.y;
                }
                *(float2*)(cp + col) = v;
            }
        }
    }
}

// =====================================================================
// RoPE in-place on q,k parts of g_qkv. grid=S, block=512 (16 heads x 32)
// =====================================================================
__global__ void __launch_bounds__(512) rope_kernel()
{
    const int s = blockIdx.x;
    const int h = threadIdx.x >> 5;
    const int j = threadIdx.x & 31;

    const float LOG2_1E4 = 13.28771237954945f;
    float inv = exp2f(-(float)j * (LOG2_1E4 / 32.0f));
    float ang = (float)s * inv;
    float sn, cs;
    sincosf(ang, &sn, &cs);

    float* q = g_qkv + (size_t)s * 3072 + h * 64;
    float* k = q + 1024;

    float q0 = q[j], q1 = q[j + 32];
    q[j]      = q0 * cs - q1 * sn;
    q[j + 32] = q1 * cs + q0 * sn;

    float k0 = k[j], k1 = k[j + 32];
    k[j]      = k0 * cs - k1 * sn;
    k[j + 32] = k1 * cs + k0 * sn;
}

// =====================================================================
// Windowed causal flash attention (fp32 FFMA). Output -> bf16 hi/lo.
// grid = (NHEADS, S/64), block = 256 (16x16), 4x4 microtile.
// =====================================================================
#define APITCH 68

__global__ void __launch_bounds__(256) attn_kernel()
{
    extern __shared__ float sm[];
    float* QT = sm;
    float* KT = sm + 64 * APITCH;
    float* Vs = sm + 2 * 64 * APITCH;
    float* PT = sm + 3 * 64 * APITCH;

    const int h  = blockIdx.x;
    const int q0 = blockIdx.y * 64;
    const int tid = threadIdx.x;
    const int tx = tid & 15;
    const int ty = tid >> 4;

    {
        const int r  = tid >> 2;
        const int c0 = (tid & 3) * 16;
        const float* src = g_qkv + (size_t)(q0 + r) * 3072 + h * 64 + c0;
#pragma unroll
        for (int i = 0; i < 16; i += 4) {
            float4 v = *(const float4*)(src + i);
            QT[(c0 + i + 0) * APITCH + r] = v.x * 0.125f;
            QT[(c0 + i + 1) * APITCH + r] = v.y * 0.125f;
            QT[(c0 + i + 2) * APITCH + r] = v.z * 0.125f;
            QT[(c0 + i + 3) * APITCH + r] = v.w * 0.125f;
        }
    }

    float m_[4], l_[4], O[4][4];
#pragma unroll
    for (int i = 0; i < 4; i++) {
        m_[i] = -1e30f;
        l_[i] = 0.f;
#pragma unroll
        for (int j = 0; j < 4; j++) O[i][j] = 0.f;
    }

    int kstart = q0 - WINDOW;
    if (kstart < 0) kstart = 0;

    for (int kc = kstart; kc <= q0; kc += 64) {
        __syncthreads();
        {
            const int r  = tid >> 2;
            const int c0 = (tid & 3) * 16;
            const float* ks = g_qkv + (size_t)(kc + r) * 3072 + 1024 + h * 64 + c0;
            const float* vs = g_qkv + (size_t)(kc + r) * 3072 + 2048 + h * 64 + c0;
#pragma unroll
            for (int i = 0; i < 16; i += 4) {
                float4 kv = *(const float4*)(ks + i);
                KT[(c0 + i + 0) * APITCH + r] = kv.x;
                KT[(c0 + i + 1) * APITCH + r] = kv.y;
                KT[(c0 + i + 2) * APITCH + r] = kv.z;
                KT[(c0 + i + 3) * APITCH + r] = kv.w;
                float4 vv = *(const float4*)(vs + i);
                *(float4*)(Vs + (size_t)r * APITCH + c0 + i) = vv;
            }
        }
        __syncthreads();

        float acc[4][4];
#pragma unroll
        for (int i = 0; i < 4; i++)
#pragma unroll
            for (int j = 0; j < 4; j++) acc[i][j] = 0.f;

#pragma unroll 8
        for (int d = 0; d < 64; d++) {
            float4 a = *(const float4*)(QT + d * APITCH + ty * 4);
            float4 b = *(const float4*)(KT + d * APITCH + tx * 4);
            float av[4] = {a.x, a.y, a.z, a.w};
            float bv[4] = {b.x, b.y, b.z, b.w};
#pragma unroll
            for (int i = 0; i < 4; i++)
#pragma unroll
                for (int j = 0; j < 4; j++)
                    acc[i][j] = fmaf(av[i], bv[j], acc[i][j]);
        }

#pragma unroll
        for (int i = 0; i < 4; i++) {
            const int q = q0 + ty * 4 + i;
            float rmax = -1e30f;
#pragma unroll
            for (int j = 0; j < 4; j++) {
                const int key = kc + tx * 4 + j;
                const bool ok = (key <= q) && (q - key <= WINDOW);
                if (!ok) acc[i][j] = -1e30f;
                rmax = fmaxf(rmax, acc[i][j]);
            }
#pragma unroll
            for (int o = 8; o >= 1; o >>= 1)
                rmax = fmaxf(rmax, __shfl_xor_sync(0xffffffffu, rmax, o));
            const float mnew = fmaxf(m_[i], rmax);
            const float scale = __expf(m_[i] - mnew);
            float rsum = 0.f;
#pragma unroll
            for (int j = 0; j < 4; j++) {
                const float p = __expf(acc[i][j] - mnew);
                PT[(size_t)(tx * 4 + j) * APITCH + ty * 4 + i] = p;
                rsum += p;
            }
#pragma unroll
            for (int o = 8; o >= 1; o >>= 1)
                rsum += __shfl_xor_sync(0xffffffffu, rsum, o);
            l_[i] = l_[i] * scale + rsum;
            m_[i] = mnew;
#pragma unroll
            for (int j = 0; j < 4; j++) O[i][j] *= scale;
        }
        __syncthreads();

#pragma unroll 8
        for (int k = 0; k < 64; k++) {
            float4 p = *(const float4*)(PT + (size_t)k * APITCH + ty * 4);
            float4 v = *(const float4*)(Vs + (size_t)k * APITCH + tx * 4);
            float pv[4] = {p.x, p.y, p.z, p.w};
            float vv[4] = {v.x, v.y, v.z, v.w};
#pragma unroll
            for (int i = 0; i < 4; i++)
#pragma unroll
                for (int j = 0; j < 4; j++)
                    O[i][j] = fmaf(pv[i], vv[j], O[i][j]);
        }
    }

    // ---- normalize + write split-bf16 [S, H*64] ----
#pragma unroll
    for (int i = 0; i < 4; i++) {
        const int s = q0 + ty * 4 + i;
        const float inv = 1.f / l_[i];
        __nv_bfloat16 hh[4], ll[4];
#pragma unroll
        for (int j = 0; j < 4; j++) {
            float v = O[i][j] * inv;
            hh[j] = __float2bfloat16(v);
            ll[j] = __float2bfloat16(v - __bfloat162float(hh[j]));
        }
        const size_t off = (size_t)s * DMODEL + h * 64 + tx * 4;
        *(uint2*)(g_ahi + off) = *(uint2*)hh;
        *(uint2*)(g_alo + off) = *(uint2*)ll;
    }
}

// =====================================================================
// LayerNorm: grid=S, block=256
// =====================================================================
__global__ void __launch_bounds__(256) ln_kernel(
    const float* __restrict__ gamma, const float* __restrict__ beta,
    float* __restrict__ y)
{
    const int s = blockIdx.x;
    const int tid = threadIdx.x;
    const float* r = g_res + (size_t)s * DMODEL;

    float4 xv = *(const float4*)(r + tid * 4);
    float s1 = xv.x + xv.y + xv.z + xv.w;
    float s2 = xv.x * xv.x + xv.y * xv.y + xv.z * xv.z + xv.w * xv.w;
#pragma unroll
    for (int o = 16; o >= 1; o >>= 1) {
        s1 += __shfl_xor_sync(0xffffffffu, s1, o);
        s2 += __shfl_xor_sync(0xffffffffu, s2, o);
    }
    __shared__ float a1[8], a2[8];
    const int w = tid >> 5, lane = tid & 31;
    if (lane == 0) { a1[w] = s1; a2[w] = s2; }
    __syncthreads();
    float t1 = 0.f, t2 = 0.f;
#pragma unroll
    for (int i = 0; i < 8; i++) { t1 += a1[i]; t2 += a2[i]; }

    const float mu  = t1 * (1.0f / DMODEL);
    const float var = t2 * (1.0f / DMODEL) - mu * mu;
    const float rstd = rsqrtf(var + LN_EPS);

    const int c = tid * 4;
    float4 g = *(const float4*)(gamma + c);
    float4 b = *(const float4*)(beta + c);
    float4 o;
    o.x = (xv.x - mu) * rstd * g.x + b.x;
    o.y = (xv.y - mu) * rstd * g.y + b.y;
    o.z = (xv.z - mu) * rstd * g.z + b.z;
    o.w = (xv.w - mu) * rstd * g.w + b.w;
    *(float4*)(y + (size_t)s * DMODEL + c) = o;
}

// =====================================================================
// launch
// =====================================================================
extern "C" void kernel_launch(void* const* d_in, const int* in_sizes, int n_in,
                              void* d_out, int out_size)
{
    const float* x     = (const float*)d_in[0];
    const float* state = (const float*)d_in[1];
    const float* Wqkv  = (const float*)d_in[2];
    const float* Wout  = (const float*)d_in[3];
    const float* gamma = (const float*)d_in[4];
    const float* beta  = (const float*)d_in[5];
    float* y = (float*)d_out;

    float *qkv, *res;
    __nv_bfloat16 *xhi, *xlo, *ahi, *alo, *wqhi, *wqlo, *wohi, *wolo;
    cudaGetSymbolAddress((void**)&qkv,  g_qkv);
    cudaGetSymbolAddress((void**)&res,  g_res);
    cudaGetSymbolAddress((void**)&xhi,  g_xhi);
    cudaGetSymbolAddress((void**)&xlo,  g_xlo);
    cudaGetSymbolAddress((void**)&ahi,  g_ahi);
    cudaGetSymbolAddress((void**)&alo,  g_alo);
    cudaGetSymbolAddress((void**)&wqhi, g_wqhi);
    cudaGetSymbolAddress((void**)&wqlo, g_wqlo);
    cudaGetSymbolAddress((void**)&wohi, g_wohi);
    cudaGetSymbolAddress((void**)&wolo, g_wolo);

    cudaFuncSetAttribute(gemm_bf16s, cudaFuncAttributeMaxDynamicSharedMemorySize, GEMM_SMEM);
    cudaFuncSetAttribute(attn_kernel, cudaFuncAttributeMaxDynamicSharedMemorySize,
                         4 * 64 * APITCH * (int)sizeof(float));

    // 0) operand prep: split x, transpose+split weights
    split_kernel<<<512, 256>>>((const float4*)x, (uint2*)xhi, (uint2*)xlo,
                               S_LEN * DMODEL / 4);
    wsplit_kernel<<<dim3(3 * DMODEL / 32, DMODEL / 32), 256>>>(Wqkv, wqhi, wqlo,
                                                               DMODEL, 3 * DMODEL);
    wsplit_kernel<<<dim3(DMODEL / 32, DMODEL / 32), 256>>>(Wout, wohi, wolo,
                                                           DMODEL, DMODEL);

    // 1) QKV projection (mma.sync split-bf16, cp.async pipelined)
    gemm_bf16s<<<dim3(3 * DMODEL / 128, S_LEN / 128), 256, GEMM_SMEM>>>(
        xhi, xlo, wqhi, wqlo, qkv, nullptr, 3 * DMODEL);

    // 2) RoPE in place on q,k
    rope_kernel<<<S_LEN, 512>>>();

    // 3) windowed attention (writes split-bf16 output)
    attn_kernel<<<dim3(NHEADS, S_LEN / 64), 256, 4 * 64 * APITCH * sizeof(float)>>>();

    // 4) output projection + residual: res = x + attn @ W_out
    gemm_bf16s<<<dim3(DMODEL / 128, S_LEN / 128), 256, GEMM_SMEM>>>(
        ahi, alo, wohi, wolo, res, x, DMODEL);

    // 5) LayerNorm -> y
    ln_kernel<<<S_LEN, 256>>>(gamma, beta, y);

    // 6) pass-through state if the output buffer includes it
    if (out_size >= S_LEN * DMODEL + DMODEL) {
        cudaMemcpyAsync(y + (size_t)S_LEN * DMODEL, state,
                        DMODEL * sizeof(float), cudaMemcpyDeviceToDevice);
    }
}

// round 7
// speedup vs baseline: 2.0192x; 1.2062x over previous
#include <cuda_runtime.h>
#include <cuda_bf16.h>
#include <math.h>
#include <stdint.h>

#define S_LEN   2048
#define DMODEL  1024
#define NHEADS  16
#define WINDOW  256
#define LN_EPS  1e-5f

// ---------------- scratch (no allocations allowed) ----------------
__device__ float g_qkv[(size_t)S_LEN * 3 * DMODEL];   // [S, 3*D] fp32 (q | k | v)
__device__ float g_res[(size_t)S_LEN * DMODEL];       // residual pre-LN

// split-bf16 operands
__device__ __nv_bfloat16 g_xhi[(size_t)S_LEN * DMODEL];
__device__ __nv_bfloat16 g_xlo[(size_t)S_LEN * DMODEL];
__device__ __nv_bfloat16 g_ahi[(size_t)S_LEN * DMODEL];   // attention out hi
__device__ __nv_bfloat16 g_alo[(size_t)S_LEN * DMODEL];   // attention out lo
__device__ __nv_bfloat16 g_wqhi[(size_t)3 * DMODEL * DMODEL];  // W_qkv^T [3072,1024]
__device__ __nv_bfloat16 g_wqlo[(size_t)3 * DMODEL * DMODEL];
__device__ __nv_bfloat16 g_wohi[(size_t)DMODEL * DMODEL];      // W_out^T [1024,1024]
__device__ __nv_bfloat16 g_wolo[(size_t)DMODEL * DMODEL];

// attention operands (split bf16)
__device__ __nv_bfloat16 g_qh[(size_t)S_LEN * DMODEL];  // [s][h*64+d], pre-scaled 1/8
__device__ __nv_bfloat16 g_ql[(size_t)S_LEN * DMODEL];
__device__ __nv_bfloat16 g_kh[(size_t)S_LEN * DMODEL];
__device__ __nv_bfloat16 g_kl[(size_t)S_LEN * DMODEL];
__device__ __nv_bfloat16 g_vh[(size_t)DMODEL * S_LEN];  // transposed: [h*64+d][s]
__device__ __nv_bfloat16 g_vl[(size_t)DMODEL * S_LEN];

// =====================================================================
// warp-level tensor-core helpers (sm_80+ baseline)
// =====================================================================
__device__ __forceinline__ uint32_t smem_u32(const void* p) {
    uint32_t a;
    asm("{ .reg .u64 t; cvta.to.shared.u64 t, %1; cvt.u32.u64 %0, t; }" : "=r"(a) : "l"(p));
    return a;
}
__device__ __forceinline__ void ldsm_x4(uint32_t* r, uint32_t addr) {
    asm volatile("ldmatrix.sync.aligned.m8n8.x4.shared.b16 {%0,%1,%2,%3}, [%4];"
                 : "=r"(r[0]), "=r"(r[1]), "=r"(r[2]), "=r"(r[3]) : "r"(addr));
}
__device__ __forceinline__ void mma_bf16(float* d, const uint32_t* a, const uint32_t* b) {
    asm volatile(
        "mma.sync.aligned.m16n8k16.row.col.f32.bf16.bf16.f32 "
        "{%0,%1,%2,%3}, {%4,%5,%6,%7}, {%8,%9}, {%0,%1,%2,%3};"
        : "+f"(d[0]), "+f"(d[1]), "+f"(d[2]), "+f"(d[3])
        : "r"(a[0]), "r"(a[1]), "r"(a[2]), "r"(a[3]), "r"(b[0]), "r"(b[1]));
}
__device__ __forceinline__ void cp16(uint32_t dst, const void* src) {
    asm volatile("cp.async.cg.shared.global [%0], [%1], 16;" :: "r"(dst), "l"(src));
}
__device__ __forceinline__ void cp_commit() {
    asm volatile("cp.async.commit_group;" ::: "memory");
}
template <int N>
__device__ __forceinline__ void cp_wait() {
    asm volatile("cp.async.wait_group %0;" :: "n"(N) : "memory");
}

#define SWZ128(bo) ((bo) ^ (((bo) >> 3) & 0x70))

__device__ __forceinline__ uint32_t pack_bf2(float a, float b) {
    __nv_bfloat162 p = {__float2bfloat16(a), __float2bfloat16(b)};
    return *(uint32_t*)&p;
}

// =====================================================================
// split x -> bf16 hi/lo
// =====================================================================
__global__ void __launch_bounds__(256) split_kernel(
    const float4* __restrict__ in, uint2* __restrict__ hi, uint2* __restrict__ lo, int n4)
{
    for (int i = blockIdx.x * blockDim.x + threadIdx.x; i < n4; i += gridDim.x * blockDim.x) {
        float4 v = in[i];
        __nv_bfloat16 h0 = __float2bfloat16(v.x), h1 = __float2bfloat16(v.y);
        __nv_bfloat16 h2 = __float2bfloat16(v.z), h3 = __float2bfloat16(v.w);
        __nv_bfloat16 l0 = __float2bfloat16(v.x - __bfloat162float(h0));
        __nv_bfloat16 l1 = __float2bfloat16(v.y - __bfloat162float(h1));
        __nv_bfloat16 l2 = __float2bfloat16(v.z - __bfloat162float(h2));
        __nv_bfloat16 l3 = __float2bfloat16(v.w - __bfloat162float(h3));
        __nv_bfloat162 hp0 = {h0, h1}, hp1 = {h2, h3};
        __nv_bfloat162 lp0 = {l0, l1}, lp1 = {l2, l3};
        hi[i] = make_uint2(*(uint32_t*)&hp0, *(uint32_t*)&hp1);
        lo[i] = make_uint2(*(uint32_t*)&lp0, *(uint32_t*)&lp1);
    }
}

// =====================================================================
// transpose + split: W [K,N] fp32 -> Wt hi/lo [N,K] bf16
// =====================================================================
__global__ void __launch_bounds__(256) wsplit_kernel(
    const float* __restrict__ W, __nv_bfloat16* __restrict__ hi,
    __nv_bfloat16* __restrict__ lo, int K, int N)
{
    __shared__ float t[32][33];
    const int tx = threadIdx.x & 31;
    const int ty = threadIdx.x >> 5;
    const int bn = blockIdx.x * 32;
    const int bk = blockIdx.y * 32;
#pragma unroll
    for (int i = 0; i < 32; i += 8)
        t[ty + i][tx] = W[(size_t)(bk + ty + i) * N + bn + tx];
    __syncthreads();
#pragma unroll
    for (int i = 0; i < 32; i += 8) {
        float v = t[tx][ty + i];
        __nv_bfloat16 h = __float2bfloat16(v);
        __nv_bfloat16 l = __float2bfloat16(v - __bfloat162float(h));
        size_t o = (size_t)(bn + ty + i) * K + bk + tx;
        hi[o] = h;
        lo[o] = l;
    }
}

// =====================================================================
// V transpose + split: g_qkv v region [s][c] -> g_vh/g_vl [c][s]
// =====================================================================
__global__ void __launch_bounds__(256) vsplit_kernel()
{
    __shared__ float t[32][33];
    const int tx = threadIdx.x & 31;
    const int ty = threadIdx.x >> 5;
    const int c0 = blockIdx.x * 32;   // v column (0..1023)
    const int s0 = blockIdx.y * 32;   // sequence
#pragma unroll
    for (int i = 0; i < 32; i += 8)
        t[ty + i][tx] = g_qkv[(size_t)(s0 + ty + i) * 3072 + 2048 + c0 + tx];
    __syncthreads();
#pragma unroll
    for (int i = 0; i < 32; i += 8) {
        float v = t[tx][ty + i];   // element (s = s0+tx, c = c0+ty+i)
        __nv_bfloat16 h = __float2bfloat16(v);
        __nv_bfloat16 l = __float2bfloat16(v - __bfloat162float(h));
        size_t o = (size_t)(c0 + ty + i) * S_LEN + s0 + tx;
        g_vh[o] = h;
        g_vl[o] = l;
    }
}

// =====================================================================
// split-bf16 tensor-core GEMM, 3-stage cp.async pipeline, 1 sync/chunk.
// CTA 128x128, K-chunk 32. 8 warps 2x4 (warp 64x32).
// SMEM row (128B SW128): [hi 64B | lo 64B]. Stage 32KB; 3 stages = 96KB.
// =====================================================================
#define GEMM_SMEM (3 * 32768)

__global__ void __launch_bounds__(256, 2) gemm_bf16s(
    const __nv_bfloat16* __restrict__ Ahi, const __nv_bfloat16* __restrict__ Alo,
    const __nv_bfloat16* __restrict__ Bhi, const __nv_bfloat16* __restrict__ Blo,
    float* __restrict__ C, const float* __restrict__ Cadd, int ldC)
{
    extern __shared__ char smem[];
    const uint32_t sb = smem_u32(smem);

    const int tid  = threadIdx.x;
    const int wid  = tid >> 5;
    const int lane = tid & 31;
    const int wm   = wid & 1;
    const int wn   = wid >> 1;
    const int m0 = blockIdx.y * 128;
    const int n0 = blockIdx.x * 128;

    float acc[4][4][4];
#pragma unroll
    for (int i = 0; i < 4; i++)
#pragma unroll
        for (int j = 0; j < 4; j++)
#pragma unroll
            for (int c = 0; c < 4; c++) acc[i][j][c] = 0.f;

    const int r = tid >> 1;
    const int h = tid & 1;
    const __nv_bfloat16* gAh = Ahi + (size_t)(m0 + r) * DMODEL + h * 16;
    const __nv_bfloat16* gAl = Alo + (size_t)(m0 + r) * DMODEL + h * 16;
    const __nv_bfloat16* gBh = Bhi + (size_t)(n0 + r) * DMODEL + h * 16;
    const __nv_bfloat16* gBl = Blo + (size_t)(n0 + r) * DMODEL + h * 16;
    const uint32_t dhi0 = SWZ128((uint32_t)(r * 128 + h * 32));
    const uint32_t dhi1 = SWZ128((uint32_t)(r * 128 + h * 32 + 16));
    const uint32_t dlo0 = SWZ128((uint32_t)(r * 128 + 64 + h * 32));
    const uint32_t dlo1 = SWZ128((uint32_t)(r * 128 + 64 + h * 32 + 16));

    const int aRow = wm * 64 + (lane & 15);
    const int aKb  = (lane >> 4) << 4;
    const int bRow = wn * 32 + (lane & 15);

    const int NCH = DMODEL / 32;

#define LOAD_STAGE(kc, s)                                                   \
    do {                                                                    \
        const uint32_t bA = sb + (s) * 32768;                               \
        const uint32_t bB = bA + 16384;                                     \
        cp16(bA + dhi0, gAh + (kc));                                        \
        cp16(bA + dhi1, gAh + (kc) + 8);                                    \
        cp16(bA + dlo0, gAl + (kc));                                        \
        cp16(bA + dlo1, gAl + (kc) + 8);                                    \
        cp16(bB + dhi0, gBh + (kc));                                        \
        cp16(bB + dhi1, gBh + (kc) + 8);                                    \
        cp16(bB + dlo0, gBl + (kc));                                        \
        cp16(bB + dlo1, gBl + (kc) + 8);                                    \
    } while (0)

    LOAD_STAGE(0, 0);
    cp_commit();
    LOAD_STAGE(32, 1);
    cp_commit();

    for (int it = 0; it < NCH; it++) {
        if (it + 1 < NCH) cp_wait<1>(); else cp_wait<0>();
        __syncthreads();
        if (it + 2 < NCH) {
            LOAD_STAGE((it + 2) * 32, (it + 2) % 3);
            cp_commit();
        }

        const uint32_t bA = sb + (uint32_t)(it % 3) * 32768;
        const uint32_t bB = bA + 16384;

#pragma unroll
        for (int kk = 0; kk < 32; kk += 16) {
            uint32_t ah[4][4], al[4][4];
#pragma unroll
            for (int mt = 0; mt < 4; mt++) {
                const uint32_t row = (uint32_t)(aRow + mt * 16) * 128;
                ldsm_x4(ah[mt], bA + SWZ128(row + kk * 2 + aKb));
                ldsm_x4(al[mt], bA + SWZ128(row + 64 + kk * 2 + aKb));
            }
#pragma unroll
            for (int ntp = 0; ntp < 2; ntp++) {
                const uint32_t row = (uint32_t)(bRow + ntp * 16) * 128;
                uint32_t bh[4], bl[4];
                ldsm_x4(bh, bB + SWZ128(row + kk * 2 + aKb));
                ldsm_x4(bl, bB + SWZ128(row + 64 + kk * 2 + aKb));
#pragma unroll
                for (int half = 0; half < 2; half++) {
                    const int nt = ntp * 2 + half;
                    uint32_t bhf[2] = {bh[half], bh[half + 2]};
                    uint32_t blf[2] = {bl[half], bl[half + 2]};
#pragma unroll
                    for (int mt = 0; mt < 4; mt++) {
                        mma_bf16(acc[mt][nt], ah[mt], bhf);
                        mma_bf16(acc[mt][nt], ah[mt], blf);
                        mma_bf16(acc[mt][nt], al[mt], bhf);
                    }
                }
            }
        }
    }

    const int g  = lane >> 2;
    const int tg = lane & 3;
#pragma unroll
    for (int mt = 0; mt < 4; mt++) {
#pragma unroll
        for (int half = 0; half < 2; half++) {
            const int m = m0 + wm * 64 + mt * 16 + g + half * 8;
            float* cp = C + (size_t)m * ldC + n0 + wn * 32;
            const float* ap = Cadd ? (Cadd + (size_t)m * ldC + n0 + wn * 32) : nullptr;
#pragma unroll
            for (int nt = 0; nt < 4; nt++) {
                const int col = nt * 8 + tg * 2;
                float2 v = make_float2(acc[mt][nt][half * 2], acc[mt][nt][half * 2 + 1]);
                if (ap) {
                    float2 c = *(const float2*)(ap + col);
                    v.x += c.x; v.y += c.y;
                }
                *(float2*)(cp + col) = v;
            }
        }
    }
}

// =====================================================================
// RoPE: read fp32 q,k from g_qkv, emit bf16 hi/lo (q pre-scaled 1/8).
// =====================================================================
__global__ void __launch_bounds__(512) rope_kernel()
{
    const int s = blockIdx.x;
    const int h = threadIdx.x >> 5;
    const int j = threadIdx.x & 31;

    const float LOG2_1E4 = 13.28771237954945f;
    float inv = exp2f(-(float)j * (LOG2_1E4 / 32.0f));
    float ang = (float)s * inv;
    float sn, cs;
    sincosf(ang, &sn, &cs);

    const float* q = g_qkv + (size_t)s * 3072 + h * 64;
    const float* k = q + 1024;

    float q0 = q[j], q1 = q[j + 32];
    float qr0 = (q0 * cs - q1 * sn) * 0.125f;
    float qr1 = (q1 * cs + q0 * sn) * 0.125f;
    float k0 = k[j], k1 = k[j + 32];
    float kr0 = k0 * cs - k1 * sn;
    float kr1 = k1 * cs + k0 * sn;

    const size_t o = (size_t)s * DMODEL + h * 64 + j;
    __nv_bfloat16 hh;
    hh = __float2bfloat16(qr0); g_qh[o] = hh; g_ql[o] = __float2bfloat16(qr0 - __bfloat162float(hh));
    hh = __float2bfloat16(qr1); g_qh[o + 32] = hh; g_ql[o + 32] = __float2bfloat16(qr1 - __bfloat162float(hh));
    hh = __float2bfloat16(kr0); g_kh[o] = hh; g_kl[o] = __float2bfloat16(kr0 - __bfloat162float(hh));
    hh = __float2bfloat16(kr1); g_kh[o + 32] = hh; g_kl[o + 32] = __float2bfloat16(kr1 - __bfloat162float(hh));
}

// =====================================================================
// Windowed causal flash attention, tensor-core (split-bf16 mma.sync).
// grid = (NHEADS, S/64), 256 threads = 8 warps (2x4).
// Per chunk: S=QK^T (mma) -> smem -> fp32 online softmax -> P (bf16 hi/lo
// smem) -> O += P*V (mma). K double-buffered cp.async.
// =====================================================================
// smem layout (bytes):
#define AQH 0u
#define AQL 8192u
#define AKB0 16384u
#define AKB1 32768u
#define AVH 49152u
#define AVL 57344u
#define ASS 65536u               // S fp32 [64][68]
#define APH 82944u               // P hi [64 rows][128B] SW128
#define APL 91136u
#define AROW 99328u              // 64 floats row scales
#define ATT_SMEM 99584

__global__ void __launch_bounds__(256) attn_kernel()
{
    extern __shared__ char sm[];
    const uint32_t sb = smem_u32(sm);
    float* sS   = (float*)(sm + ASS);
    float* sRow = (float*)(sm + AROW);

    const int h   = blockIdx.x;
    const int q0  = blockIdx.y * 64;
    const int tid = threadIdx.x;
    const int wid = tid >> 5, lane = tid & 31;
    const int wm = wid & 1, wn = wid >> 1;
    const int g = lane >> 2, tg = lane & 3;
    const int tx = tid & 15, ty = tid >> 4;

    // tile-load mapping: 64 rows x 128B, 4 threads/row, 2x16B per thread
    const int r4 = tid >> 2;
    const int s4 = (tid & 3) * 2;
    const uint32_t tdst0 = SWZ128((uint32_t)(r4 * 128 + s4 * 16));
    const uint32_t tdst1 = SWZ128((uint32_t)(r4 * 128 + s4 * 16 + 16));

#define ATL(dstbase, srcptr)                         \
    do {                                             \
        cp16((dstbase) + tdst0, (srcptr));           \
        cp16((dstbase) + tdst1, (srcptr) + 8);       \
    } while (0)

    const int kstart = (q0 - WINDOW) < 0 ? 0 : (q0 - WINDOW);
    const int nch = (q0 - kstart) / 64 + 1;

    // prologue: Q (hi+lo) and K chunk 0 -> buf0, one cp group
    ATL(sb + AQH, g_qh + (size_t)(q0 + r4) * DMODEL + h * 64 + s4 * 8);
    ATL(sb + AQL, g_ql + (size_t)(q0 + r4) * DMODEL + h * 64 + s4 * 8);
    ATL(sb + AKB0,        g_kh + (size_t)(kstart + r4) * DMODEL + h * 64 + s4 * 8);
    ATL(sb + AKB0 + 8192, g_kl + (size_t)(kstart + r4) * DMODEL + h * 64 + s4 * 8);
    cp_commit();

    // persistent state
    float o[2][2][4];
#pragma unroll
    for (int i = 0; i < 2; i++)
#pragma unroll
        for (int j = 0; j < 2; j++)
#pragma unroll
            for (int c = 0; c < 4; c++) o[i][j][c] = 0.f;
    float m_[4], l_[4];
#pragma unroll
    for (int i = 0; i < 4; i++) { m_[i] = -1e30f; l_[i] = 0.f; }

    const int kb = (lane >> 4) * 16;            // k-half byte offset for ldsm
    const int aRowQ = wm * 32 + (lane & 15);    // + mt*16
    const int bRow  = wn * 16 + (lane & 15);

    for (int it = 0; it < nch; it++) {
        const int kc = kstart + it * 64;
        const uint32_t KB  = (it & 1) ? AKB1 : AKB0;
        const uint32_t KBn = (it & 1) ? AKB0 : AKB1;
        const bool pf = (it + 1 < nch);

        cp_wait<0>();          // K(it) resident (and Q on it==0)
        __syncthreads();       // all parts visible; sV free (prev PV done)

        // V(it) load (consumed after softmax)
        ATL(sb + AVH, g_vh + (size_t)(h * 64 + r4) * S_LEN + kc + s4 * 8);
        ATL(sb + AVL, g_vl + (size_t)(h * 64 + r4) * S_LEN + kc + s4 * 8);
        cp_commit();

        // ---- S = Q K^T (3-product split) ----
        float sacc[2][2][4];
#pragma unroll
        for (int i = 0; i < 2; i++)
#pragma unroll
            for (int j = 0; j < 2; j++)
#pragma unroll
                for (int c = 0; c < 4; c++) sacc[i][j][c] = 0.f;

#pragma unroll
        for (int kk = 0; kk < 4; kk++) {
            uint32_t ah[2][4], al[2][4];
#pragma unroll
            for (int mt = 0; mt < 2; mt++) {
                const uint32_t row = (uint32_t)(aRowQ + mt * 16) * 128;
                ldsm_x4(ah[mt], sb + AQH + SWZ128(row + kk * 32 + kb));
                ldsm_x4(al[mt], sb + AQL + SWZ128(row + kk * 32 + kb));
            }
            uint32_t bh[4], bl[4];
            const uint32_t brow = (uint32_t)bRow * 128;
            ldsm_x4(bh, sb + KB + SWZ128(brow + kk * 32 + kb));
            ldsm_x4(bl, sb + KB + 8192 + SWZ128(brow + kk * 32 + kb));
#pragma unroll
            for (int nt = 0; nt < 2; nt++) {
                uint32_t bhf[2] = {bh[nt], bh[nt + 2]};
                uint32_t blf[2] = {bl[nt], bl[nt + 2]};
#pragma unroll
                for (int mt = 0; mt < 2; mt++) {
                    mma_bf16(sacc[mt][nt], ah[mt], bhf);
                    mma_bf16(sacc[mt][nt], ah[mt], blf);
                    mma_bf16(sacc[mt][nt], al[mt], bhf);
                }
            }
        }

        // prefetch next K (other buffer)
        if (pf) {
            ATL(sb + KBn,        g_kh + (size_t)(kc + 64 + r4) * DMODEL + h * 64 + s4 * 8);
            ATL(sb + KBn + 8192, g_kl + (size_t)(kc + 64 + r4) * DMODEL + h * 64 + s4 * 8);
            cp_commit();
        }

        // ---- S fragments -> smem ----
#pragma unroll
        for (int mt = 0; mt < 2; mt++) {
#pragma unroll
            for (int nt = 0; nt < 2; nt++) {
                const int rr = wm * 32 + mt * 16 + g;
                const int cc = wn * 16 + nt * 8 + tg * 2;
                *(float2*)&sS[rr * 68 + cc]       = make_float2(sacc[mt][nt][0], sacc[mt][nt][1]);
                *(float2*)&sS[(rr + 8) * 68 + cc] = make_float2(sacc[mt][nt][2], sacc[mt][nt][3]);
            }
        }
        __syncthreads();

        // ---- fp32 online softmax (tx/ty layout, 4x4 per thread) ----
#pragma unroll
        for (int i = 0; i < 4; i++) {
            const int q = q0 + ty * 4 + i;
            float sv[4];
            float rmax = -1e30f;
#pragma unroll
            for (int j = 0; j < 4; j++) {
                const int key = kc + tx * 4 + j;
                float v = sS[(ty * 4 + i) * 68 + tx * 4 + j];
                const bool ok = (key <= q) && (q - key <= WINDOW);
                sv[j] = ok ? v : -1e30f;
                rmax = fmaxf(rmax, sv[j]);
            }
#pragma unroll
            for (int of = 8; of >= 1; of >>= 1)
                rmax = fmaxf(rmax, __shfl_xor_sync(0xffffffffu, rmax, of));
            const float mnew = fmaxf(m_[i], rmax);
            const float scale = __expf(m_[i] - mnew);
            float p[4], rsum = 0.f;
#pragma unroll
            for (int j = 0; j < 4; j++) { p[j] = __expf(sv[j] - mnew); rsum += p[j]; }
            // write P hi/lo (row = local q, cols = local keys)
            {
                uint32_t hp0 = pack_bf2(p[0], p[1]);
                uint32_t hp1 = pack_bf2(p[2], p[3]);
                float r0 = p[0] - __bfloat162float(__float2bfloat16(p[0]));
                float r1 = p[1] - __bfloat162float(__float2bfloat16(p[1]));
                float r2 = p[2] - __bfloat162float(__float2bfloat16(p[2]));
                float r3 = p[3] - __bfloat162float(__float2bfloat16(p[3]));
                uint32_t lp0 = pack_bf2(r0, r1);
                uint32_t lp1 = pack_bf2(r2, r3);
                const uint32_t off = SWZ128((uint32_t)((ty * 4 + i) * 128 + tx * 8));
                *(uint2*)(sm + APH + off) = make_uint2(hp0, hp1);
                *(uint2*)(sm + APL + off) = make_uint2(lp0, lp1);
            }
#pragma unroll
            for (int of = 8; of >= 1; of >>= 1)
                rsum += __shfl_xor_sync(0xffffffffu, rsum, of);
            l_[i] = l_[i] * scale + rsum;
            m_[i] = mnew;
            if (tx == 0) sRow[ty * 4 + i] = scale;
        }

        if (pf) cp_wait<1>(); else cp_wait<0>();   // V resident
        __syncthreads();                            // P + sRow + V visible

        // ---- rescale O, then O += P V ----
#pragma unroll
        for (int mt = 0; mt < 2; mt++) {
            const float rs0 = sRow[wm * 32 + mt * 16 + g];
            const float rs1 = sRow[wm * 32 + mt * 16 + g + 8];
#pragma unroll
            for (int nt = 0; nt < 2; nt++) {
                o[mt][nt][0] *= rs0; o[mt][nt][1] *= rs0;
                o[mt][nt][2] *= rs1; o[mt][nt][3] *= rs1;
            }
        }
#pragma unroll
        for (int kk = 0; kk < 4; kk++) {
            uint32_t ah[2][4], al[2][4];
#pragma unroll
            for (int mt = 0; mt < 2; mt++) {
                const uint32_t row = (uint32_t)(aRowQ + mt * 16) * 128;
                ldsm_x4(ah[mt], sb + APH + SWZ128(row + kk * 32 + kb));
                ldsm_x4(al[mt], sb + APL + SWZ128(row + kk * 32 + kb));
            }
            uint32_t bh[4], bl[4];
            const uint32_t brow = (uint32_t)bRow * 128;
            ldsm_x4(bh, sb + AVH + SWZ128(brow + kk * 32 + kb));
            ldsm_x4(bl, sb + AVL + SWZ128(brow + kk * 32 + kb));
#pragma unroll
            for (int nt = 0; nt < 2; nt++) {
                uint32_t bhf[2] = {bh[nt], bh[nt + 2]};
                uint32_t blf[2] = {bl[nt], bl[nt + 2]};
#pragma unroll
                for (int mt = 0; mt < 2; mt++) {
                    mma_bf16(o[mt][nt], ah[mt], bhf);
                    mma_bf16(o[mt][nt], ah[mt], blf);
                    mma_bf16(o[mt][nt], al[mt], bhf);
                }
            }
        }
    }

    // final 1/l per row
    __syncthreads();
#pragma unroll
    for (int i = 0; i < 4; i++)
        if (tx == 0) sRow[ty * 4 + i] = 1.f / l_[i];
    __syncthreads();

    // write O (split bf16) to g_ahi/g_alo [s][h*64+d]
#pragma unroll
    for (int mt = 0; mt < 2; mt++) {
        const int r0 = wm * 32 + mt * 16 + g;
        const float inv0 = sRow[r0], inv1 = sRow[r0 + 8];
#pragma unroll
        for (int nt = 0; nt < 2; nt++) {
            const int col = h * 64 + wn * 16 + nt * 8 + tg * 2;
#pragma unroll
            for (int half = 0; half < 2; half++) {
                const float iv = half ? inv1 : inv0;
                const int rr = r0 + half * 8;
                const float v0 = o[mt][nt][half * 2] * iv;
                const float v1 = o[mt][nt][half * 2 + 1] * iv;
                const __nv_bfloat16 h0 = __float2bfloat16(v0);
                const __nv_bfloat16 h1 = __float2bfloat16(v1);
                __nv_bfloat162 hp = {h0, h1};
                __nv_bfloat162 lp = {__float2bfloat16(v0 - __bfloat162float(h0)),
                                     __float2bfloat16(v1 - __bfloat162float(h1))};
                const size_t off = (size_t)(q0 + rr) * DMODEL + col;
                *(uint32_t*)(g_ahi + off) = *(uint32_t*)&hp;
                *(uint32_t*)(g_alo + off) = *(uint32_t*)&lp;
            }
        }
    }
}

// =====================================================================
// LayerNorm: grid=S, block=256
// =====================================================================
__global__ void __launch_bounds__(256) ln_kernel(
    const float* __restrict__ gamma, const float* __restrict__ beta,
    float* __restrict__ y)
{
    const int s = blockIdx.x;
    const int tid = threadIdx.x;
    const float* r = g_res + (size_t)s * DMODEL;

    float4 xv = *(const float4*)(r + tid * 4);
    float s1 = xv.x + xv.y + xv.z + xv.w;
    float s2 = xv.x * xv.x + xv.y * xv.y + xv.z * xv.z + xv.w * xv.w;
#pragma unroll
    for (int o = 16; o >= 1; o >>= 1) {
        s1 += __shfl_xor_sync(0xffffffffu, s1, o);
        s2 += __shfl_xor_sync(0xffffffffu, s2, o);
    }
    __shared__ float a1[8], a2[8];
    const int w = tid >> 5, lane = tid & 31;
    if (lane == 0) { a1[w] = s1; a2[w] = s2; }
    __syncthreads();
    float t1 = 0.f, t2 = 0.f;
#pragma unroll
    for (int i = 0; i < 8; i++) { t1 += a1[i]; t2 += a2[i]; }

    const float mu  = t1 * (1.0f / DMODEL);
    const float var = t2 * (1.0f / DMODEL) - mu * mu;
    const float rstd = rsqrtf(var + LN_EPS);

    const int c = tid * 4;
    float4 gm = *(const float4*)(gamma + c);
    float4 b = *(const float4*)(beta + c);
    float4 o;
    o.x = (xv.x - mu) * rstd * gm.x + b.x;
    o.y = (xv.y - mu) * rstd * gm.y + b.y;
    o.z = (xv.z - mu) * rstd * gm.z + b.z;
    o.w = (xv.w - mu) * rstd * gm.w + b.w;
    *(float4*)(y + (size_t)s * DMODEL + c) = o;
}

// =====================================================================
// launch
// =====================================================================
extern "C" void kernel_launch(void* const* d_in, const int* in_sizes, int n_in,
                              void* d_out, int out_size)
{
    const float* x     = (const float*)d_in[0];
    const float* state = (const float*)d_in[1];
    const float* Wqkv  = (const float*)d_in[2];
    const float* Wout  = (const float*)d_in[3];
    const float* gamma = (const float*)d_in[4];
    const float* beta  = (const float*)d_in[5];
    float* y = (float*)d_out;

    float *qkv, *res;
    __nv_bfloat16 *xhi, *xlo, *ahi, *alo, *wqhi, *wqlo, *wohi, *wolo;
    cudaGetSymbolAddress((void**)&qkv,  g_qkv);
    cudaGetSymbolAddress((void**)&res,  g_res);
    cudaGetSymbolAddress((void**)&xhi,  g_xhi);
    cudaGetSymbolAddress((void**)&xlo,  g_xlo);
    cudaGetSymbolAddress((void**)&ahi,  g_ahi);
    cudaGetSymbolAddress((void**)&alo,  g_alo);
    cudaGetSymbolAddress((void**)&wqhi, g_wqhi);
    cudaGetSymbolAddress((void**)&wqlo, g_wqlo);
    cudaGetSymbolAddress((void**)&wohi, g_wohi);
    cudaGetSymbolAddress((void**)&wolo, g_wolo);

    cudaFuncSetAttribute(gemm_bf16s, cudaFuncAttributeMaxDynamicSharedMemorySize, GEMM_SMEM);
    cudaFuncSetAttribute(attn_kernel, cudaFuncAttributeMaxDynamicSharedMemorySize, ATT_SMEM);

    // 0) operand prep
    split_kernel<<<512, 256>>>((const float4*)x, (uint2*)xhi, (uint2*)xlo,
                               S_LEN * DMODEL / 4);
    wsplit_kernel<<<dim3(3 * DMODEL / 32, DMODEL / 32), 256>>>(Wqkv, wqhi, wqlo,
                                                               DMODEL, 3 * DMODEL);
    wsplit_kernel<<<dim3(DMODEL / 32, DMODEL / 32), 256>>>(Wout, wohi, wolo,
                                                           DMODEL, DMODEL);

    // 1) QKV projection
    gemm_bf16s<<<dim3(3 * DMODEL / 128, S_LEN / 128), 256, GEMM_SMEM>>>(
        xhi, xlo, wqhi, wqlo, qkv, nullptr, 3 * DMODEL);

    // 2) RoPE -> bf16 split q,k ; V transpose+split
    rope_kernel<<<S_LEN, 512>>>();
    vsplit_kernel<<<dim3(DMODEL / 32, S_LEN / 32), 256>>>();

    // 3) windowed attention (tensor cores)
    attn_kernel<<<dim3(NHEADS, S_LEN / 64), 256, ATT_SMEM>>>();

    // 4) output projection + residual
    gemm_bf16s<<<dim3(DMODEL / 128, S_LEN / 128), 256, GEMM_SMEM>>>(
        ahi, alo, wohi, wolo, res, x, DMODEL);

    // 5) LayerNorm -> y
    ln_kernel<<<S_LEN, 256>>>(gamma, beta, y);

    // 6) pass-through state if the output buffer includes it
    if (out_size >= S_LEN * DMODEL + DMODEL) {
        cudaMemcpyAsync(y + (size_t)S_LEN * DMODEL, state,
                        DMODEL * sizeof(float), cudaMemcpyDeviceToDevice);
    }
}

// round 8
// speedup vs baseline: 2.0210x; 1.0009x over previous
#include <cuda_runtime.h>
#include <cuda_bf16.h>
#include <math.h>
#include <stdint.h>

#define S_LEN   2048
#define DMODEL  1024
#define NHEADS  16
#define WINDOW  256
#define LN_EPS  1e-5f

// ---------------- scratch (no allocations allowed) ----------------
__device__ float g_qkv[(size_t)S_LEN * 3 * DMODEL];   // [S, 3*D] fp32 (q | k | v)
__device__ float g_res[(size_t)S_LEN * DMODEL];       // residual pre-LN

// split-bf16 operands
__device__ __nv_bfloat16 g_xhi[(size_t)S_LEN * DMODEL];
__device__ __nv_bfloat16 g_xlo[(size_t)S_LEN * DMODEL];
__device__ __nv_bfloat16 g_ahi[(size_t)S_LEN * DMODEL];   // attention out hi
__device__ __nv_bfloat16 g_alo[(size_t)S_LEN * DMODEL];   // attention out lo
__device__ __nv_bfloat16 g_wqhi[(size_t)3 * DMODEL * DMODEL];  // W_qkv^T [3072,1024]
__device__ __nv_bfloat16 g_wqlo[(size_t)3 * DMODEL * DMODEL];
__device__ __nv_bfloat16 g_wohi[(size_t)DMODEL * DMODEL];      // W_out^T [1024,1024]
__device__ __nv_bfloat16 g_wolo[(size_t)DMODEL * DMODEL];

// attention operands (split bf16)
__device__ __nv_bfloat16 g_qh[(size_t)S_LEN * DMODEL];  // [s][h*64+d], pre-scaled 1/8
__device__ __nv_bfloat16 g_ql[(size_t)S_LEN * DMODEL];
__device__ __nv_bfloat16 g_kh[(size_t)S_LEN * DMODEL];
__device__ __nv_bfloat16 g_kl[(size_t)S_LEN * DMODEL];
__device__ __nv_bfloat16 g_vh[(size_t)DMODEL * S_LEN];  // transposed: [h*64+d][s]
__device__ __nv_bfloat16 g_vl[(size_t)DMODEL * S_LEN];

// =====================================================================
// warp-level tensor-core helpers (sm_80+ baseline)
// =====================================================================
__device__ __forceinline__ uint32_t smem_u32(const void* p) {
    uint32_t a;
    asm("{ .reg .u64 t; cvta.to.shared.u64 t, %1; cvt.u32.u64 %0, t; }" : "=r"(a) : "l"(p));
    return a;
}
__device__ __forceinline__ void ldsm_x4(uint32_t* r, uint32_t addr) {
    asm volatile("ldmatrix.sync.aligned.m8n8.x4.shared.b16 {%0,%1,%2,%3}, [%4];"
                 : "=r"(r[0]), "=r"(r[1]), "=r"(r[2]), "=r"(r[3]) : "r"(addr));
}
__device__ __forceinline__ void mma_bf16(float* d, const uint32_t* a, const uint32_t* b) {
    asm volatile(
        "mma.sync.aligned.m16n8k16.row.col.f32.bf16.bf16.f32 "
        "{%0,%1,%2,%3}, {%4,%5,%6,%7}, {%8,%9}, {%0,%1,%2,%3};"
        : "+f"(d[0]), "+f"(d[1]), "+f"(d[2]), "+f"(d[3])
        : "r"(a[0]), "r"(a[1]), "r"(a[2]), "r"(a[3]), "r"(b[0]), "r"(b[1]));
}
__device__ __forceinline__ void cp16(uint32_t dst, const void* src) {
    asm volatile("cp.async.cg.shared.global [%0], [%1], 16;" :: "r"(dst), "l"(src));
}
__device__ __forceinline__ void cp_commit() {
    asm volatile("cp.async.commit_group;" ::: "memory");
}
template <int N>
__device__ __forceinline__ void cp_wait() {
    asm volatile("cp.async.wait_group %0;" :: "n"(N) : "memory");
}

#define SWZ128(bo) ((bo) ^ (((bo) >> 3) & 0x70))

__device__ __forceinline__ uint32_t pack_bf2(float a, float b) {
    __nv_bfloat162 p = {__float2bfloat16(a), __float2bfloat16(b)};
    return *(uint32_t*)&p;
}

// =====================================================================
// split x -> bf16 hi/lo
// =====================================================================
__global__ void __launch_bounds__(256) split_kernel(
    const float4* __restrict__ in, uint2* __restrict__ hi, uint2* __restrict__ lo, int n4)
{
    for (int i = blockIdx.x * blockDim.x + threadIdx.x; i < n4; i += gridDim.x * blockDim.x) {
        float4 v = in[i];
        __nv_bfloat16 h0 = __float2bfloat16(v.x), h1 = __float2bfloat16(v.y);
        __nv_bfloat16 h2 = __float2bfloat16(v.z), h3 = __float2bfloat16(v.w);
        __nv_bfloat16 l0 = __float2bfloat16(v.x - __bfloat162float(h0));
        __nv_bfloat16 l1 = __float2bfloat16(v.y - __bfloat162float(h1));
        __nv_bfloat16 l2 = __float2bfloat16(v.z - __bfloat162float(h2));
        __nv_bfloat16 l3 = __float2bfloat16(v.w - __bfloat162float(h3));
        __nv_bfloat162 hp0 = {h0, h1}, hp1 = {h2, h3};
        __nv_bfloat162 lp0 = {l0, l1}, lp1 = {l2, l3};
        hi[i] = make_uint2(*(uint32_t*)&hp0, *(uint32_t*)&hp1);
        lo[i] = make_uint2(*(uint32_t*)&lp0, *(uint32_t*)&lp1);
    }
}

// =====================================================================
// transpose + split: W [K,N] fp32 -> Wt hi/lo [N,K] bf16
// =====================================================================
__global__ void __launch_bounds__(256) wsplit_kernel(
    const float* __restrict__ W, __nv_bfloat16* __restrict__ hi,
    __nv_bfloat16* __restrict__ lo, int K, int N)
{
    __shared__ float t[32][33];
    const int tx = threadIdx.x & 31;
    const int ty = threadIdx.x >> 5;
    const int bn = blockIdx.x * 32;
    const int bk = blockIdx.y * 32;
#pragma unroll
    for (int i = 0; i < 32; i += 8)
        t[ty + i][tx] = W[(size_t)(bk + ty + i) * N + bn + tx];
    __syncthreads();
#pragma unroll
    for (int i = 0; i < 32; i += 8) {
        float v = t[tx][ty + i];
        __nv_bfloat16 h = __float2bfloat16(v);
        __nv_bfloat16 l = __float2bfloat16(v - __bfloat162float(h));
        size_t o = (size_t)(bn + ty + i) * K + bk + tx;
        hi[o] = h;
        lo[o] = l;
    }
}

// =====================================================================
// V transpose + split: g_qkv v region [s][c] -> g_vh/g_vl [c][s]
// =====================================================================
__global__ void __launch_bounds__(256) vsplit_kernel()
{
    __shared__ float t[32][33];
    const int tx = threadIdx.x & 31;
    const int ty = threadIdx.x >> 5;
    const int c0 = blockIdx.x * 32;   // v column (0..1023)
    const int s0 = blockIdx.y * 32;   // sequence
#pragma unroll
    for (int i = 0; i < 32; i += 8)
        t[ty + i][tx] = g_qkv[(size_t)(s0 + ty + i) * 3072 + 2048 + c0 + tx];
    __syncthreads();
#pragma unroll
    for (int i = 0; i < 32; i += 8) {
        float v = t[tx][ty + i];   // element (s = s0+tx, c = c0+ty+i)
        __nv_bfloat16 h = __float2bfloat16(v);
        __nv_bfloat16 l = __float2bfloat16(v - __bfloat162float(h));
        size_t o = (size_t)(c0 + ty + i) * S_LEN + s0 + tx;
        g_vh[o] = h;
        g_vl[o] = l;
    }
}

// =====================================================================
// split-bf16 tensor-core GEMM, 3-stage cp.async pipeline.
// Inner loop is PRODUCT-MAJOR so the same accumulator is only re-touched
// after 8 independent HMMAs (breaks the RAW chain on acc).
// CTA 128x128, K-chunk 32. 8 warps 2x4 (warp 64x32).
// SMEM row (128B SW128): [hi 64B | lo 64B]. Stage 32KB; 3 stages = 96KB.
// =====================================================================
#define GEMM_SMEM (3 * 32768)

__global__ void __launch_bounds__(256, 2) gemm_bf16s(
    const __nv_bfloat16* __restrict__ Ahi, const __nv_bfloat16* __restrict__ Alo,
    const __nv_bfloat16* __restrict__ Bhi, const __nv_bfloat16* __restrict__ Blo,
    float* __restrict__ C, const float* __restrict__ Cadd, int ldC)
{
    extern __shared__ char smem[];
    const uint32_t sb = smem_u32(smem);

    const int tid  = threadIdx.x;
    const int wid  = tid >> 5;
    const int lane = tid & 31;
    const int wm   = wid & 1;
    const int wn   = wid >> 1;
    const int m0 = blockIdx.y * 128;
    const int n0 = blockIdx.x * 128;

    float acc[4][4][4];
#pragma unroll
    for (int i = 0; i < 4; i++)
#pragma unroll
        for (int j = 0; j < 4; j++)
#pragma unroll
            for (int c = 0; c < 4; c++) acc[i][j][c] = 0.f;

    const int r = tid >> 1;
    const int h = tid & 1;
    const __nv_bfloat16* gAh = Ahi + (size_t)(m0 + r) * DMODEL + h * 16;
    const __nv_bfloat16* gAl = Alo + (size_t)(m0 + r) * DMODEL + h * 16;
    const __nv_bfloat16* gBh = Bhi + (size_t)(n0 + r) * DMODEL + h * 16;
    const __nv_bfloat16* gBl = Blo + (size_t)(n0 + r) * DMODEL + h * 16;
    const uint32_t dhi0 = SWZ128((uint32_t)(r * 128 + h * 32));
    const uint32_t dhi1 = SWZ128((uint32_t)(r * 128 + h * 32 + 16));
    const uint32_t dlo0 = SWZ128((uint32_t)(r * 128 + 64 + h * 32));
    const uint32_t dlo1 = SWZ128((uint32_t)(r * 128 + 64 + h * 32 + 16));

    const int aRow = wm * 64 + (lane & 15);
    const int aKb  = (lane >> 4) << 4;
    const int bRow = wn * 32 + (lane & 15);

    const int NCH = DMODEL / 32;

#define LOAD_STAGE(kc, s)                                                   \
    do {                                                                    \
        const uint32_t bA = sb + (s) * 32768;                               \
        const uint32_t bB = bA + 16384;                                     \
        cp16(bA + dhi0, gAh + (kc));                                        \
        cp16(bA + dhi1, gAh + (kc) + 8);                                    \
        cp16(bA + dlo0, gAl + (kc));                                        \
        cp16(bA + dlo1, gAl + (kc) + 8);                                    \
        cp16(bB + dhi0, gBh + (kc));                                        \
        cp16(bB + dhi1, gBh + (kc) + 8);                                    \
        cp16(bB + dlo0, gBl + (kc));                                        \
        cp16(bB + dlo1, gBl + (kc) + 8);                                    \
    } while (0)

    LOAD_STAGE(0, 0);
    cp_commit();
    LOAD_STAGE(32, 1);
    cp_commit();

    for (int it = 0; it < NCH; it++) {
        if (it + 1 < NCH) cp_wait<1>(); else cp_wait<0>();
        __syncthreads();
        if (it + 2 < NCH) {
            LOAD_STAGE((it + 2) * 32, (it + 2) % 3);
            cp_commit();
        }

        const uint32_t bA = sb + (uint32_t)(it % 3) * 32768;
        const uint32_t bB = bA + 16384;

#pragma unroll
        for (int kk = 0; kk < 32; kk += 16) {
            uint32_t ah[4][4], al[4][4];
#pragma unroll
            for (int mt = 0; mt < 4; mt++) {
                const uint32_t row = (uint32_t)(aRow + mt * 16) * 128;
                ldsm_x4(ah[mt], bA + SWZ128(row + kk * 2 + aKb));
                ldsm_x4(al[mt], bA + SWZ128(row + 64 + kk * 2 + aKb));
            }
#pragma unroll
            for (int ntp = 0; ntp < 2; ntp++) {
                const uint32_t row = (uint32_t)(bRow + ntp * 16) * 128;
                uint32_t bh[4], bl[4];
                ldsm_x4(bh, bB + SWZ128(row + kk * 2 + aKb));
                ldsm_x4(bl, bB + SWZ128(row + 64 + kk * 2 + aKb));
                // product-major: same acc re-touched only every 8 MMAs
#pragma unroll
                for (int p = 0; p < 3; p++) {
#pragma unroll
                    for (int half = 0; half < 2; half++) {
                        const int nt = ntp * 2 + half;
                        uint32_t bf[2];
                        if (p == 1) { bf[0] = bl[half]; bf[1] = bl[half + 2]; }
                        else        { bf[0] = bh[half]; bf[1] = bh[half + 2]; }
#pragma unroll
                        for (int mt = 0; mt < 4; mt++)
                            mma_bf16(acc[mt][nt], (p == 2) ? al[mt] : ah[mt], bf);
                    }
                }
            }
        }
    }

    const int g  = lane >> 2;
    const int tg = lane & 3;
#pragma unroll
    for (int mt = 0; mt < 4; mt++) {
#pragma unroll
        for (int half = 0; half < 2; half++) {
            const int m = m0 + wm * 64 + mt * 16 + g + half * 8;
            float* cp = C + (size_t)m * ldC + n0 + wn * 32;
            const float* ap = Cadd ? (Cadd + (size_t)m * ldC + n0 + wn * 32) : nullptr;
#pragma unroll
            for (int nt = 0; nt < 4; nt++) {
                const int col = nt * 8 + tg * 2;
                float2 v = make_float2(acc[mt][nt][half * 2], acc[mt][nt][half * 2 + 1]);
                if (ap) {
                    float2 c = *(const float2*)(ap + col);
                    v.x += c.x; v.y += c.y;
                }
                *(float2*)(cp + col) = v;
            }
        }
    }
}

// =====================================================================
// RoPE: read fp32 q,k from g_qkv, emit bf16 hi/lo (q pre-scaled 1/8).
// =====================================================================
__global__ void __launch_bounds__(512) rope_kernel()
{
    const int s = blockIdx.x;
    const int h = threadIdx.x >> 5;
    const int j = threadIdx.x & 31;

    const float LOG2_1E4 = 13.28771237954945f;
    float inv = exp2f(-(float)j * (LOG2_1E4 / 32.0f));
    float ang = (float)s * inv;
    float sn, cs;
    sincosf(ang, &sn, &cs);

    const float* q = g_qkv + (size_t)s * 3072 + h * 64;
    const float* k = q + 1024;

    float q0 = q[j], q1 = q[j + 32];
    float qr0 = (q0 * cs - q1 * sn) * 0.125f;
    float qr1 = (q1 * cs + q0 * sn) * 0.125f;
    float k0 = k[j], k1 = k[j + 32];
    float kr0 = k0 * cs - k1 * sn;
    float kr1 = k1 * cs + k0 * sn;

    const size_t o = (size_t)s * DMODEL + h * 64 + j;
    __nv_bfloat16 hh;
    hh = __float2bfloat16(qr0); g_qh[o] = hh; g_ql[o] = __float2bfloat16(qr0 - __bfloat162float(hh));
    hh = __float2bfloat16(qr1); g_qh[o + 32] = hh; g_ql[o + 32] = __float2bfloat16(qr1 - __bfloat162float(hh));
    hh = __float2bfloat16(kr0); g_kh[o] = hh; g_kl[o] = __float2bfloat16(kr0 - __bfloat162float(hh));
    hh = __float2bfloat16(kr1); g_kh[o + 32] = hh; g_kl[o + 32] = __float2bfloat16(kr1 - __bfloat162float(hh));
}

// =====================================================================
// Windowed causal flash attention, tensor-core (split-bf16 mma.sync).
// grid = (NHEADS, S/64), 256 threads = 8 warps (2x4).
// =====================================================================
// smem layout (bytes):
#define AQH 0u
#define AQL 8192u
#define AKB0 16384u
#define AKB1 32768u
#define AVH 49152u
#define AVL 57344u
#define ASS 65536u               // S fp32 [64][68]
#define APH 82944u               // P hi [64 rows][128B] SW128
#define APL 91136u
#define AROW 99328u              // 64 floats row scales
#define ATT_SMEM 99584

__global__ void __launch_bounds__(256) attn_kernel()
{
    extern __shared__ char sm[];
    const uint32_t sb = smem_u32(sm);
    float* sS   = (float*)(sm + ASS);
    float* sRow = (float*)(sm + AROW);

    const int h   = blockIdx.x;
    const int q0  = blockIdx.y * 64;
    const int tid = threadIdx.x;
    const int wid = tid >> 5, lane = tid & 31;
    const int wm = wid & 1, wn = wid >> 1;
    const int g = lane >> 2, tg = lane & 3;
    const int tx = tid & 15, ty = tid >> 4;

    const int r4 = tid >> 2;
    const int s4 = (tid & 3) * 2;
    const uint32_t tdst0 = SWZ128((uint32_t)(r4 * 128 + s4 * 16));
    const uint32_t tdst1 = SWZ128((uint32_t)(r4 * 128 + s4 * 16 + 16));

#define ATL(dstbase, srcptr)                         \
    do {                                             \
        cp16((dstbase) + tdst0, (srcptr));           \
        cp16((dstbase) + tdst1, (srcptr) + 8);       \
    } while (0)

    const int kstart = (q0 - WINDOW) < 0 ? 0 : (q0 - WINDOW);
    const int nch = (q0 - kstart) / 64 + 1;

    ATL(sb + AQH, g_qh + (size_t)(q0 + r4) * DMODEL + h * 64 + s4 * 8);
    ATL(sb + AQL, g_ql + (size_t)(q0 + r4) * DMODEL + h * 64 + s4 * 8);
    ATL(sb + AKB0,        g_kh + (size_t)(kstart + r4) * DMODEL + h * 64 + s4 * 8);
    ATL(sb + AKB0 + 8192, g_kl + (size_t)(kstart + r4) * DMODEL + h * 64 + s4 * 8);
    cp_commit();

    float o[2][2][4];
#pragma unroll
    for (int i = 0; i < 2; i++)
#pragma unroll
        for (int j = 0; j < 2; j++)
#pragma unroll
            for (int c = 0; c < 4; c++) o[i][j][c] = 0.f;
    float m_[4], l_[4];
#pragma unroll
    for (int i = 0; i < 4; i++) { m_[i] = -1e30f; l_[i] = 0.f; }

    const int kb = (lane >> 4) * 16;
    const int aRowQ = wm * 32 + (lane & 15);
    const int bRow  = wn * 16 + (lane & 15);

    for (int it = 0; it < nch; it++) {
        const int kc = kstart + it * 64;
        const uint32_t KB  = (it & 1) ? AKB1 : AKB0;
        const uint32_t KBn = (it & 1) ? AKB0 : AKB1;
        const bool pf = (it + 1 < nch);

        cp_wait<0>();
        __syncthreads();

        ATL(sb + AVH, g_vh + (size_t)(h * 64 + r4) * S_LEN + kc + s4 * 8);
        ATL(sb + AVL, g_vl + (size_t)(h * 64 + r4) * S_LEN + kc + s4 * 8);
        cp_commit();

        // ---- S = Q K^T (3-product split, product-major) ----
        float sacc[2][2][4];
#pragma unroll
        for (int i = 0; i < 2; i++)
#pragma unroll
            for (int j = 0; j < 2; j++)
#pragma unroll
                for (int c = 0; c < 4; c++) sacc[i][j][c] = 0.f;

#pragma unroll
        for (int kk = 0; kk < 4; kk++) {
            uint32_t ah[2][4], al[2][4];
#pragma unroll
            for (int mt = 0; mt < 2; mt++) {
                const uint32_t row = (uint32_t)(aRowQ + mt * 16) * 128;
                ldsm_x4(ah[mt], sb + AQH + SWZ128(row + kk * 32 + kb));
                ldsm_x4(al[mt], sb + AQL + SWZ128(row + kk * 32 + kb));
            }
            uint32_t bh[4], bl[4];
            const uint32_t brow = (uint32_t)bRow * 128;
            ldsm_x4(bh, sb + KB + SWZ128(brow + kk * 32 + kb));
            ldsm_x4(bl, sb + KB + 8192 + SWZ128(brow + kk * 32 + kb));
#pragma unroll
            for (int p = 0; p < 3; p++) {
#pragma unroll
                for (int nt = 0; nt < 2; nt++) {
                    uint32_t bf[2];
                    if (p == 1) { bf[0] = bl[nt]; bf[1] = bl[nt + 2]; }
                    else        { bf[0] = bh[nt]; bf[1] = bh[nt + 2]; }
#pragma unroll
                    for (int mt = 0; mt < 2; mt++)
                        mma_bf16(sacc[mt][nt], (p == 2) ? al[mt] : ah[mt], bf);
                }
            }
        }

        if (pf) {
            ATL(sb + KBn,        g_kh + (size_t)(kc + 64 + r4) * DMODEL + h * 64 + s4 * 8);
            ATL(sb + KBn + 8192, g_kl + (size_t)(kc + 64 + r4) * DMODEL + h * 64 + s4 * 8);
            cp_commit();
        }

        // ---- S fragments -> smem ----
#pragma unroll
        for (int mt = 0; mt < 2; mt++) {
#pragma unroll
            for (int nt = 0; nt < 2; nt++) {
                const int rr = wm * 32 + mt * 16 + g;
                const int cc = wn * 16 + nt * 8 + tg * 2;
                *(float2*)&sS[rr * 68 + cc]       = make_float2(sacc[mt][nt][0], sacc[mt][nt][1]);
                *(float2*)&sS[(rr + 8) * 68 + cc] = make_float2(sacc[mt][nt][2], sacc[mt][nt][3]);
            }
        }
        __syncthreads();

        // ---- fp32 online softmax ----
#pragma unroll
        for (int i = 0; i < 4; i++) {
            const int q = q0 + ty * 4 + i;
            float sv[4];
            float rmax = -1e30f;
#pragma unroll
            for (int j = 0; j < 4; j++) {
                const int key = kc + tx * 4 + j;
                float v = sS[(ty * 4 + i) * 68 + tx * 4 + j];
                const bool ok = (key <= q) && (q - key <= WINDOW);
                sv[j] = ok ? v : -1e30f;
                rmax = fmaxf(rmax, sv[j]);
            }
#pragma unroll
            for (int of = 8; of >= 1; of >>= 1)
                rmax = fmaxf(rmax, __shfl_xor_sync(0xffffffffu, rmax, of));
            const float mnew = fmaxf(m_[i], rmax);
            const float scale = __expf(m_[i] - mnew);
            float p[4], rsum = 0.f;
#pragma unroll
            for (int j = 0; j < 4; j++) { p[j] = __expf(sv[j] - mnew); rsum += p[j]; }
            {
                uint32_t hp0 = pack_bf2(p[0], p[1]);
                uint32_t hp1 = pack_bf2(p[2], p[3]);
                float r0 = p[0] - __bfloat162float(__float2bfloat16(p[0]));
                float r1 = p[1] - __bfloat162float(__float2bfloat16(p[1]));
                float r2 = p[2] - __bfloat162float(__float2bfloat16(p[2]));
                float r3 = p[3] - __bfloat162float(__float2bfloat16(p[3]));
                uint32_t lp0 = pack_bf2(r0, r1);
                uint32_t lp1 = pack_bf2(r2, r3);
                const uint32_t off = SWZ128((uint32_t)((ty * 4 + i) * 128 + tx * 8));
                *(uint2*)(sm + APH + off) = make_uint2(hp0, hp1);
                *(uint2*)(sm + APL + off) = make_uint2(lp0, lp1);
            }
#pragma unroll
            for (int of = 8; of >= 1; of >>= 1)
                rsum += __shfl_xor_sync(0xffffffffu, rsum, of);
            l_[i] = l_[i] * scale + rsum;
            m_[i] = mnew;
            if (tx == 0) sRow[ty * 4 + i] = scale;
        }

        if (pf) cp_wait<1>(); else cp_wait<0>();
        __syncthreads();

        // ---- rescale O, then O += P V (product-major) ----
#pragma unroll
        for (int mt = 0; mt < 2; mt++) {
            const float rs0 = sRow[wm * 32 + mt * 16 + g];
            const float rs1 = sRow[wm * 32 + mt * 16 + g + 8];
#pragma unroll
            for (int nt = 0; nt < 2; nt++) {
                o[mt][nt][0] *= rs0; o[mt][nt][1] *= rs0;
                o[mt][nt][2] *= rs1; o[mt][nt][3] *= rs1;
            }
        }
#pragma unroll
        for (int kk = 0; kk < 4; kk++) {
            uint32_t ah[2][4], al[2][4];
#pragma unroll
            for (int mt = 0; mt < 2; mt++) {
                const uint32_t row = (uint32_t)(aRowQ + mt * 16) * 128;
                ldsm_x4(ah[mt], sb + APH + SWZ128(row + kk * 32 + kb));
                ldsm_x4(al[mt], sb + APL + SWZ128(row + kk * 32 + kb));
            }
            uint32_t bh[4], bl[4];
            const uint32_t brow = (uint32_t)bRow * 128;
            ldsm_x4(bh, sb + AVH + SWZ128(brow + kk * 32 + kb));
            ldsm_x4(bl, sb + AVL + SWZ128(brow + kk * 32 + kb));
#pragma unroll
            for (int p = 0; p < 3; p++) {
#pragma unroll
                for (int nt = 0; nt < 2; nt++) {
                    uint32_t bf[2];
                    if (p == 1) { bf[0] = bl[nt]; bf[1] = bl[nt + 2]; }
                    else        { bf[0] = bh[nt]; bf[1] = bh[nt + 2]; }
#pragma unroll
                    for (int mt = 0; mt < 2; mt++)
                        mma_bf16(o[mt][nt], (p == 2) ? al[mt] : ah[mt], bf);
                }
            }
        }
    }

    __syncthreads();
#pragma unroll
    for (int i = 0; i < 4; i++)
        if (tx == 0) sRow[ty * 4 + i] = 1.f / l_[i];
    __syncthreads();

#pragma unroll
    for (int mt = 0; mt < 2; mt++) {
        const int r0 = wm * 32 + mt * 16 + g;
        const float inv0 = sRow[r0], inv1 = sRow[r0 + 8];
#pragma unroll
        for (int nt = 0; nt < 2; nt++) {
            const int col = h * 64 + wn * 16 + nt * 8 + tg * 2;
#pragma unroll
            for (int half = 0; half < 2; half++) {
                const float iv = half ? inv1 : inv0;
                const int rr = r0 + half * 8;
                const float v0 = o[mt][nt][half * 2] * iv;
                const float v1 = o[mt][nt][half * 2 + 1] * iv;
                const __nv_bfloat16 h0 = __float2bfloat16(v0);
                const __nv_bfloat16 h1 = __float2bfloat16(v1);
                __nv_bfloat162 hp = {h0, h1};
                __nv_bfloat162 lp = {__float2bfloat16(v0 - __bfloat162float(h0)),
                                     __float2bfloat16(v1 - __bfloat162float(h1))};
                const size_t off = (size_t)(q0 + rr) * DMODEL + col;
                *(uint32_t*)(g_ahi + off) = *(uint32_t*)&hp;
                *(uint32_t*)(g_alo + off) = *(uint32_t*)&lp;
            }
        }
    }
}

// =====================================================================
// LayerNorm: grid=S, block=256
// =====================================================================
__global__ void __launch_bounds__(256) ln_kernel(
    const float* __restrict__ gamma, const float* __restrict__ beta,
    float* __restrict__ y)
{
    const int s = blockIdx.x;
    const int tid = threadIdx.x;
    const float* r = g_res + (size_t)s * DMODEL;

    float4 xv = *(const float4*)(r + tid * 4);
    float s1 = xv.x + xv.y + xv.z + xv.w;
    float s2 = xv.x * xv.x + xv.y * xv.y + xv.z * xv.z + xv.w * xv.w;
#pragma unroll
    for (int o = 16; o >= 1; o >>= 1) {
        s1 += __shfl_xor_sync(0xffffffffu, s1, o);
        s2 += __shfl_xor_sync(0xffffffffu, s2, o);
    }
    __shared__ float a1[8], a2[8];
    const int w = tid >> 5, lane = tid & 31;
    if (lane == 0) { a1[w] = s1; a2[w] = s2; }
    __syncthreads();
    float t1 = 0.f, t2 = 0.f;
#pragma unroll
    for (int i = 0; i < 8; i++) { t1 += a1[i]; t2 += a2[i]; }

    const float mu  = t1 * (1.0f / DMODEL);
    const float var = t2 * (1.0f / DMODEL) - mu * mu;
    const float rstd = rsqrtf(var + LN_EPS);

    const int c = tid * 4;
    float4 gm = *(const float4*)(gamma + c);
    float4 b = *(const float4*)(beta + c);
    float4 o;
    o.x = (xv.x - mu) * rstd * gm.x + b.x;
    o.y = (xv.y - mu) * rstd * gm.y + b.y;
    o.z = (xv.z - mu) * rstd * gm.z + b.z;
    o.w = (xv.w - mu) * rstd * gm.w + b.w;
    *(float4*)(y + (size_t)s * DMODEL + c) = o;
}

// =====================================================================
// launch
// =====================================================================
extern "C" void kernel_launch(void* const* d_in, const int* in_sizes, int n_in,
                              void* d_out, int out_size)
{
    const float* x     = (const float*)d_in[0];
    const float* state = (const float*)d_in[1];
    const float* Wqkv  = (const float*)d_in[2];
    const float* Wout  = (const float*)d_in[3];
    const float* gamma = (const float*)d_in[4];
    const float* beta  = (const float*)d_in[5];
    float* y = (float*)d_out;

    float *qkv, *res;
    __nv_bfloat16 *xhi, *xlo, *ahi, *alo, *wqhi, *wqlo, *wohi, *wolo;
    cudaGetSymbolAddress((void**)&qkv,  g_qkv);
    cudaGetSymbolAddress((void**)&res,  g_res);
    cudaGetSymbolAddress((void**)&xhi,  g_xhi);
    cudaGetSymbolAddress((void**)&xlo,  g_xlo);
    cudaGetSymbolAddress((void**)&ahi,  g_ahi);
    cudaGetSymbolAddress((void**)&alo,  g_alo);
    cudaGetSymbolAddress((void**)&wqhi, g_wqhi);
    cudaGetSymbolAddress((void**)&wqlo, g_wqlo);
    cudaGetSymbolAddress((void**)&wohi, g_wohi);
    cudaGetSymbolAddress((void**)&wolo, g_wolo);

    cudaFuncSetAttribute(gemm_bf16s, cudaFuncAttributeMaxDynamicSharedMemorySize, GEMM_SMEM);
    cudaFuncSetAttribute(attn_kernel, cudaFuncAttributeMaxDynamicSharedMemorySize, ATT_SMEM);

    // 0) operand prep
    split_kernel<<<512, 256>>>((const float4*)x, (uint2*)xhi, (uint2*)xlo,
                               S_LEN * DMODEL / 4);
    wsplit_kernel<<<dim3(3 * DMODEL / 32, DMODEL / 32), 256>>>(Wqkv, wqhi, wqlo,
                                                               DMODEL, 3 * DMODEL);
    wsplit_kernel<<<dim3(DMODEL / 32, DMODEL / 32), 256>>>(Wout, wohi, wolo,
                                                           DMODEL, DMODEL);

    // 1) QKV projection
    gemm_bf16s<<<dim3(3 * DMODEL / 128, S_LEN / 128), 256, GEMM_SMEM>>>(
        xhi, xlo, wqhi, wqlo, qkv, nullptr, 3 * DMODEL);

    // 2) RoPE -> bf16 split q,k ; V transpose+split
    rope_kernel<<<S_LEN, 512>>>();
    vsplit_kernel<<<dim3(DMODEL / 32, S_LEN / 32), 256>>>();

    // 3) windowed attention (tensor cores)
    attn_kernel<<<dim3(NHEADS, S_LEN / 64), 256, ATT_SMEM>>>();

    // 4) output projection + residual
    gemm_bf16s<<<dim3(DMODEL / 128, S_LEN / 128), 256, GEMM_SMEM>>>(
        ahi, alo, wohi, wolo, res, x, DMODEL);

    // 5) LayerNorm -> y
    ln_kernel<<<S_LEN, 256>>>(gamma, beta, y);

    // 6) pass-through state if the output buffer includes it
    if (out_size >= S_LEN * DMODEL + DMODEL) {
        cudaMemcpyAsync(y + (size_t)S_LEN * DMODEL, state,
                        DMODEL * sizeof(float), cudaMemcpyDeviceToDevice);
    }
}

// round 9
// speedup vs baseline: 2.0356x; 1.0072x over previous
#include <cuda_runtime.h>
#include <cuda_bf16.h>
#include <math.h>
#include <stdint.h>

#define S_LEN   2048
#define DMODEL  1024
#define NHEADS  16
#define WINDOW  256
#define LN_EPS  1e-5f

// ---------------- scratch (no allocations allowed) ----------------
__device__ float g_qkv[(size_t)S_LEN * 3 * DMODEL];   // reused: out-proj partials o0|o1
__device__ float g_pa[(size_t)S_LEN * 3 * DMODEL];    // QKV split-K partial 0
__device__ float g_pb[(size_t)S_LEN * 3 * DMODEL];    // QKV split-K partial 1

// split-bf16 operands
__device__ __nv_bfloat16 g_xhi[(size_t)S_LEN * DMODEL];
__device__ __nv_bfloat16 g_xlo[(size_t)S_LEN * DMODEL];
__device__ __nv_bfloat16 g_ahi[(size_t)S_LEN * DMODEL];   // attention out hi
__device__ __nv_bfloat16 g_alo[(size_t)S_LEN * DMODEL];   // attention out lo
__device__ __nv_bfloat16 g_wqhi[(size_t)3 * DMODEL * DMODEL];  // W_qkv^T [3072,1024]
__device__ __nv_bfloat16 g_wqlo[(size_t)3 * DMODEL * DMODEL];
__device__ __nv_bfloat16 g_wohi[(size_t)DMODEL * DMODEL];      // W_out^T [1024,1024]
__device__ __nv_bfloat16 g_wolo[(size_t)DMODEL * DMODEL];

// attention operands (split bf16)
__device__ __nv_bfloat16 g_qh[(size_t)S_LEN * DMODEL];  // [s][h*64+d], pre-scaled 1/8
__device__ __nv_bfloat16 g_ql[(size_t)S_LEN * DMODEL];
__device__ __nv_bfloat16 g_kh[(size_t)S_LEN * DMODEL];
__device__ __nv_bfloat16 g_kl[(size_t)S_LEN * DMODEL];
__device__ __nv_bfloat16 g_vh[(size_t)DMODEL * S_LEN];  // transposed: [h*64+d][s]
__device__ __nv_bfloat16 g_vl[(size_t)DMODEL * S_LEN];

// =====================================================================
// warp-level tensor-core helpers (sm_80+ baseline)
// =====================================================================
__device__ __forceinline__ uint32_t smem_u32(const void* p) {
    uint32_t a;
    asm("{ .reg .u64 t; cvta.to.shared.u64 t, %1; cvt.u32.u64 %0, t; }" : "=r"(a) : "l"(p));
    return a;
}
__device__ __forceinline__ void ldsm_x4(uint32_t* r, uint32_t addr) {
    asm volatile("ldmatrix.sync.aligned.m8n8.x4.shared.b16 {%0,%1,%2,%3}, [%4];"
                 : "=r"(r[0]), "=r"(r[1]), "=r"(r[2]), "=r"(r[3]) : "r"(addr));
}
__device__ __forceinline__ void mma_bf16(float* d, const uint32_t* a, const uint32_t* b) {
    asm volatile(
        "mma.sync.aligned.m16n8k16.row.col.f32.bf16.bf16.f32 "
        "{%0,%1,%2,%3}, {%4,%5,%6,%7}, {%8,%9}, {%0,%1,%2,%3};"
        : "+f"(d[0]), "+f"(d[1]), "+f"(d[2]), "+f"(d[3])
        : "r"(a[0]), "r"(a[1]), "r"(a[2]), "r"(a[3]), "r"(b[0]), "r"(b[1]));
}
__device__ __forceinline__ void cp16(uint32_t dst, const void* src) {
    asm volatile("cp.async.cg.shared.global [%0], [%1], 16;" :: "r"(dst), "l"(src));
}
__device__ __forceinline__ void cp_commit() {
    asm volatile("cp.async.commit_group;" ::: "memory");
}
template <int N>
__device__ __forceinline__ void cp_wait() {
    asm volatile("cp.async.wait_group %0;" :: "n"(N) : "memory");
}

#define SWZ128(bo) ((bo) ^ (((bo) >> 3) & 0x70))

__device__ __forceinline__ uint32_t pack_bf2(float a, float b) {
    __nv_bfloat162 p = {__float2bfloat16(a), __float2bfloat16(b)};
    return *(uint32_t*)&p;
}

// =====================================================================
// split x -> bf16 hi/lo
// =====================================================================
__global__ void __launch_bounds__(256) split_kernel(
    const float4* __restrict__ in, uint2* __restrict__ hi, uint2* __restrict__ lo, int n4)
{
    for (int i = blockIdx.x * blockDim.x + threadIdx.x; i < n4; i += gridDim.x * blockDim.x) {
        float4 v = in[i];
        __nv_bfloat16 h0 = __float2bfloat16(v.x), h1 = __float2bfloat16(v.y);
        __nv_bfloat16 h2 = __float2bfloat16(v.z), h3 = __float2bfloat16(v.w);
        __nv_bfloat16 l0 = __float2bfloat16(v.x - __bfloat162float(h0));
        __nv_bfloat16 l1 = __float2bfloat16(v.y - __bfloat162float(h1));
        __nv_bfloat16 l2 = __float2bfloat16(v.z - __bfloat162float(h2));
        __nv_bfloat16 l3 = __float2bfloat16(v.w - __bfloat162float(h3));
        __nv_bfloat162 hp0 = {h0, h1}, hp1 = {h2, h3};
        __nv_bfloat162 lp0 = {l0, l1}, lp1 = {l2, l3};
        hi[i] = make_uint2(*(uint32_t*)&hp0, *(uint32_t*)&hp1);
        lo[i] = make_uint2(*(uint32_t*)&lp0, *(uint32_t*)&lp1);
    }
}

// =====================================================================
// transpose + split: W [K,N] fp32 -> Wt hi/lo [N,K] bf16
// =====================================================================
__global__ void __launch_bounds__(256) wsplit_kernel(
    const float* __restrict__ W, __nv_bfloat16* __restrict__ hi,
    __nv_bfloat16* __restrict__ lo, int K, int N)
{
    __shared__ float t[32][33];
    const int tx = threadIdx.x & 31;
    const int ty = threadIdx.x >> 5;
    const int bn = blockIdx.x * 32;
    const int bk = blockIdx.y * 32;
#pragma unroll
    for (int i = 0; i < 32; i += 8)
        t[ty + i][tx] = W[(size_t)(bk + ty + i) * N + bn + tx];
    __syncthreads();
#pragma unroll
    for (int i = 0; i < 32; i += 8) {
        float v = t[tx][ty + i];
        __nv_bfloat16 h = __float2bfloat16(v);
        __nv_bfloat16 l = __float2bfloat16(v - __bfloat162float(h));
        size_t o = (size_t)(bn + ty + i) * K + bk + tx;
        hi[o] = h;
        lo[o] = l;
    }
}

// =====================================================================
// V transpose + split: (g_pa + g_pb) v region [s][c] -> g_vh/g_vl [c][s]
// =====================================================================
__global__ void __launch_bounds__(256) vsplit_kernel()
{
    __shared__ float t[32][33];
    const int tx = threadIdx.x & 31;
    const int ty = threadIdx.x >> 5;
    const int c0 = blockIdx.x * 32;   // v column (0..1023)
    const int s0 = blockIdx.y * 32;   // sequence
#pragma unroll
    for (int i = 0; i < 32; i += 8) {
        const size_t idx = (size_t)(s0 + ty + i) * 3072 + 2048 + c0 + tx;
        t[ty + i][tx] = g_pa[idx] + g_pb[idx];
    }
    __syncthreads();
#pragma unroll
    for (int i = 0; i < 32; i += 8) {
        float v = t[tx][ty + i];   // element (s = s0+tx, c = c0+ty+i)
        __nv_bfloat16 h = __float2bfloat16(v);
        __nv_bfloat16 l = __float2bfloat16(v - __bfloat162float(h));
        size_t o = (size_t)(c0 + ty + i) * S_LEN + s0 + tx;
        g_vh[o] = h;
        g_vl[o] = l;
    }
}

// =====================================================================
// split-bf16 tensor-core GEMM, SPLIT-K=2 (blockIdx.z picks K-half and
// output partial buffer). 3-stage cp.async pipeline.
// CTA 128x128 x K=512. 8 warps 2x4 (warp 64x32).
// SMEM row (128B SW128): [hi 64B | lo 64B]. Stage 32KB; 3 stages = 96KB.
// =====================================================================
#define GEMM_SMEM (3 * 32768)
#define KSPLIT 512

__global__ void __launch_bounds__(256, 2) gemm_bf16s(
    const __nv_bfloat16* __restrict__ Ahi, const __nv_bfloat16* __restrict__ Alo,
    const __nv_bfloat16* __restrict__ Bhi, const __nv_bfloat16* __restrict__ Blo,
    float* __restrict__ C0, float* __restrict__ C1, int ldC)
{
    extern __shared__ char smem[];
    const uint32_t sb = smem_u32(smem);

    const int tid  = threadIdx.x;
    const int wid  = tid >> 5;
    const int lane = tid & 31;
    const int wm   = wid & 1;
    const int wn   = wid >> 1;
    const int m0 = blockIdx.y * 128;
    const int n0 = blockIdx.x * 128;
    const int kOff = blockIdx.z * KSPLIT;
    float* __restrict__ C = blockIdx.z ? C1 : C0;

    float acc[4][4][4];
#pragma unroll
    for (int i = 0; i < 4; i++)
#pragma unroll
        for (int j = 0; j < 4; j++)
#pragma unroll
            for (int c = 0; c < 4; c++) acc[i][j][c] = 0.f;

    const int r = tid >> 1;
    const int h = tid & 1;
    const __nv_bfloat16* gAh = Ahi + (size_t)(m0 + r) * DMODEL + kOff + h * 16;
    const __nv_bfloat16* gAl = Alo + (size_t)(m0 + r) * DMODEL + kOff + h * 16;
    const __nv_bfloat16* gBh = Bhi + (size_t)(n0 + r) * DMODEL + kOff + h * 16;
    const __nv_bfloat16* gBl = Blo + (size_t)(n0 + r) * DMODEL + kOff + h * 16;
    const uint32_t dhi0 = SWZ128((uint32_t)(r * 128 + h * 32));
    const uint32_t dhi1 = SWZ128((uint32_t)(r * 128 + h * 32 + 16));
    const uint32_t dlo0 = SWZ128((uint32_t)(r * 128 + 64 + h * 32));
    const uint32_t dlo1 = SWZ128((uint32_t)(r * 128 + 64 + h * 32 + 16));

    const int aRow = wm * 64 + (lane & 15);
    const int aKb  = (lane >> 4) << 4;
    const int bRow = wn * 32 + (lane & 15);

    const int NCH = KSPLIT / 32;   // 16 chunks

#define LOAD_STAGE(kc, s)                                                   \
    do {                                                                    \
        const uint32_t bA = sb + (s) * 32768;                               \
        const uint32_t bB = bA + 16384;                                     \
        cp16(bA + dhi0, gAh + (kc));                                        \
        cp16(bA + dhi1, gAh + (kc) + 8);                                    \
        cp16(bA + dlo0, gAl + (kc));                                        \
        cp16(bA + dlo1, gAl + (kc) + 8);                                    \
        cp16(bB + dhi0, gBh + (kc));                                        \
        cp16(bB + dhi1, gBh + (kc) + 8);                                    \
        cp16(bB + dlo0, gBl + (kc));                                        \
        cp16(bB + dlo1, gBl + (kc) + 8);                                    \
    } while (0)

    LOAD_STAGE(0, 0);
    cp_commit();
    LOAD_STAGE(32, 1);
    cp_commit();

    for (int it = 0; it < NCH; it++) {
        if (it + 1 < NCH) cp_wait<1>(); else cp_wait<0>();
        __syncthreads();
        if (it + 2 < NCH) {
            LOAD_STAGE((it + 2) * 32, (it + 2) % 3);
            cp_commit();
        }

        const uint32_t bA = sb + (uint32_t)(it % 3) * 32768;
        const uint32_t bB = bA + 16384;

#pragma unroll
        for (int kk = 0; kk < 32; kk += 16) {
            uint32_t ah[4][4], al[4][4];
#pragma unroll
            for (int mt = 0; mt < 4; mt++) {
                const uint32_t row = (uint32_t)(aRow + mt * 16) * 128;
                ldsm_x4(ah[mt], bA + SWZ128(row + kk * 2 + aKb));
                ldsm_x4(al[mt], bA + SWZ128(row + 64 + kk * 2 + aKb));
            }
#pragma unroll
            for (int ntp = 0; ntp < 2; ntp++) {
                const uint32_t row = (uint32_t)(bRow + ntp * 16) * 128;
                uint32_t bh[4], bl[4];
                ldsm_x4(bh, bB + SWZ128(row + kk * 2 + aKb));
                ldsm_x4(bl, bB + SWZ128(row + 64 + kk * 2 + aKb));
#pragma unroll
                for (int p = 0; p < 3; p++) {
#pragma unroll
                    for (int half = 0; half < 2; half++) {
                        const int nt = ntp * 2 + half;
                        uint32_t bf[2];
                        if (p == 1) { bf[0] = bl[half]; bf[1] = bl[half + 2]; }
                        else        { bf[0] = bh[half]; bf[1] = bh[half + 2]; }
#pragma unroll
                        for (int mt = 0; mt < 4; mt++)
                            mma_bf16(acc[mt][nt], (p == 2) ? al[mt] : ah[mt], bf);
                    }
                }
            }
        }
    }

    const int g  = lane >> 2;
    const int tg = lane & 3;
#pragma unroll
    for (int mt = 0; mt < 4; mt++) {
#pragma unroll
        for (int half = 0; half < 2; half++) {
            const int m = m0 + wm * 64 + mt * 16 + g + half * 8;
            float* cp = C + (size_t)m * ldC + n0 + wn * 32;
#pragma unroll
            for (int nt = 0; nt < 4; nt++) {
                const int col = nt * 8 + tg * 2;
                *(float2*)(cp + col) =
                    make_float2(acc[mt][nt][half * 2], acc[mt][nt][half * 2 + 1]);
            }
        }
    }
}

// =====================================================================
// RoPE: read fp32 q,k = (pa+pb), emit bf16 hi/lo (q pre-scaled 1/8).
// =====================================================================
__global__ void __launch_bounds__(512) rope_kernel()
{
    const int s = blockIdx.x;
    const int h = threadIdx.x >> 5;
    const int j = threadIdx.x & 31;

    const float LOG2_1E4 = 13.28771237954945f;
    float inv = exp2f(-(float)j * (LOG2_1E4 / 32.0f));
    float ang = (float)s * inv;
    float sn, cs;
    sincosf(ang, &sn, &cs);

    const size_t base = (size_t)s * 3072 + h * 64;
    const float* pa = g_pa + base;
    const float* pb = g_pb + base;

    float q0 = pa[j] + pb[j];
    float q1 = pa[j + 32] + pb[j + 32];
    float k0 = pa[1024 + j] + pb[1024 + j];
    float k1 = pa[1024 + j + 32] + pb[1024 + j + 32];

    float qr0 = (q0 * cs - q1 * sn) * 0.125f;
    float qr1 = (q1 * cs + q0 * sn) * 0.125f;
    float kr0 = k0 * cs - k1 * sn;
    float kr1 = k1 * cs + k0 * sn;

    const size_t o = (size_t)s * DMODEL + h * 64 + j;
    __nv_bfloat16 hh;
    hh = __float2bfloat16(qr0); g_qh[o] = hh; g_ql[o] = __float2bfloat16(qr0 - __bfloat162float(hh));
    hh = __float2bfloat16(qr1); g_qh[o + 32] = hh; g_ql[o + 32] = __float2bfloat16(qr1 - __bfloat162float(hh));
    hh = __float2bfloat16(kr0); g_kh[o] = hh; g_kl[o] = __float2bfloat16(kr0 - __bfloat162float(hh));
    hh = __float2bfloat16(kr1); g_kh[o + 32] = hh; g_kl[o + 32] = __float2bfloat16(kr1 - __bfloat162float(hh));
}

// =====================================================================
// Windowed causal flash attention, tensor-core (split-bf16 mma.sync).
// grid = (NHEADS, S/64), 256 threads = 8 warps (2x4).
// =====================================================================
// smem layout (bytes):
#define AQH 0u
#define AQL 8192u
#define AKB0 16384u
#define AKB1 32768u
#define AVH 49152u
#define AVL 57344u
#define ASS 65536u               // S fp32 [64][68]
#define APH 82944u               // P hi [64 rows][128B] SW128
#define APL 91136u
#define AROW 99328u              // 64 floats row scales
#define ATT_SMEM 99584

__global__ void __launch_bounds__(256) attn_kernel()
{
    extern __shared__ char sm[];
    const uint32_t sb = smem_u32(sm);
    float* sS   = (float*)(sm + ASS);
    float* sRow = (float*)(sm + AROW);

    const int h   = blockIdx.x;
    const int q0  = blockIdx.y * 64;
    const int tid = threadIdx.x;
    const int wid = tid >> 5, lane = tid & 31;
    const int wm = wid & 1, wn = wid >> 1;
    const int g = lane >> 2, tg = lane & 3;
    const int tx = tid & 15, ty = tid >> 4;

    const int r4 = tid >> 2;
    const int s4 = (tid & 3) * 2;
    const uint32_t tdst0 = SWZ128((uint32_t)(r4 * 128 + s4 * 16));
    const uint32_t tdst1 = SWZ128((uint32_t)(r4 * 128 + s4 * 16 + 16));

#define ATL(dstbase, srcptr)                         \
    do {                                             \
        cp16((dstbase) + tdst0, (srcptr));           \
        cp16((dstbase) + tdst1, (srcptr) + 8);       \
    } while (0)

    const int kstart = (q0 - WINDOW) < 0 ? 0 : (q0 - WINDOW);
    const int nch = (q0 - kstart) / 64 + 1;

    ATL(sb + AQH, g_qh + (size_t)(q0 + r4) * DMODEL + h * 64 + s4 * 8);
    ATL(sb + AQL, g_ql + (size_t)(q0 + r4) * DMODEL + h * 64 + s4 * 8);
    ATL(sb + AKB0,        g_kh + (size_t)(kstart + r4) * DMODEL + h * 64 + s4 * 8);
    ATL(sb + AKB0 + 8192, g_kl + (size_t)(kstart + r4) * DMODEL + h * 64 + s4 * 8);
    cp_commit();

    float o[2][2][4];
#pragma unroll
    for (int i = 0; i < 2; i++)
#pragma unroll
        for (int j = 0; j < 2; j++)
#pragma unroll
            for (int c = 0; c < 4; c++) o[i][j][c] = 0.f;
    float m_[4], l_[4];
#pragma unroll
    for (int i = 0; i < 4; i++) { m_[i] = -1e30f; l_[i] = 0.f; }

    const int kb = (lane >> 4) * 16;
    const int aRowQ = wm * 32 + (lane & 15);
    const int bRow  = wn * 16 + (lane & 15);

    for (int it = 0; it < nch; it++) {
        const int kc = kstart + it * 64;
        const uint32_t KB  = (it & 1) ? AKB1 : AKB0;
        const uint32_t KBn = (it & 1) ? AKB0 : AKB1;
        const bool pf = (it + 1 < nch);

        cp_wait<0>();
        __syncthreads();

        ATL(sb + AVH, g_vh + (size_t)(h * 64 + r4) * S_LEN + kc + s4 * 8);
        ATL(sb + AVL, g_vl + (size_t)(h * 64 + r4) * S_LEN + kc + s4 * 8);
        cp_commit();

        // ---- S = Q K^T (3-product split, product-major) ----
        float sacc[2][2][4];
#pragma unroll
        for (int i = 0; i < 2; i++)
#pragma unroll
            for (int j = 0; j < 2; j++)
#pragma unroll
                for (int c = 0; c < 4; c++) sacc[i][j][c] = 0.f;

#pragma unroll
        for (int kk = 0; kk < 4; kk++) {
            uint32_t ah[2][4], al[2][4];
#pragma unroll
            for (int mt = 0; mt < 2; mt++) {
                const uint32_t row = (uint32_t)(aRowQ + mt * 16) * 128;
                ldsm_x4(ah[mt], sb + AQH + SWZ128(row + kk * 32 + kb));
                ldsm_x4(al[mt], sb + AQL + SWZ128(row + kk * 32 + kb));
            }
            uint32_t bh[4], bl[4];
            const uint32_t brow = (uint32_t)bRow * 128;
            ldsm_x4(bh, sb + KB + SWZ128(brow + kk * 32 + kb));
            ldsm_x4(bl, sb + KB + 8192 + SWZ128(brow + kk * 32 + kb));
#pragma unroll
            for (int p = 0; p < 3; p++) {
#pragma unroll
                for (int nt = 0; nt < 2; nt++) {
                    uint32_t bf[2];
                    if (p == 1) { bf[0] = bl[nt]; bf[1] = bl[nt + 2]; }
                    else        { bf[0] = bh[nt]; bf[1] = bh[nt + 2]; }
#pragma unroll
                    for (int mt = 0; mt < 2; mt++)
                        mma_bf16(sacc[mt][nt], (p == 2) ? al[mt] : ah[mt], bf);
                }
            }
        }

        if (pf) {
            ATL(sb + KBn,        g_kh + (size_t)(kc + 64 + r4) * DMODEL + h * 64 + s4 * 8);
            ATL(sb + KBn + 8192, g_kl + (size_t)(kc + 64 + r4) * DMODEL + h * 64 + s4 * 8);
            cp_commit();
        }

        // ---- S fragments -> smem ----
#pragma unroll
        for (int mt = 0; mt < 2; mt++) {
#pragma unroll
            for (int nt = 0; nt < 2; nt++) {
                const int rr = wm * 32 + mt * 16 + g;
                const int cc = wn * 16 + nt * 8 + tg * 2;
                *(float2*)&sS[rr * 68 + cc]       = make_float2(sacc[mt][nt][0], sacc[mt][nt][1]);
                *(float2*)&sS[(rr + 8) * 68 + cc] = make_float2(sacc[mt][nt][2], sacc[mt][nt][3]);
            }
        }
        __syncthreads();

        // ---- fp32 online softmax ----
#pragma unroll
        for (int i = 0; i < 4; i++) {
            const int q = q0 + ty * 4 + i;
            float sv[4];
            float rmax = -1e30f;
#pragma unroll
            for (int j = 0; j < 4; j++) {
                const int key = kc + tx * 4 + j;
                float v = sS[(ty * 4 + i) * 68 + tx * 4 + j];
                const bool ok = (key <= q) && (q - key <= WINDOW);
                sv[j] = ok ? v : -1e30f;
                rmax = fmaxf(rmax, sv[j]);
            }
#pragma unroll
            for (int of = 8; of >= 1; of >>= 1)
                rmax = fmaxf(rmax, __shfl_xor_sync(0xffffffffu, rmax, of));
            const float mnew = fmaxf(m_[i], rmax);
            const float scale = __expf(m_[i] - mnew);
            float p[4], rsum = 0.f;
#pragma unroll
            for (int j = 0; j < 4; j++) { p[j] = __expf(sv[j] - mnew); rsum += p[j]; }
            {
                uint32_t hp0 = pack_bf2(p[0], p[1]);
                uint32_t hp1 = pack_bf2(p[2], p[3]);
                float r0 = p[0] - __bfloat162float(__float2bfloat16(p[0]));
                float r1 = p[1] - __bfloat162float(__float2bfloat16(p[1]));
                float r2 = p[2] - __bfloat162float(__float2bfloat16(p[2]));
                float r3 = p[3] - __bfloat162float(__float2bfloat16(p[3]));
                uint32_t lp0 = pack_bf2(r0, r1);
                uint32_t lp1 = pack_bf2(r2, r3);
                const uint32_t off = SWZ128((uint32_t)((ty * 4 + i) * 128 + tx * 8));
                *(uint2*)(sm + APH + off) = make_uint2(hp0, hp1);
                *(uint2*)(sm + APL + off) = make_uint2(lp0, lp1);
            }
#pragma unroll
            for (int of = 8; of >= 1; of >>= 1)
                rsum += __shfl_xor_sync(0xffffffffu, rsum, of);
            l_[i] = l_[i] * scale + rsum;
            m_[i] = mnew;
            if (tx == 0) sRow[ty * 4 + i] = scale;
        }

        if (pf) cp_wait<1>(); else cp_wait<0>();
        __syncthreads();

        // ---- rescale O, then O += P V (product-major) ----
#pragma unroll
        for (int mt = 0; mt < 2; mt++) {
            const float rs0 = sRow[wm * 32 + mt * 16 + g];
            const float rs1 = sRow[wm * 32 + mt * 16 + g + 8];
#pragma unroll
            for (int nt = 0; nt < 2; nt++) {
                o[mt][nt][0] *= rs0; o[mt][nt][1] *= rs0;
                o[mt][nt][2] *= rs1; o[mt][nt][3] *= rs1;
            }
        }
#pragma unroll
        for (int kk = 0; kk < 4; kk++) {
            uint32_t ah[2][4], al[2][4];
#pragma unroll
            for (int mt = 0; mt < 2; mt++) {
                const uint32_t row = (uint32_t)(aRowQ + mt * 16) * 128;
                ldsm_x4(ah[mt], sb + APH + SWZ128(row + kk * 32 + kb));
                ldsm_x4(al[mt], sb + APL + SWZ128(row + kk * 32 + kb));
            }
            uint32_t bh[4], bl[4];
            const uint32_t brow = (uint32_t)bRow * 128;
            ldsm_x4(bh, sb + AVH + SWZ128(brow + kk * 32 + kb));
            ldsm_x4(bl, sb + AVL + SWZ128(brow + kk * 32 + kb));
#pragma unroll
            for (int p = 0; p < 3; p++) {
#pragma unroll
                for (int nt = 0; nt < 2; nt++) {
                    uint32_t bf[2];
                    if (p == 1) { bf[0] = bl[nt]; bf[1] = bl[nt + 2]; }
                    else        { bf[0] = bh[nt]; bf[1] = bh[nt + 2]; }
#pragma unroll
                    for (int mt = 0; mt < 2; mt++)
                        mma_bf16(o[mt][nt], (p == 2) ? al[mt] : ah[mt], bf);
                }
            }
        }
    }

    __syncthreads();
#pragma unroll
    for (int i = 0; i < 4; i++)
        if (tx == 0) sRow[ty * 4 + i] = 1.f / l_[i];
    __syncthreads();

#pragma unroll
    for (int mt = 0; mt < 2; mt++) {
        const int r0 = wm * 32 + mt * 16 + g;
        const float inv0 = sRow[r0], inv1 = sRow[r0 + 8];
#pragma unroll
        for (int nt = 0; nt < 2; nt++) {
            const int col = h * 64 + wn * 16 + nt * 8 + tg * 2;
#pragma unroll
            for (int half = 0; half < 2; half++) {
                const float iv = half ? inv1 : inv0;
                const int rr = r0 + half * 8;
                const float v0 = o[mt][nt][half * 2] * iv;
                const float v1 = o[mt][nt][half * 2 + 1] * iv;
                const __nv_bfloat16 h0 = __float2bfloat16(v0);
                const __nv_bfloat16 h1 = __float2bfloat16(v1);
                __nv_bfloat162 hp = {h0, h1};
                __nv_bfloat162 lp = {__float2bfloat16(v0 - __bfloat162float(h0)),
                                     __float2bfloat16(v1 - __bfloat162float(h1))};
                const size_t off = (size_t)(q0 + rr) * DMODEL + col;
                *(uint32_t*)(g_ahi + off) = *(uint32_t*)&hp;
                *(uint32_t*)(g_alo + off) = *(uint32_t*)&lp;
            }
        }
    }
}

// =====================================================================
// LayerNorm with fused residual + split-K reduce:
//   res = x + o0 + o1 ; y = LN(res)*gamma + beta.  grid=S, block=256
// =====================================================================
__global__ void __launch_bounds__(256) ln_kernel(
    const float* __restrict__ x,
    const float* __restrict__ o0, const float* __restrict__ o1,
    const float* __restrict__ gamma, const float* __restrict__ beta,
    float* __restrict__ y)
{
    const int s = blockIdx.x;
    const int tid = threadIdx.x;
    const size_t base = (size_t)s * DMODEL + tid * 4;

    float4 xv = *(const float4*)(x + base);
    float4 a  = *(const float4*)(o0 + base);
    float4 b4 = *(const float4*)(o1 + base);
    xv.x += a.x + b4.x;
    xv.y += a.y + b4.y;
    xv.z += a.z + b4.z;
    xv.w += a.w + b4.w;

    float s1 = xv.x + xv.y + xv.z + xv.w;
    float s2 = xv.x * xv.x + xv.y * xv.y + xv.z * xv.z + xv.w * xv.w;
#pragma unroll
    for (int o = 16; o >= 1; o >>= 1) {
        s1 += __shfl_xor_sync(0xffffffffu, s1, o);
        s2 += __shfl_xor_sync(0xffffffffu, s2, o);
    }
    __shared__ float a1[8], a2[8];
    const int w = tid >> 5, lane = tid & 31;
    if (lane == 0) { a1[w] = s1; a2[w] = s2; }
    __syncthreads();
    float t1 = 0.f, t2 = 0.f;
#pragma unroll
    for (int i = 0; i < 8; i++) { t1 += a1[i]; t2 += a2[i]; }

    const float mu  = t1 * (1.0f / DMODEL);
    const float var = t2 * (1.0f / DMODEL) - mu * mu;
    const float rstd = rsqrtf(var + LN_EPS);

    const int c = tid * 4;
    float4 gm = *(const float4*)(gamma + c);
    float4 bt = *(const float4*)(beta + c);
    float4 o;
    o.x = (xv.x - mu) * rstd * gm.x + bt.x;
    o.y = (xv.y - mu) * rstd * gm.y + bt.y;
    o.z = (xv.z - mu) * rstd * gm.z + bt.z;
    o.w = (xv.w - mu) * rstd * gm.w + bt.w;
    *(float4*)(y + (size_t)s * DMODEL + c) = o;
}

// =====================================================================
// launch
// =====================================================================
extern "C" void kernel_launch(void* const* d_in, const int* in_sizes, int n_in,
                              void* d_out, int out_size)
{
    const float* x     = (const float*)d_in[0];
    const float* state = (const float*)d_in[1];
    const float* Wqkv  = (const float*)d_in[2];
    const float* Wout  = (const float*)d_in[3];
    const float* gamma = (const float*)d_in[4];
    const float* beta  = (const float*)d_in[5];
    float* y = (float*)d_out;

    float *qkv, *pa, *pb;
    __nv_bfloat16 *xhi, *xlo, *ahi, *alo, *wqhi, *wqlo, *wohi, *wolo;
    cudaGetSymbolAddress((void**)&qkv,  g_qkv);
    cudaGetSymbolAddress((void**)&pa,   g_pa);
    cudaGetSymbolAddress((void**)&pb,   g_pb);
    cudaGetSymbolAddress((void**)&xhi,  g_xhi);
    cudaGetSymbolAddress((void**)&xlo,  g_xlo);
    cudaGetSymbolAddress((void**)&ahi,  g_ahi);
    cudaGetSymbolAddress((void**)&alo,  g_alo);
    cudaGetSymbolAddress((void**)&wqhi, g_wqhi);
    cudaGetSymbolAddress((void**)&wqlo, g_wqlo);
    cudaGetSymbolAddress((void**)&wohi, g_wohi);
    cudaGetSymbolAddress((void**)&wolo, g_wolo);

    // out-proj partials reuse g_qkv storage (dead after rope/vsplit consume pa/pb)
    float* o0 = qkv;
    float* o1 = qkv + (size_t)S_LEN * DMODEL;

    cudaFuncSetAttribute(gemm_bf16s, cudaFuncAttributeMaxDynamicSharedMemorySize, GEMM_SMEM);
    cudaFuncSetAttribute(attn_kernel, cudaFuncAttributeMaxDynamicSharedMemorySize, ATT_SMEM);

    // 0) operand prep
    split_kernel<<<512, 256>>>((const float4*)x, (uint2*)xhi, (uint2*)xlo,
                               S_LEN * DMODEL / 4);
    wsplit_kernel<<<dim3(3 * DMODEL / 32, DMODEL / 32), 256>>>(Wqkv, wqhi, wqlo,
                                                               DMODEL, 3 * DMODEL);
    wsplit_kernel<<<dim3(DMODEL / 32, DMODEL / 32), 256>>>(Wout, wohi, wolo,
                                                           DMODEL, DMODEL);

    // 1) QKV projection, split-K=2 -> pa, pb
    gemm_bf16s<<<dim3(3 * DMODEL / 128, S_LEN / 128, 2), 256, GEMM_SMEM>>>(
        xhi, xlo, wqhi, wqlo, pa, pb, 3 * DMODEL);

    // 2) RoPE (reads pa+pb) -> bf16 split q,k ; V transpose+split (reads pa+pb)
    rope_kernel<<<S_LEN, 512>>>();
    vsplit_kernel<<<dim3(DMODEL / 32, S_LEN / 32), 256>>>();

    // 3) windowed attention (tensor cores)
    attn_kernel<<<dim3(NHEADS, S_LEN / 64), 256, ATT_SMEM>>>();

    // 4) output projection, split-K=2 -> o0, o1
    gemm_bf16s<<<dim3(DMODEL / 128, S_LEN / 128, 2), 256, GEMM_SMEM>>>(
        ahi, alo, wohi, wolo, o0, o1, DMODEL);

    // 5) LayerNorm (fused residual + split-K reduce) -> y
    ln_kernel<<<S_LEN, 256>>>(x, o0, o1, gamma, beta, y);

    // 6) pass-through state if the output buffer includes it
    if (out_size >= S_LEN * DMODEL + DMODEL) {
        cudaMemcpyAsync(y + (size_t)S_LEN * DMODEL, state,
                        DMODEL * sizeof(float), cudaMemcpyDeviceToDevice);
    }
}

// round 10
// speedup vs baseline: 2.6739x; 1.3136x over previous
#include <cuda_runtime.h>
#include <cuda_fp16.h>
#include <math.h>
#include <stdint.h>

#define S_LEN   2048
#define DMODEL  1024
#define NHEADS  16
#define WINDOW  256
#define LN_EPS  1e-5f

// ---------------- scratch (no allocations allowed) ----------------
__device__ float g_out0[(size_t)S_LEN * DMODEL];      // out-proj partial 0
__device__ float g_out1[(size_t)S_LEN * DMODEL];      // out-proj partial 1
__device__ float g_pa[(size_t)S_LEN * 3 * DMODEL];    // QKV split-K partial 0
__device__ float g_pb[(size_t)S_LEN * 3 * DMODEL];    // QKV split-K partial 1

// fp16 operands (A-side split hi/lo, B-side single)
__device__ __half g_xhi[(size_t)S_LEN * DMODEL];
__device__ __half g_xlo[(size_t)S_LEN * DMODEL];
__device__ __half g_ahi[(size_t)S_LEN * DMODEL];      // attention out hi
__device__ __half g_alo[(size_t)S_LEN * DMODEL];      // attention out lo
__device__ __half g_wq[(size_t)3 * DMODEL * DMODEL];  // W_qkv^T [3072,1024] single fp16
__device__ __half g_wo[(size_t)DMODEL * DMODEL];      // W_out^T [1024,1024] single fp16

// attention operands
__device__ __half g_qh[(size_t)S_LEN * DMODEL];  // q split hi (pre-scaled 1/8)
__device__ __half g_ql[(size_t)S_LEN * DMODEL];  // q split lo
__device__ __half g_k [(size_t)S_LEN * DMODEL];  // k single fp16
__device__ __half g_vh[(size_t)DMODEL * S_LEN];  // V^T split hi: [h*64+d][s]
__device__ __half g_vl[(size_t)DMODEL * S_LEN];  // V^T split lo

// =====================================================================
// warp-level tensor-core helpers (sm_80+ baseline)
// =====================================================================
__device__ __forceinline__ uint32_t smem_u32(const void* p) {
    uint32_t a;
    asm("{ .reg .u64 t; cvta.to.shared.u64 t, %1; cvt.u32.u64 %0, t; }" : "=r"(a) : "l"(p));
    return a;
}
__device__ __forceinline__ void ldsm_x4(uint32_t* r, uint32_t addr) {
    asm volatile("ldmatrix.sync.aligned.m8n8.x4.shared.b16 {%0,%1,%2,%3}, [%4];"
                 : "=r"(r[0]), "=r"(r[1]), "=r"(r[2]), "=r"(r[3]) : "r"(addr));
}
__device__ __forceinline__ void mma_f16(float* d, const uint32_t* a, const uint32_t* b) {
    asm volatile(
        "mma.sync.aligned.m16n8k16.row.col.f32.f16.f16.f32 "
        "{%0,%1,%2,%3}, {%4,%5,%6,%7}, {%8,%9}, {%0,%1,%2,%3};"
        : "+f"(d[0]), "+f"(d[1]), "+f"(d[2]), "+f"(d[3])
        : "r"(a[0]), "r"(a[1]), "r"(a[2]), "r"(a[3]), "r"(b[0]), "r"(b[1]));
}
__device__ __forceinline__ void cp16(uint32_t dst, const void* src) {
    asm volatile("cp.async.cg.shared.global [%0], [%1], 16;" :: "r"(dst), "l"(src));
}
__device__ __forceinline__ void cp_commit() {
    asm volatile("cp.async.commit_group;" ::: "memory");
}
template <int N>
__device__ __forceinline__ void cp_wait() {
    asm volatile("cp.async.wait_group %0;" :: "n"(N) : "memory");
}

#define SWZ128(bo) ((bo) ^ (((bo) >> 3) & 0x70))

__device__ __forceinline__ uint32_t pack_hf2(float a, float b) {
    __half2 p = {__float2half_rn(a), __float2half_rn(b)};
    return *(uint32_t*)&p;
}

// =====================================================================
// split x -> fp16 hi/lo
// =====================================================================
__global__ void __launch_bounds__(256) split_kernel(
    const float4* __restrict__ in, uint2* __restrict__ hi, uint2* __restrict__ lo, int n4)
{
    for (int i = blockIdx.x * blockDim.x + threadIdx.x; i < n4; i += gridDim.x * blockDim.x) {
        float4 v = in[i];
        __half h0 = __float2half_rn(v.x), h1 = __float2half_rn(v.y);
        __half h2 = __float2half_rn(v.z), h3 = __float2half_rn(v.w);
        __half l0 = __float2half_rn(v.x - __half2float(h0));
        __half l1 = __float2half_rn(v.y - __half2float(h1));
        __half l2 = __float2half_rn(v.z - __half2float(h2));
        __half l3 = __float2half_rn(v.w - __half2float(h3));
        __half2 hp0 = {h0, h1}, hp1 = {h2, h3};
        __half2 lp0 = {l0, l1}, lp1 = {l2, l3};
        hi[i] = make_uint2(*(uint32_t*)&hp0, *(uint32_t*)&hp1);
        lo[i] = make_uint2(*(uint32_t*)&lp0, *(uint32_t*)&lp1);
    }
}

// =====================================================================
// transpose: W [K,N] fp32 -> W^T [N,K] single fp16
// =====================================================================
__global__ void __launch_bounds__(256) wsplit_kernel(
    const float* __restrict__ W, __half* __restrict__ out, int K, int N)
{
    __shared__ float t[32][33];
    const int tx = threadIdx.x & 31;
    const int ty = threadIdx.x >> 5;
    const int bn = blockIdx.x * 32;
    const int bk = blockIdx.y * 32;
#pragma unroll
    for (int i = 0; i < 32; i += 8)
        t[ty + i][tx] = W[(size_t)(bk + ty + i) * N + bn + tx];
    __syncthreads();
#pragma unroll
    for (int i = 0; i < 32; i += 8)
        out[(size_t)(bn + ty + i) * K + bk + tx] = __float2half_rn(t[tx][ty + i]);
}

// =====================================================================
// V transpose + split: (g_pa + g_pb) v region [s][c] -> g_vh/g_vl [c][s]
// =====================================================================
__global__ void __launch_bounds__(256) vsplit_kernel()
{
    __shared__ float t[32][33];
    const int tx = threadIdx.x & 31;
    const int ty = threadIdx.x >> 5;
    const int c0 = blockIdx.x * 32;
    const int s0 = blockIdx.y * 32;
#pragma unroll
    for (int i = 0; i < 32; i += 8) {
        const size_t idx = (size_t)(s0 + ty + i) * 3072 + 2048 + c0 + tx;
        t[ty + i][tx] = g_pa[idx] + g_pb[idx];
    }
    __syncthreads();
#pragma unroll
    for (int i = 0; i < 32; i += 8) {
        float v = t[tx][ty + i];
        __half h = __float2half_rn(v);
        __half l = __float2half_rn(v - __half2float(h));
        size_t o = (size_t)(c0 + ty + i) * S_LEN + s0 + tx;
        g_vh[o] = h;
        g_vl[o] = l;
    }
}

// =====================================================================
// fp16 2-product tensor-core GEMM (A split hi/lo, B single), SPLIT-K=2.
// CTA 128x128 x K=512, K-chunk 64, 2-stage cp.async.
// SMEM stage: Ahi 16KB | Alo 16KB | B 16KB = 48KB; 2 stages = 96KB.
// Rows are 128B (64 fp16 of K), SW128 swizzled.
// =====================================================================
#define STAGE_B 49152
#define GEMM_SMEM (2 * STAGE_B)
#define KSPLIT 512

__global__ void __launch_bounds__(256, 2) gemm_f16s(
    const __half* __restrict__ Ahi, const __half* __restrict__ Alo,
    const __half* __restrict__ B,
    float* __restrict__ C0, float* __restrict__ C1, int ldC)
{
    extern __shared__ char smem[];
    const uint32_t sb = smem_u32(smem);

    const int tid  = threadIdx.x;
    const int wid  = tid >> 5;
    const int lane = tid & 31;
    const int wm   = wid & 1;
    const int wn   = wid >> 1;
    const int m0 = blockIdx.y * 128;
    const int n0 = blockIdx.x * 128;
    const int kOff = blockIdx.z * KSPLIT;
    float* __restrict__ C = blockIdx.z ? C1 : C0;

    float acc[4][4][4];
#pragma unroll
    for (int i = 0; i < 4; i++)
#pragma unroll
        for (int j = 0; j < 4; j++)
#pragma unroll
            for (int c = 0; c < 4; c++) acc[i][j][c] = 0.f;

    // g2s: thread owns 64B (4x16B) of one 128B row per tile
    const int r  = tid >> 1;
    const int h2 = tid & 1;
    uint32_t dofs[4];
#pragma unroll
    for (int s = 0; s < 4; s++)
        dofs[s] = SWZ128((uint32_t)(r * 128 + h2 * 64 + s * 16));
    const __half* gAh = Ahi + (size_t)(m0 + r) * DMODEL + kOff + h2 * 32;
    const __half* gAl = Alo + (size_t)(m0 + r) * DMODEL + kOff + h2 * 32;
    const __half* gB  = B   + (size_t)(n0 + r) * DMODEL + kOff + h2 * 32;

    // ldmatrix lane addressing
    const int aRow = wm * 64 + (lane & 15);
    const int bRow = wn * 32 + (lane & 15);
    const int kb   = (lane >> 4) << 4;     // byte offset of k-half in 32B group

    const int NCH = KSPLIT / 64;   // 8 chunks

#define LOAD_STAGE(kc, st)                                                  \
    do {                                                                    \
        const uint32_t base = sb + (uint32_t)(st) * STAGE_B;                \
        _Pragma("unroll")                                                   \
        for (int s = 0; s < 4; s++) {                                       \
            cp16(base + dofs[s],           gAh + (kc) + s * 8);             \
            cp16(base + 16384 + dofs[s],   gAl + (kc) + s * 8);             \
            cp16(base + 32768 + dofs[s],   gB  + (kc) + s * 8);             \
        }                                                                   \
    } while (0)

    LOAD_STAGE(0, 0);
    cp_commit();

    for (int it = 0; it < NCH; it++) {
        if (it + 1 < NCH) {
            LOAD_STAGE((it + 1) * 64, (it + 1) & 1);
            cp_commit();
            cp_wait<1>();
        } else {
            cp_wait<0>();
        }
        __syncthreads();

        const uint32_t bA = sb + (uint32_t)(it & 1) * STAGE_B;
        const uint32_t bL = bA + 16384;
        const uint32_t bB = bA + 32768;

#pragma unroll
        for (int kk = 0; kk < 4; kk++) {
            const uint32_t kby = (uint32_t)(kk * 32 + kb);
            uint32_t ah[4][4], al[4][4];
#pragma unroll
            for (int mt = 0; mt < 4; mt++) {
                const uint32_t row = (uint32_t)(aRow + mt * 16) * 128;
                ldsm_x4(ah[mt], bA + SWZ128(row + kby));
                ldsm_x4(al[mt], bL + SWZ128(row + kby));
            }
#pragma unroll
            for (int ntp = 0; ntp < 2; ntp++) {
                const uint32_t row = (uint32_t)(bRow + ntp * 16) * 128;
                uint32_t bb[4];
                ldsm_x4(bb, bB + SWZ128(row + kby));
#pragma unroll
                for (int p = 0; p < 2; p++) {
#pragma unroll
                    for (int half = 0; half < 2; half++) {
                        const int nt = ntp * 2 + half;
                        uint32_t bf[2] = {bb[half], bb[half + 2]};
#pragma unroll
                        for (int mt = 0; mt < 4; mt++)
                            mma_f16(acc[mt][nt], p ? al[mt] : ah[mt], bf);
                    }
                }
            }
        }
        __syncthreads();
    }

    const int g  = lane >> 2;
    const int tg = lane & 3;
#pragma unroll
    for (int mt = 0; mt < 4; mt++) {
#pragma unroll
        for (int half = 0; half < 2; half++) {
            const int m = m0 + wm * 64 + mt * 16 + g + half * 8;
            float* cp = C + (size_t)m * ldC + n0 + wn * 32;
#pragma unroll
            for (int nt = 0; nt < 4; nt++) {
                const int col = nt * 8 + tg * 2;
                *(float2*)(cp + col) =
                    make_float2(acc[mt][nt][half * 2], acc[mt][nt][half * 2 + 1]);
            }
        }
    }
}

// =====================================================================
// RoPE: read fp32 q,k = (pa+pb); q -> fp16 hi/lo (pre-scaled 1/8),
// k -> single fp16.
// =====================================================================
__global__ void __launch_bounds__(512) rope_kernel()
{
    const int s = blockIdx.x;
    const int h = threadIdx.x >> 5;
    const int j = threadIdx.x & 31;

    const float LOG2_1E4 = 13.28771237954945f;
    float inv = exp2f(-(float)j * (LOG2_1E4 / 32.0f));
    float ang = (float)s * inv;
    float sn, cs;
    sincosf(ang, &sn, &cs);

    const size_t base = (size_t)s * 3072 + h * 64;
    const float* pa = g_pa + base;
    const float* pb = g_pb + base;

    float q0 = pa[j] + pb[j];
    float q1 = pa[j + 32] + pb[j + 32];
    float k0 = pa[1024 + j] + pb[1024 + j];
    float k1 = pa[1024 + j + 32] + pb[1024 + j + 32];

    float qr0 = (q0 * cs - q1 * sn) * 0.125f;
    float qr1 = (q1 * cs + q0 * sn) * 0.125f;
    float kr0 = k0 * cs - k1 * sn;
    float kr1 = k1 * cs + k0 * sn;

    const size_t o = (size_t)s * DMODEL + h * 64 + j;
    __half hh;
    hh = __float2half_rn(qr0); g_qh[o] = hh;
    g_ql[o] = __float2half_rn(qr0 - __half2float(hh));
    hh = __float2half_rn(qr1); g_qh[o + 32] = hh;
    g_ql[o + 32] = __float2half_rn(qr1 - __half2float(hh));
    g_k[o]      = __float2half_rn(kr0);
    g_k[o + 32] = __float2half_rn(kr1);
}

// =====================================================================
// Windowed causal flash attention, fp16 2-product mma.sync.
// grid = (NHEADS, S/64), 256 threads = 8 warps (2x4).
// S = (Qh + Ql) K^T   (K single fp16)
// O += P (Vh + Vl)    (P single fp16)
// =====================================================================
#define AQH 0u
#define AQL 8192u
#define AK0 16384u
#define AK1 24576u
#define AVH 32768u
#define AVL 40960u
#define ASS 49152u               // S fp32 [64][68] = 17408 B
#define APH 66560u               // P fp16 [64 rows][128B] SW128
#define AROW 74752u              // 64 floats row scales
#define ATT_SMEM 75008

__global__ void __launch_bounds__(256, 2) attn_kernel()
{
    extern __shared__ char sm[];
    const uint32_t sb = smem_u32(sm);
    float* sS   = (float*)(sm + ASS);
    float* sRow = (float*)(sm + AROW);

    const int h   = blockIdx.x;
    const int q0  = blockIdx.y * 64;
    const int tid = threadIdx.x;
    const int wid = tid >> 5, lane = tid & 31;
    const int wm = wid & 1, wn = wid >> 1;
    const int g = lane >> 2, tg = lane & 3;
    const int tx = tid & 15, ty = tid >> 4;

    const int r4 = tid >> 2;
    const int s4 = (tid & 3) * 2;
    const uint32_t tdst0 = SWZ128((uint32_t)(r4 * 128 + s4 * 16));
    const uint32_t tdst1 = SWZ128((uint32_t)(r4 * 128 + s4 * 16 + 16));

#define ATL(dstbase, srcptr)                         \
    do {                                             \
        cp16((dstbase) + tdst0, (srcptr));           \
        cp16((dstbase) + tdst1, (srcptr) + 8);       \
    } while (0)

    const int kstart = (q0 - WINDOW) < 0 ? 0 : (q0 - WINDOW);
    const int nch = (q0 - kstart) / 64 + 1;

    ATL(sb + AQH, g_qh + (size_t)(q0 + r4) * DMODEL + h * 64 + s4 * 8);
    ATL(sb + AQL, g_ql + (size_t)(q0 + r4) * DMODEL + h * 64 + s4 * 8);
    ATL(sb + AK0, g_k  + (size_t)(kstart + r4) * DMODEL + h * 64 + s4 * 8);
    cp_commit();

    float o[2][2][4];
#pragma unroll
    for (int i = 0; i < 2; i++)
#pragma unroll
        for (int j = 0; j < 2; j++)
#pragma unroll
            for (int c = 0; c < 4; c++) o[i][j][c] = 0.f;
    float m_[4], l_[4];
#pragma unroll
    for (int i = 0; i < 4; i++) { m_[i] = -1e30f; l_[i] = 0.f; }

    const int kb = (lane >> 4) * 16;
    const int aRowQ = wm * 32 + (lane & 15);
    const int bRow  = wn * 16 + (lane & 15);

    for (int it = 0; it < nch; it++) {
        const int kc = kstart + it * 64;
        const uint32_t KB  = (it & 1) ? AK1 : AK0;
        const uint32_t KBn = (it & 1) ? AK0 : AK1;
        const bool pf = (it + 1 < nch);

        cp_wait<0>();
        __syncthreads();

        ATL(sb + AVH, g_vh + (size_t)(h * 64 + r4) * S_LEN + kc + s4 * 8);
        ATL(sb + AVL, g_vl + (size_t)(h * 64 + r4) * S_LEN + kc + s4 * 8);
        cp_commit();

        // ---- S = Q K^T (2-product: Qh.K + Ql.K) ----
        float sacc[2][2][4];
#pragma unroll
        for (int i = 0; i < 2; i++)
#pragma unroll
            for (int j = 0; j < 2; j++)
#pragma unroll
                for (int c = 0; c < 4; c++) sacc[i][j][c] = 0.f;

#pragma unroll
        for (int kk = 0; kk < 4; kk++) {
            const uint32_t kby = (uint32_t)(kk * 32 + kb);
            uint32_t ah[2][4], al[2][4];
#pragma unroll
            for (int mt = 0; mt < 2; mt++) {
                const uint32_t row = (uint32_t)(aRowQ + mt * 16) * 128;
                ldsm_x4(ah[mt], sb + AQH + SWZ128(row + kby));
                ldsm_x4(al[mt], sb + AQL + SWZ128(row + kby));
            }
            uint32_t bb[4];
            ldsm_x4(bb, sb + KB + SWZ128((uint32_t)bRow * 128 + kby));
#pragma unroll
            for (int p = 0; p < 2; p++) {
#pragma unroll
                for (int nt = 0; nt < 2; nt++) {
                    uint32_t bf[2] = {bb[nt], bb[nt + 2]};
#pragma unroll
                    for (int mt = 0; mt < 2; mt++)
                        mma_f16(sacc[mt][nt], p ? al[mt] : ah[mt], bf);
                }
            }
        }

        if (pf) {
            ATL(sb + KBn, g_k + (size_t)(kc + 64 + r4) * DMODEL + h * 64 + s4 * 8);
            cp_commit();
        }

        // ---- S fragments -> smem ----
#pragma unroll
        for (int mt = 0; mt < 2; mt++) {
#pragma unroll
            for (int nt = 0; nt < 2; nt++) {
                const int rr = wm * 32 + mt * 16 + g;
                const int cc = wn * 16 + nt * 8 + tg * 2;
                *(float2*)&sS[rr * 68 + cc]       = make_float2(sacc[mt][nt][0], sacc[mt][nt][1]);
                *(float2*)&sS[(rr + 8) * 68 + cc] = make_float2(sacc[mt][nt][2], sacc[mt][nt][3]);
            }
        }
        __syncthreads();

        // ---- fp32 online softmax; P -> single fp16 tile ----
#pragma unroll
        for (int i = 0; i < 4; i++) {
            const int q = q0 + ty * 4 + i;
            float sv[4];
            float rmax = -1e30f;
#pragma unroll
            for (int j = 0; j < 4; j++) {
                const int key = kc + tx * 4 + j;
                float v = sS[(ty * 4 + i) * 68 + tx * 4 + j];
                const bool ok = (key <= q) && (q - key <= WINDOW);
                sv[j] = ok ? v : -1e30f;
                rmax = fmaxf(rmax, sv[j]);
            }
#pragma unroll
            for (int of = 8; of >= 1; of >>= 1)
                rmax = fmaxf(rmax, __shfl_xor_sync(0xffffffffu, rmax, of));
            const float mnew = fmaxf(m_[i], rmax);
            const float scale = __expf(m_[i] - mnew);
            float p[4], rsum = 0.f;
#pragma unroll
            for (int j = 0; j < 4; j++) { p[j] = __expf(sv[j] - mnew); rsum += p[j]; }
            {
                const uint32_t off = SWZ128((uint32_t)((ty * 4 + i) * 128 + tx * 8));
                *(uint2*)(sm + APH + off) =
                    make_uint2(pack_hf2(p[0], p[1]), pack_hf2(p[2], p[3]));
            }
#pragma unroll
            for (int of = 8; of >= 1; of >>= 1)
                rsum += __shfl_xor_sync(0xffffffffu, rsum, of);
            l_[i] = l_[i] * scale + rsum;
            m_[i] = mnew;
            if (tx == 0) sRow[ty * 4 + i] = scale;
        }

        if (pf) cp_wait<1>(); else cp_wait<0>();
        __syncthreads();

        // ---- rescale O, then O += P (Vh + Vl) ----
#pragma unroll
        for (int mt = 0; mt < 2; mt++) {
            const float rs0 = sRow[wm * 32 + mt * 16 + g];
            const float rs1 = sRow[wm * 32 + mt * 16 + g + 8];
#pragma unroll
            for (int nt = 0; nt < 2; nt++) {
                o[mt][nt][0] *= rs0; o[mt][nt][1] *= rs0;
                o[mt][nt][2] *= rs1; o[mt][nt][3] *= rs1;
            }
        }
#pragma unroll
        for (int kk = 0; kk < 4; kk++) {
            const uint32_t kby = (uint32_t)(kk * 32 + kb);
            uint32_t ap[2][4];
#pragma unroll
            for (int mt = 0; mt < 2; mt++) {
                const uint32_t row = (uint32_t)(aRowQ + mt * 16) * 128;
                ldsm_x4(ap[mt], sb + APH + SWZ128(row + kby));
            }
            uint32_t bh[4], bl[4];
            const uint32_t brow = (uint32_t)bRow * 128;
            ldsm_x4(bh, sb + AVH + SWZ128(brow + kby));
            ldsm_x4(bl, sb + AVL + SWZ128(brow + kby));
#pragma unroll
            for (int p = 0; p < 2; p++) {
#pragma unroll
                for (int nt = 0; nt < 2; nt++) {
                    uint32_t bf[2];
                    if (p) { bf[0] = bl[nt]; bf[1] = bl[nt + 2]; }
                    else   { bf[0] = bh[nt]; bf[1] = bh[nt + 2]; }
#pragma unroll
                    for (int mt = 0; mt < 2; mt++)
                        mma_f16(o[mt][nt], ap[mt], bf);
                }
            }
        }
    }

    __syncthreads();
#pragma unroll
    for (int i = 0; i < 4; i++)
        if (tx == 0) sRow[ty * 4 + i] = 1.f / l_[i];
    __syncthreads();

    // write O (split fp16) to g_ahi/g_alo [s][h*64+d]
#pragma unroll
    for (int mt = 0; mt < 2; mt++) {
        const int r0 = wm * 32 + mt * 16 + g;
        const float inv0 = sRow[r0], inv1 = sRow[r0 + 8];
#pragma unroll
        for (int nt = 0; nt < 2; nt++) {
            const int col = h * 64 + wn * 16 + nt * 8 + tg * 2;
#pragma unroll
            for (int half = 0; half < 2; half++) {
                const float iv = half ? inv1 : inv0;
                const int rr = r0 + half * 8;
                const float v0 = o[mt][nt][half * 2] * iv;
                const float v1 = o[mt][nt][half * 2 + 1] * iv;
                const __half h0 = __float2half_rn(v0);
                const __half h1 = __float2half_rn(v1);
                __half2 hp = {h0, h1};
                __half2 lp = {__float2half_rn(v0 - __half2float(h0)),
                              __float2half_rn(v1 - __half2float(h1))};
                const size_t off = (size_t)(q0 + rr) * DMODEL + col;
                *(uint32_t*)(g_ahi + off) = *(uint32_t*)&hp;
                *(uint32_t*)(g_alo + off) = *(uint32_t*)&lp;
            }
        }
    }
}

// =====================================================================
// LayerNorm with fused residual + split-K reduce:
//   res = x + o0 + o1 ; y = LN(res)*gamma + beta.  grid=S, block=256
// =====================================================================
__global__ void __launch_bounds__(256) ln_kernel(
    const float* __restrict__ x,
    const float* __restrict__ o0, const float* __restrict__ o1,
    const float* __restrict__ gamma, const float* __restrict__ beta,
    float* __restrict__ y)
{
    const int s = blockIdx.x;
    const int tid = threadIdx.x;
    const size_t base = (size_t)s * DMODEL + tid * 4;

    float4 xv = *(const float4*)(x + base);
    float4 a  = *(const float4*)(o0 + base);
    float4 b4 = *(const float4*)(o1 + base);
    xv.x += a.x + b4.x;
    xv.y += a.y + b4.y;
    xv.z += a.z + b4.z;
    xv.w += a.w + b4.w;

    float s1 = xv.x + xv.y + xv.z + xv.w;
    float s2 = xv.x * xv.x + xv.y * xv.y + xv.z * xv.z + xv.w * xv.w;
#pragma unroll
    for (int o = 16; o >= 1; o >>= 1) {
        s1 += __shfl_xor_sync(0xffffffffu, s1, o);
        s2 += __shfl_xor_sync(0xffffffffu, s2, o);
    }
    __shared__ float a1[8], a2[8];
    const int w = tid >> 5, lane = tid & 31;
    if (lane == 0) { a1[w] = s1; a2[w] = s2; }
    __syncthreads();
    float t1 = 0.f, t2 = 0.f;
#pragma unroll
    for (int i = 0; i < 8; i++) { t1 += a1[i]; t2 += a2[i]; }

    const float mu  = t1 * (1.0f / DMODEL);
    const float var = t2 * (1.0f / DMODEL) - mu * mu;
    const float rstd = rsqrtf(var + LN_EPS);

    const int c = tid * 4;
    float4 gm = *(const float4*)(gamma + c);
    float4 bt = *(const float4*)(beta + c);
    float4 o;
    o.x = (xv.x - mu) * rstd * gm.x + bt.x;
    o.y = (xv.y - mu) * rstd * gm.y + bt.y;
    o.z = (xv.z - mu) * rstd * gm.z + bt.z;
    o.w = (xv.w - mu) * rstd * gm.w + bt.w;
    *(float4*)(y + (size_t)s * DMODEL + c) = o;
}

// =====================================================================
// launch
// =====================================================================
extern "C" void kernel_launch(void* const* d_in, const int* in_sizes, int n_in,
                              void* d_out, int out_size)
{
    const float* x     = (const float*)d_in[0];
    const float* state = (const float*)d_in[1];
    const float* Wqkv  = (const float*)d_in[2];
    const float* Wout  = (const float*)d_in[3];
    const float* gamma = (const float*)d_in[4];
    const float* beta  = (const float*)d_in[5];
    float* y = (float*)d_out;

    float *o0, *o1, *pa, *pb;
    __half *xhi, *xlo, *ahi, *alo, *wq, *wo;
    cudaGetSymbolAddress((void**)&o0,  g_out0);
    cudaGetSymbolAddress((void**)&o1,  g_out1);
    cudaGetSymbolAddress((void**)&pa,  g_pa);
    cudaGetSymbolAddress((void**)&pb,  g_pb);
    cudaGetSymbolAddress((void**)&xhi, g_xhi);
    cudaGetSymbolAddress((void**)&xlo, g_xlo);
    cudaGetSymbolAddress((void**)&ahi, g_ahi);
    cudaGetSymbolAddress((void**)&alo, g_alo);
    cudaGetSymbolAddress((void**)&wq,  g_wq);
    cudaGetSymbolAddress((void**)&wo,  g_wo);

    cudaFuncSetAttribute(gemm_f16s, cudaFuncAttributeMaxDynamicSharedMemorySize, GEMM_SMEM);
    cudaFuncSetAttribute(attn_kernel, cudaFuncAttributeMaxDynamicSharedMemorySize, ATT_SMEM);

    // 0) operand prep
    split_kernel<<<512, 256>>>((const float4*)x, (uint2*)xhi, (uint2*)xlo,
                               S_LEN * DMODEL / 4);
    wsplit_kernel<<<dim3(3 * DMODEL / 32, DMODEL / 32), 256>>>(Wqkv, wq,
                                                               DMODEL, 3 * DMODEL);
    wsplit_kernel<<<dim3(DMODEL / 32, DMODEL / 32), 256>>>(Wout, wo,
                                                           DMODEL, DMODEL);

    // 1) QKV projection, split-K=2 -> pa, pb
    gemm_f16s<<<dim3(3 * DMODEL / 128, S_LEN / 128, 2), 256, GEMM_SMEM>>>(
        xhi, xlo, wq, pa, pb, 3 * DMODEL);

    // 2) RoPE (reads pa+pb) -> q hi/lo, k single ; V transpose+split
    rope_kernel<<<S_LEN, 512>>>();
    vsplit_kernel<<<dim3(DMODEL / 32, S_LEN / 32), 256>>>();

    // 3) windowed attention (fp16 tensor cores)
    attn_kernel<<<dim3(NHEADS, S_LEN / 64), 256, ATT_SMEM>>>();

    // 4) output projection, split-K=2 -> o0, o1
    gemm_f16s<<<dim3(DMODEL / 128, S_LEN / 128, 2), 256, GEMM_SMEM>>>(
        ahi, alo, wo, o0, o1, DMODEL);

    // 5) LayerNorm (fused residual + split-K reduce) -> y
    ln_kernel<<<S_LEN, 256>>>(x, o0, o1, gamma, beta, y);

    // 6) pass-through state if the output buffer includes it
    if (out_size >= S_LEN * DMODEL + DMODEL) {
        cudaMemcpyAsync(y + (size_t)S_LEN * DMODEL, state,
                        DMODEL * sizeof(float), cudaMemcpyDeviceToDevice);
    }
}

// round 11
// speedup vs baseline: 4.0082x; 1.4990x over previous
#include <cuda_runtime.h>
#include <cuda_fp16.h>
#include <math.h>
#include <stdint.h>

#define S_LEN   2048
#define DMODEL  1024
#define NHEADS  16
#define WINDOW  256
#define LN_EPS  1e-5f

// ---------------- scratch (no allocations allowed) ----------------
__device__ float g_out0[(size_t)S_LEN * DMODEL];      // out-proj partial 0
__device__ float g_out1[(size_t)S_LEN * DMODEL];      // out-proj partial 1
__device__ float g_pa[(size_t)S_LEN * 3 * DMODEL];    // QKV split-K partial 0
__device__ float g_pb[(size_t)S_LEN * 3 * DMODEL];    // QKV split-K partial 1

// single fp16 operands
__device__ __half g_x16[(size_t)S_LEN * DMODEL];      // x fp16
__device__ __half g_a16[(size_t)S_LEN * DMODEL];      // attention out fp16
__device__ __half g_wq[(size_t)3 * DMODEL * DMODEL];  // W_qkv^T [3072,1024]
__device__ __half g_wo[(size_t)DMODEL * DMODEL];      // W_out^T [1024,1024]

// attention operands
__device__ __half g_q[(size_t)S_LEN * DMODEL];   // q (pre-scaled 1/8)
__device__ __half g_k[(size_t)S_LEN * DMODEL];   // k
__device__ __half g_v[(size_t)DMODEL * S_LEN];   // V^T: [h*64+d][s]

// =====================================================================
// warp-level tensor-core helpers (sm_80+ baseline)
// =====================================================================
__device__ __forceinline__ uint32_t smem_u32(const void* p) {
    uint32_t a;
    asm("{ .reg .u64 t; cvta.to.shared.u64 t, %1; cvt.u32.u64 %0, t; }" : "=r"(a) : "l"(p));
    return a;
}
__device__ __forceinline__ void ldsm_x4(uint32_t* r, uint32_t addr) {
    asm volatile("ldmatrix.sync.aligned.m8n8.x4.shared.b16 {%0,%1,%2,%3}, [%4];"
                 : "=r"(r[0]), "=r"(r[1]), "=r"(r[2]), "=r"(r[3]) : "r"(addr));
}
__device__ __forceinline__ void mma_f16(float* d, const uint32_t* a, const uint32_t* b) {
    asm volatile(
        "mma.sync.aligned.m16n8k16.row.col.f32.f16.f16.f32 "
        "{%0,%1,%2,%3}, {%4,%5,%6,%7}, {%8,%9}, {%0,%1,%2,%3};"
        : "+f"(d[0]), "+f"(d[1]), "+f"(d[2]), "+f"(d[3])
        : "r"(a[0]), "r"(a[1]), "r"(a[2]), "r"(a[3]), "r"(b[0]), "r"(b[1]));
}
__device__ __forceinline__ void cp16(uint32_t dst, const void* src) {
    asm volatile("cp.async.cg.shared.global [%0], [%1], 16;" :: "r"(dst), "l"(src));
}
__device__ __forceinline__ void cp_commit() {
    asm volatile("cp.async.commit_group;" ::: "memory");
}
template <int N>
__device__ __forceinline__ void cp_wait() {
    asm volatile("cp.async.wait_group %0;" :: "n"(N) : "memory");
}

#define SWZ128(bo) ((bo) ^ (((bo) >> 3) & 0x70))

__device__ __forceinline__ uint32_t pack_hf2(float a, float b) {
    __half2 p = {__float2half_rn(a), __float2half_rn(b)};
    return *(uint32_t*)&p;
}

// =====================================================================
// x -> single fp16
// =====================================================================
__global__ void __launch_bounds__(256) tofp16_kernel(
    const float4* __restrict__ in, uint2* __restrict__ out, int n4)
{
    for (int i = blockIdx.x * blockDim.x + threadIdx.x; i < n4; i += gridDim.x * blockDim.x) {
        float4 v = in[i];
        __half2 p0 = {__float2half_rn(v.x), __float2half_rn(v.y)};
        __half2 p1 = {__float2half_rn(v.z), __float2half_rn(v.w)};
        out[i] = make_uint2(*(uint32_t*)&p0, *(uint32_t*)&p1);
    }
}

// =====================================================================
// transpose: W [K,N] fp32 -> W^T [N,K] single fp16
// =====================================================================
__global__ void __launch_bounds__(256) wsplit_kernel(
    const float* __restrict__ W, __half* __restrict__ out, int K, int N)
{
    __shared__ float t[32][33];
    const int tx = threadIdx.x & 31;
    const int ty = threadIdx.x >> 5;
    const int bn = blockIdx.x * 32;
    const int bk = blockIdx.y * 32;
#pragma unroll
    for (int i = 0; i < 32; i += 8)
        t[ty + i][tx] = W[(size_t)(bk + ty + i) * N + bn + tx];
    __syncthreads();
#pragma unroll
    for (int i = 0; i < 32; i += 8)
        out[(size_t)(bn + ty + i) * K + bk + tx] = __float2half_rn(t[tx][ty + i]);
}

// =====================================================================
// V transpose: (g_pa + g_pb) v region [s][c] -> g_v [c][s] fp16
// =====================================================================
__global__ void __launch_bounds__(256) vsplit_kernel()
{
    __shared__ float t[32][33];
    const int tx = threadIdx.x & 31;
    const int ty = threadIdx.x >> 5;
    const int c0 = blockIdx.x * 32;
    const int s0 = blockIdx.y * 32;
#pragma unroll
    for (int i = 0; i < 32; i += 8) {
        const size_t idx = (size_t)(s0 + ty + i) * 3072 + 2048 + c0 + tx;
        t[ty + i][tx] = g_pa[idx] + g_pb[idx];
    }
    __syncthreads();
#pragma unroll
    for (int i = 0; i < 32; i += 8)
        g_v[(size_t)(c0 + ty + i) * S_LEN + s0 + tx] = __float2half_rn(t[tx][ty + i]);
}

// =====================================================================
// single-fp16 tensor-core GEMM, SPLIT-K=2.
// CTA 128x128 x K=512, K-chunk 64, 2-stage cp.async.
// SMEM stage: A 16KB | B 16KB = 32KB; 2 stages = 64KB.
// Rows are 128B (64 fp16 of K), SW128 swizzled.
// =====================================================================
#define STAGE_B 32768
#define GEMM_SMEM (2 * STAGE_B)
#define KSPLIT 512

__global__ void __launch_bounds__(256, 2) gemm_f16(
    const __half* __restrict__ A, const __half* __restrict__ B,
    float* __restrict__ C0, float* __restrict__ C1, int ldC)
{
    extern __shared__ char smem[];
    const uint32_t sb = smem_u32(smem);

    const int tid  = threadIdx.x;
    const int wid  = tid >> 5;
    const int lane = tid & 31;
    const int wm   = wid & 1;
    const int wn   = wid >> 1;
    const int m0 = blockIdx.y * 128;
    const int n0 = blockIdx.x * 128;
    const int kOff = blockIdx.z * KSPLIT;
    float* __restrict__ C = blockIdx.z ? C1 : C0;

    float acc[4][4][4];
#pragma unroll
    for (int i = 0; i < 4; i++)
#pragma unroll
        for (int j = 0; j < 4; j++)
#pragma unroll
            for (int c = 0; c < 4; c++) acc[i][j][c] = 0.f;

    // g2s: thread owns 64B (4x16B) of one 128B row per tile
    const int r  = tid >> 1;
    const int h2 = tid & 1;
    uint32_t dofs[4];
#pragma unroll
    for (int s = 0; s < 4; s++)
        dofs[s] = SWZ128((uint32_t)(r * 128 + h2 * 64 + s * 16));
    const __half* gA = A + (size_t)(m0 + r) * DMODEL + kOff + h2 * 32;
    const __half* gB = B + (size_t)(n0 + r) * DMODEL + kOff + h2 * 32;

    const int aRow = wm * 64 + (lane & 15);
    const int bRow = wn * 32 + (lane & 15);
    const int kb   = (lane >> 4) << 4;

    const int NCH = KSPLIT / 64;   // 8 chunks

#define LOAD_STAGE(kc, st)                                                  \
    do {                                                                    \
        const uint32_t base = sb + (uint32_t)(st) * STAGE_B;                \
        _Pragma("unroll")                                                   \
        for (int s = 0; s < 4; s++) {                                       \
            cp16(base + dofs[s],         gA + (kc) + s * 8);                \
            cp16(base + 16384 + dofs[s], gB + (kc) + s * 8);                \
        }                                                                   \
    } while (0)

    LOAD_STAGE(0, 0);
    cp_commit();

    for (int it = 0; it < NCH; it++) {
        if (it + 1 < NCH) {
            LOAD_STAGE((it + 1) * 64, (it + 1) & 1);
            cp_commit();
            cp_wait<1>();
        } else {
            cp_wait<0>();
        }
        __syncthreads();

        const uint32_t bA = sb + (uint32_t)(it & 1) * STAGE_B;
        const uint32_t bB = bA + 16384;

#pragma unroll
        for (int kk = 0; kk < 4; kk++) {
            const uint32_t kby = (uint32_t)(kk * 32 + kb);
            uint32_t ah[4][4];
#pragma unroll
            for (int mt = 0; mt < 4; mt++) {
                const uint32_t row = (uint32_t)(aRow + mt * 16) * 128;
                ldsm_x4(ah[mt], bA + SWZ128(row + kby));
            }
#pragma unroll
            for (int ntp = 0; ntp < 2; ntp++) {
                const uint32_t row = (uint32_t)(bRow + ntp * 16) * 128;
                uint32_t bb[4];
                ldsm_x4(bb, bB + SWZ128(row + kby));
#pragma unroll
                for (int half = 0; half < 2; half++) {
                    const int nt = ntp * 2 + half;
                    uint32_t bf[2] = {bb[half], bb[half + 2]};
#pragma unroll
                    for (int mt = 0; mt < 4; mt++)
                        mma_f16(acc[mt][nt], ah[mt], bf);
                }
            }
        }
        __syncthreads();
    }

    const int g  = lane >> 2;
    const int tg = lane & 3;
#pragma unroll
    for (int mt = 0; mt < 4; mt++) {
#pragma unroll
        for (int half = 0; half < 2; half++) {
            const int m = m0 + wm * 64 + mt * 16 + g + half * 8;
            float* cp = C + (size_t)m * ldC + n0 + wn * 32;
#pragma unroll
            for (int nt = 0; nt < 4; nt++) {
                const int col = nt * 8 + tg * 2;
                *(float2*)(cp + col) =
                    make_float2(acc[mt][nt][half * 2], acc[mt][nt][half * 2 + 1]);
            }
        }
    }
}

// =====================================================================
// RoPE: read fp32 q,k = (pa+pb); emit single fp16 (q pre-scaled 1/8).
// =====================================================================
__global__ void __launch_bounds__(512) rope_kernel()
{
    const int s = blockIdx.x;
    const int h = threadIdx.x >> 5;
    const int j = threadIdx.x & 31;

    const float LOG2_1E4 = 13.28771237954945f;
    float inv = exp2f(-(float)j * (LOG2_1E4 / 32.0f));
    float ang = (float)s * inv;
    float sn, cs;
    sincosf(ang, &sn, &cs);

    const size_t base = (size_t)s * 3072 + h * 64;
    const float* pa = g_pa + base;
    const float* pb = g_pb + base;

    float q0 = pa[j] + pb[j];
    float q1 = pa[j + 32] + pb[j + 32];
    float k0 = pa[1024 + j] + pb[1024 + j];
    float k1 = pa[1024 + j + 32] + pb[1024 + j + 32];

    const size_t o = (size_t)s * DMODEL + h * 64 + j;
    g_q[o]      = __float2half_rn((q0 * cs - q1 * sn) * 0.125f);
    g_q[o + 32] = __float2half_rn((q1 * cs + q0 * sn) * 0.125f);
    g_k[o]      = __float2half_rn(k0 * cs - k1 * sn);
    g_k[o + 32] = __float2half_rn(k1 * cs + k0 * sn);
}

// =====================================================================
// Windowed causal flash attention, single-fp16 mma.sync.
// grid = (NHEADS, S/64), 256 threads = 8 warps (2x4).
// =====================================================================
#define AQ0 0u
#define AK0 8192u
#define AK1 16384u
#define AV0 24576u
#define ASS 32768u               // S fp32 [64][68] = 17408 B
#define APH 50176u               // P fp16 [64 rows][128B] SW128
#define AROW 58368u              // 64 floats row scales
#define ATT_SMEM 58624

__global__ void __launch_bounds__(256, 2) attn_kernel()
{
    extern __shared__ char sm[];
    const uint32_t sb = smem_u32(sm);
    float* sS   = (float*)(sm + ASS);
    float* sRow = (float*)(sm + AROW);

    const int h   = blockIdx.x;
    const int q0  = blockIdx.y * 64;
    const int tid = threadIdx.x;
    const int wid = tid >> 5, lane = tid & 31;
    const int wm = wid & 1, wn = wid >> 1;
    const int g = lane >> 2, tg = lane & 3;
    const int tx = tid & 15, ty = tid >> 4;

    const int r4 = tid >> 2;
    const int s4 = (tid & 3) * 2;
    const uint32_t tdst0 = SWZ128((uint32_t)(r4 * 128 + s4 * 16));
    const uint32_t tdst1 = SWZ128((uint32_t)(r4 * 128 + s4 * 16 + 16));

#define ATL(dstbase, srcptr)                         \
    do {                                             \
        cp16((dstbase) + tdst0, (srcptr));           \
        cp16((dstbase) + tdst1, (srcptr) + 8);       \
    } while (0)

    const int kstart = (q0 - WINDOW) < 0 ? 0 : (q0 - WINDOW);
    const int nch = (q0 - kstart) / 64 + 1;

    ATL(sb + AQ0, g_q + (size_t)(q0 + r4) * DMODEL + h * 64 + s4 * 8);
    ATL(sb + AK0, g_k + (size_t)(kstart + r4) * DMODEL + h * 64 + s4 * 8);
    cp_commit();

    float o[2][2][4];
#pragma unroll
    for (int i = 0; i < 2; i++)
#pragma unroll
        for (int j = 0; j < 2; j++)
#pragma unroll
            for (int c = 0; c < 4; c++) o[i][j][c] = 0.f;
    float m_[4], l_[4];
#pragma unroll
    for (int i = 0; i < 4; i++) { m_[i] = -1e30f; l_[i] = 0.f; }

    const int kb = (lane >> 4) * 16;
    const int aRowQ = wm * 32 + (lane & 15);
    const int bRow  = wn * 16 + (lane & 15);

    for (int it = 0; it < nch; it++) {
        const int kc = kstart + it * 64;
        const uint32_t KB  = (it & 1) ? AK1 : AK0;
        const uint32_t KBn = (it & 1) ? AK0 : AK1;
        const bool pf = (it + 1 < nch);

        cp_wait<0>();
        __syncthreads();

        ATL(sb + AV0, g_v + (size_t)(h * 64 + r4) * S_LEN + kc + s4 * 8);
        cp_commit();

        // ---- S = Q K^T ----
        float sacc[2][2][4];
#pragma unroll
        for (int i = 0; i < 2; i++)
#pragma unroll
            for (int j = 0; j < 2; j++)
#pragma unroll
                for (int c = 0; c < 4; c++) sacc[i][j][c] = 0.f;

#pragma unroll
        for (int kk = 0; kk < 4; kk++) {
            const uint32_t kby = (uint32_t)(kk * 32 + kb);
            uint32_t ah[2][4];
#pragma unroll
            for (int mt = 0; mt < 2; mt++) {
                const uint32_t row = (uint32_t)(aRowQ + mt * 16) * 128;
                ldsm_x4(ah[mt], sb + AQ0 + SWZ128(row + kby));
            }
            uint32_t bb[4];
            ldsm_x4(bb, sb + KB + SWZ128((uint32_t)bRow * 128 + kby));
#pragma unroll
            for (int nt = 0; nt < 2; nt++) {
                uint32_t bf[2] = {bb[nt], bb[nt + 2]};
#pragma unroll
                for (int mt = 0; mt < 2; mt++)
                    mma_f16(sacc[mt][nt], ah[mt], bf);
            }
        }

        if (pf) {
            ATL(sb + KBn, g_k + (size_t)(kc + 64 + r4) * DMODEL + h * 64 + s4 * 8);
            cp_commit();
        }

        // ---- S fragments -> smem ----
#pragma unroll
        for (int mt = 0; mt < 2; mt++) {
#pragma unroll
            for (int nt = 0; nt < 2; nt++) {
                const int rr = wm * 32 + mt * 16 + g;
                const int cc = wn * 16 + nt * 8 + tg * 2;
                *(float2*)&sS[rr * 68 + cc]       = make_float2(sacc[mt][nt][0], sacc[mt][nt][1]);
                *(float2*)&sS[(rr + 8) * 68 + cc] = make_float2(sacc[mt][nt][2], sacc[mt][nt][3]);
            }
        }
        __syncthreads();

        // ---- fp32 online softmax; P -> fp16 tile ----
#pragma unroll
        for (int i = 0; i < 4; i++) {
            const int q = q0 + ty * 4 + i;
            float sv[4];
            float rmax = -1e30f;
#pragma unroll
            for (int j = 0; j < 4; j++) {
                const int key = kc + tx * 4 + j;
                float v = sS[(ty * 4 + i) * 68 + tx * 4 + j];
                const bool ok = (key <= q) && (q - key <= WINDOW);
                sv[j] = ok ? v : -1e30f;
                rmax = fmaxf(rmax, sv[j]);
            }
#pragma unroll
            for (int of = 8; of >= 1; of >>= 1)
                rmax = fmaxf(rmax, __shfl_xor_sync(0xffffffffu, rmax, of));
            const float mnew = fmaxf(m_[i], rmax);
            const float scale = __expf(m_[i] - mnew);
            float p[4], rsum = 0.f;
#pragma unroll
            for (int j = 0; j < 4; j++) { p[j] = __expf(sv[j] - mnew); rsum += p[j]; }
            {
                const uint32_t off = SWZ128((uint32_t)((ty * 4 + i) * 128 + tx * 8));
                *(uint2*)(sm + APH + off) =
                    make_uint2(pack_hf2(p[0], p[1]), pack_hf2(p[2], p[3]));
            }
#pragma unroll
            for (int of = 8; of >= 1; of >>= 1)
                rsum += __shfl_xor_sync(0xffffffffu, rsum, of);
            l_[i] = l_[i] * scale + rsum;
            m_[i] = mnew;
            if (tx == 0) sRow[ty * 4 + i] = scale;
        }

        if (pf) cp_wait<1>(); else cp_wait<0>();
        __syncthreads();

        // ---- rescale O, then O += P V ----
#pragma unroll
        for (int mt = 0; mt < 2; mt++) {
            const float rs0 = sRow[wm * 32 + mt * 16 + g];
            const float rs1 = sRow[wm * 32 + mt * 16 + g + 8];
#pragma unroll
            for (int nt = 0; nt < 2; nt++) {
                o[mt][nt][0] *= rs0; o[mt][nt][1] *= rs0;
                o[mt][nt][2] *= rs1; o[mt][nt][3] *= rs1;
            }
        }
#pragma unroll
        for (int kk = 0; kk < 4; kk++) {
            const uint32_t kby = (uint32_t)(kk * 32 + kb);
            uint32_t ap[2][4];
#pragma unroll
            for (int mt = 0; mt < 2; mt++) {
                const uint32_t row = (uint32_t)(aRowQ + mt * 16) * 128;
                ldsm_x4(ap[mt], sb + APH + SWZ128(row + kby));
            }
            uint32_t bb[4];
            ldsm_x4(bb, sb + AV0 + SWZ128((uint32_t)bRow * 128 + kby));
#pragma unroll
            for (int nt = 0; nt < 2; nt++) {
                uint32_t bf[2] = {bb[nt], bb[nt + 2]};
#pragma unroll
                for (int mt = 0; mt < 2; mt++)
                    mma_f16(o[mt][nt], ap[mt], bf);
            }
        }
    }

    __syncthreads();
#pragma unroll
    for (int i = 0; i < 4; i++)
        if (tx == 0) sRow[ty * 4 + i] = 1.f / l_[i];
    __syncthreads();

    // write O (single fp16) to g_a16 [s][h*64+d]
#pragma unroll
    for (int mt = 0; mt < 2; mt++) {
        const int r0 = wm * 32 + mt * 16 + g;
        const float inv0 = sRow[r0], inv1 = sRow[r0 + 8];
#pragma unroll
        for (int nt = 0; nt < 2; nt++) {
            const int col = h * 64 + wn * 16 + nt * 8 + tg * 2;
#pragma unroll
            for (int half = 0; half < 2; half++) {
                const float iv = half ? inv1 : inv0;
                const int rr = r0 + half * 8;
                __half2 hp = {__float2half_rn(o[mt][nt][half * 2] * iv),
                              __float2half_rn(o[mt][nt][half * 2 + 1] * iv)};
                *(uint32_t*)(g_a16 + (size_t)(q0 + rr) * DMODEL + col) = *(uint32_t*)&hp;
            }
        }
    }
}

// =====================================================================
// LayerNorm with fused residual + split-K reduce:
//   res = x + o0 + o1 ; y = LN(res)*gamma + beta.  grid=S, block=256
// =====================================================================
__global__ void __launch_bounds__(256) ln_kernel(
    const float* __restrict__ x,
    const float* __restrict__ o0, const float* __restrict__ o1,
    const float* __restrict__ gamma, const float* __restrict__ beta,
    float* __restrict__ y)
{
    const int s = blockIdx.x;
    const int tid = threadIdx.x;
    const size_t base = (size_t)s * DMODEL + tid * 4;

    float4 xv = *(const float4*)(x + base);
    float4 a  = *(const float4*)(o0 + base);
    float4 b4 = *(const float4*)(o1 + base);
    xv.x += a.x + b4.x;
    xv.y += a.y + b4.y;
    xv.z += a.z + b4.z;
    xv.w += a.w + b4.w;

    float s1 = xv.x + xv.y + xv.z + xv.w;
    float s2 = xv.x * xv.x + xv.y * xv.y + xv.z * xv.z + xv.w * xv.w;
#pragma unroll
    for (int o = 16; o >= 1; o >>= 1) {
        s1 += __shfl_xor_sync(0xffffffffu, s1, o);
        s2 += __shfl_xor_sync(0xffffffffu, s2, o);
    }
    __shared__ float a1[8], a2[8];
    const int w = tid >> 5, lane = tid & 31;
    if (lane == 0) { a1[w] = s1; a2[w] = s2; }
    __syncthreads();
    float t1 = 0.f, t2 = 0.f;
#pragma unroll
    for (int i = 0; i < 8; i++) { t1 += a1[i]; t2 += a2[i]; }

    const float mu  = t1 * (1.0f / DMODEL);
    const float var = t2 * (1.0f / DMODEL) - mu * mu;
    const float rstd = rsqrtf(var + LN_EPS);

    const int c = tid * 4;
    float4 gm = *(const float4*)(gamma + c);
    float4 bt = *(const float4*)(beta + c);
    float4 o;
    o.x = (xv.x - mu) * rstd * gm.x + bt.x;
    o.y = (xv.y - mu) * rstd * gm.y + bt.y;
    o.z = (xv.z - mu) * rstd * gm.z + bt.z;
    o.w = (xv.w - mu) * rstd * gm.w + bt.w;
    *(float4*)(y + (size_t)s * DMODEL + c) = o;
}

// =====================================================================
// launch
// =====================================================================
extern "C" void kernel_launch(void* const* d_in, const int* in_sizes, int n_in,
                              void* d_out, int out_size)
{
    const float* x     = (const float*)d_in[0];
    const float* state = (const float*)d_in[1];
    const float* Wqkv  = (const float*)d_in[2];
    const float* Wout  = (const float*)d_in[3];
    const float* gamma = (const float*)d_in[4];
    const float* beta  = (const float*)d_in[5];
    float* y = (float*)d_out;

    float *o0, *o1, *pa, *pb;
    __half *x16, *a16, *wq, *wo;
    cudaGetSymbolAddress((void**)&o0,  g_out0);
    cudaGetSymbolAddress((void**)&o1,  g_out1);
    cudaGetSymbolAddress((void**)&pa,  g_pa);
    cudaGetSymbolAddress((void**)&pb,  g_pb);
    cudaGetSymbolAddress((void**)&x16, g_x16);
    cudaGetSymbolAddress((void**)&a16, g_a16);
    cudaGetSymbolAddress((void**)&wq,  g_wq);
    cudaGetSymbolAddress((void**)&wo,  g_wo);

    cudaFuncSetAttribute(gemm_f16, cudaFuncAttributeMaxDynamicSharedMemorySize, GEMM_SMEM);
    cudaFuncSetAttribute(attn_kernel, cudaFuncAttributeMaxDynamicSharedMemorySize, ATT_SMEM);

    // 0) operand prep
    tofp16_kernel<<<512, 256>>>((const float4*)x, (uint2*)x16, S_LEN * DMODEL / 4);
    wsplit_kernel<<<dim3(3 * DMODEL / 32, DMODEL / 32), 256>>>(Wqkv, wq,
                                                               DMODEL, 3 * DMODEL);
    wsplit_kernel<<<dim3(DMODEL / 32, DMODEL / 32), 256>>>(Wout, wo,
                                                           DMODEL, DMODEL);

    // 1) QKV projection, split-K=2 -> pa, pb
    gemm_f16<<<dim3(3 * DMODEL / 128, S_LEN / 128, 2), 256, GEMM_SMEM>>>(
        x16, wq, pa, pb, 3 * DMODEL);

    // 2) RoPE (reads pa+pb) -> q,k fp16 ; V transpose -> fp16
    rope_kernel<<<S_LEN, 512>>>();
    vsplit_kernel<<<dim3(DMODEL / 32, S_LEN / 32), 256>>>();

    // 3) windowed attention (fp16 tensor cores)
    attn_kernel<<<dim3(NHEADS, S_LEN / 64), 256, ATT_SMEM>>>();

    // 4) output projection, split-K=2 -> o0, o1
    gemm_f16<<<dim3(DMODEL / 128, S_LEN / 128, 2), 256, GEMM_SMEM>>>(
        a16, wo, o0, o1, DMODEL);

    // 5) LayerNorm (fused residual + split-K reduce) -> y
    ln_kernel<<<S_LEN, 256>>>(x, o0, o1, gamma, beta, y);

    // 6) pass-through state if the output buffer includes it
    if (out_size >= S_LEN * DMODEL + DMODEL) {
        cudaMemcpyAsync(y + (size_t)S_LEN * DMODEL, state,
                        DMODEL * sizeof(float), cudaMemcpyDeviceToDevice);
    }
}

// round 12
// speedup vs baseline: 4.1842x; 1.0439x over previous
#include <cuda_runtime.h>
#include <cuda_fp16.h>
#include <math.h>
#include <stdint.h>

#define S_LEN   2048
#define DMODEL  1024
#define NHEADS  16
#define WINDOW  256
#define LN_EPS  1e-5f

// ---------------- scratch (no allocations allowed) ----------------
__device__ float  g_res[(size_t)S_LEN * DMODEL];       // x + attn@Wo (pre-LN)
__device__ __half g_qkv16[(size_t)S_LEN * 3 * DMODEL]; // QKV GEMM out (fp16)

// single fp16 operands
__device__ __half g_x16[(size_t)S_LEN * DMODEL];      // x fp16
__device__ __half g_a16[(size_t)S_LEN * DMODEL];      // attention out fp16
__device__ __half g_wq[(size_t)3 * DMODEL * DMODEL];  // W_qkv^T [3072,1024]
__device__ __half g_wo[(size_t)DMODEL * DMODEL];      // W_out^T [1024,1024]

// attention operands
__device__ __half g_q[(size_t)S_LEN * DMODEL];   // q (pre-scaled 1/8, roped)
__device__ __half g_k[(size_t)S_LEN * DMODEL];   // k (roped)
__device__ __half g_v[(size_t)DMODEL * S_LEN];   // V^T: [h*64+d][s]

// =====================================================================
// warp-level tensor-core helpers (sm_80+ baseline)
// =====================================================================
__device__ __forceinline__ uint32_t smem_u32(const void* p) {
    uint32_t a;
    asm("{ .reg .u64 t; cvta.to.shared.u64 t, %1; cvt.u32.u64 %0, t; }" : "=r"(a) : "l"(p));
    return a;
}
__device__ __forceinline__ void ldsm_x4(uint32_t* r, uint32_t addr) {
    asm volatile("ldmatrix.sync.aligned.m8n8.x4.shared.b16 {%0,%1,%2,%3}, [%4];"
                 : "=r"(r[0]), "=r"(r[1]), "=r"(r[2]), "=r"(r[3]) : "r"(addr));
}
__device__ __forceinline__ void mma_f16(float* d, const uint32_t* a, const uint32_t* b) {
    asm volatile(
        "mma.sync.aligned.m16n8k16.row.col.f32.f16.f16.f32 "
        "{%0,%1,%2,%3}, {%4,%5,%6,%7}, {%8,%9}, {%0,%1,%2,%3};"
        : "+f"(d[0]), "+f"(d[1]), "+f"(d[2]), "+f"(d[3])
        : "r"(a[0]), "r"(a[1]), "r"(a[2]), "r"(a[3]), "r"(b[0]), "r"(b[1]));
}
__device__ __forceinline__ void cp16(uint32_t dst, const void* src) {
    asm volatile("cp.async.cg.shared.global [%0], [%1], 16;" :: "r"(dst), "l"(src));
}
__device__ __forceinline__ void cp_commit() {
    asm volatile("cp.async.commit_group;" ::: "memory");
}
template <int N>
__device__ __forceinline__ void cp_wait() {
    asm volatile("cp.async.wait_group %0;" :: "n"(N) : "memory");
}

#define SWZ128(bo) ((bo) ^ (((bo) >> 3) & 0x70))

__device__ __forceinline__ uint32_t pack_hf2(float a, float b) {
    __half2 p = {__float2half_rn(a), __float2half_rn(b)};
    return *(uint32_t*)&p;
}

// =====================================================================
// x -> single fp16
// =====================================================================
__global__ void __launch_bounds__(256) tofp16_kernel(
    const float4* __restrict__ in, uint2* __restrict__ out, int n4)
{
    for (int i = blockIdx.x * blockDim.x + threadIdx.x; i < n4; i += gridDim.x * blockDim.x) {
        float4 v = in[i];
        out[i] = make_uint2(pack_hf2(v.x, v.y), pack_hf2(v.z, v.w));
    }
}

// =====================================================================
// transpose: W [K,N] fp32 -> W^T [N,K] single fp16
// =====================================================================
__global__ void __launch_bounds__(256) wsplit_kernel(
    const float* __restrict__ W, __half* __restrict__ out, int K, int N)
{
    __shared__ float t[32][33];
    const int tx = threadIdx.x & 31;
    const int ty = threadIdx.x >> 5;
    const int bn = blockIdx.x * 32;
    const int bk = blockIdx.y * 32;
#pragma unroll
    for (int i = 0; i < 32; i += 8)
        t[ty + i][tx] = W[(size_t)(bk + ty + i) * N + bn + tx];
    __syncthreads();
#pragma unroll
    for (int i = 0; i < 32; i += 8)
        out[(size_t)(bn + ty + i) * K + bk + tx] = __float2half_rn(t[tx][ty + i]);
}

// =====================================================================
// V transpose: g_qkv16 v region [s][c] fp16 -> g_v [c][s] fp16
// =====================================================================
__global__ void __launch_bounds__(256) vsplit_kernel()
{
    __shared__ __half t[32][34];
    const int tx = threadIdx.x & 31;
    const int ty = threadIdx.x >> 5;
    const int c0 = blockIdx.x * 32;
    const int s0 = blockIdx.y * 32;
#pragma unroll
    for (int i = 0; i < 32; i += 8)
        t[ty + i][tx] = g_qkv16[(size_t)(s0 + ty + i) * 3072 + 2048 + c0 + tx];
    __syncthreads();
#pragma unroll
    for (int i = 0; i < 32; i += 8)
        g_v[(size_t)(c0 + ty + i) * S_LEN + s0 + tx] = t[tx][ty + i];
}

// =====================================================================
// single-fp16 tensor-core GEMM, full-K.
// CTA 128x128 x K=1024, K-chunk 64, 2-stage cp.async.
// Epilogue: if C16 != null -> write fp16 (ldC elems); else fp32 C (+Cadd).
// SMEM stage: A 16KB | B 16KB = 32KB; 2 stages = 64KB.
// =====================================================================
#define STAGE_B 32768
#define GEMM_SMEM (2 * STAGE_B)

__global__ void __launch_bounds__(256, 2) gemm_f16(
    const __half* __restrict__ A, const __half* __restrict__ B,
    __half* __restrict__ C16, float* __restrict__ C,
    const float* __restrict__ Cadd, int ldC)
{
    extern __shared__ char smem[];
    const uint32_t sb = smem_u32(smem);

    const int tid  = threadIdx.x;
    const int wid  = tid >> 5;
    const int lane = tid & 31;
    const int wm   = wid & 1;
    const int wn   = wid >> 1;
    const int m0 = blockIdx.y * 128;
    const int n0 = blockIdx.x * 128;

    float acc[4][4][4];
#pragma unroll
    for (int i = 0; i < 4; i++)
#pragma unroll
        for (int j = 0; j < 4; j++)
#pragma unroll
            for (int c = 0; c < 4; c++) acc[i][j][c] = 0.f;

    const int r  = tid >> 1;
    const int h2 = tid & 1;
    uint32_t dofs[4];
#pragma unroll
    for (int s = 0; s < 4; s++)
        dofs[s] = SWZ128((uint32_t)(r * 128 + h2 * 64 + s * 16));
    const __half* gA = A + (size_t)(m0 + r) * DMODEL + h2 * 32;
    const __half* gB = B + (size_t)(n0 + r) * DMODEL + h2 * 32;

    const int aRow = wm * 64 + (lane & 15);
    const int bRow = wn * 32 + (lane & 15);
    const int kb   = (lane >> 4) << 4;

    const int NCH = DMODEL / 64;   // 16 chunks

#define LOAD_STAGE(kc, st)                                                  \
    do {                                                                    \
        const uint32_t base = sb + (uint32_t)(st) * STAGE_B;                \
        _Pragma("unroll")                                                   \
        for (int s = 0; s < 4; s++) {                                       \
            cp16(base + dofs[s],         gA + (kc) + s * 8);                \
            cp16(base + 16384 + dofs[s], gB + (kc) + s * 8);                \
        }                                                                   \
    } while (0)

    LOAD_STAGE(0, 0);
    cp_commit();

    for (int it = 0; it < NCH; it++) {
        if (it + 1 < NCH) {
            LOAD_STAGE((it + 1) * 64, (it + 1) & 1);
            cp_commit();
            cp_wait<1>();
        } else {
            cp_wait<0>();
        }
        __syncthreads();

        const uint32_t bA = sb + (uint32_t)(it & 1) * STAGE_B;
        const uint32_t bB = bA + 16384;

#pragma unroll
        for (int kk = 0; kk < 4; kk++) {
            const uint32_t kby = (uint32_t)(kk * 32 + kb);
            uint32_t ah[4][4];
#pragma unroll
            for (int mt = 0; mt < 4; mt++) {
                const uint32_t row = (uint32_t)(aRow + mt * 16) * 128;
                ldsm_x4(ah[mt], bA + SWZ128(row + kby));
            }
#pragma unroll
            for (int ntp = 0; ntp < 2; ntp++) {
                const uint32_t row = (uint32_t)(bRow + ntp * 16) * 128;
                uint32_t bb[4];
                ldsm_x4(bb, bB + SWZ128(row + kby));
#pragma unroll
                for (int half = 0; half < 2; half++) {
                    const int nt = ntp * 2 + half;
                    uint32_t bf[2] = {bb[half], bb[half + 2]};
#pragma unroll
                    for (int mt = 0; mt < 4; mt++)
                        mma_f16(acc[mt][nt], ah[mt], bf);
                }
            }
        }
        __syncthreads();
    }

    const int g  = lane >> 2;
    const int tg = lane & 3;
    if (C16) {
#pragma unroll
        for (int mt = 0; mt < 4; mt++) {
#pragma unroll
            for (int half = 0; half < 2; half++) {
                const int m = m0 + wm * 64 + mt * 16 + g + half * 8;
                __half* cp = C16 + (size_t)m * ldC + n0 + wn * 32;
#pragma unroll
                for (int nt = 0; nt < 4; nt++) {
                    const int col = nt * 8 + tg * 2;
                    *(uint32_t*)(cp + col) =
                        pack_hf2(acc[mt][nt][half * 2], acc[mt][nt][half * 2 + 1]);
                }
            }
        }
    } else {
#pragma unroll
        for (int mt = 0; mt < 4; mt++) {
#pragma unroll
            for (int half = 0; half < 2; half++) {
                const int m = m0 + wm * 64 + mt * 16 + g + half * 8;
                float* cp = C + (size_t)m * ldC + n0 + wn * 32;
                const float* ap = Cadd ? (Cadd + (size_t)m * ldC + n0 + wn * 32) : nullptr;
#pragma unroll
                for (int nt = 0; nt < 4; nt++) {
                    const int col = nt * 8 + tg * 2;
                    float2 v = make_float2(acc[mt][nt][half * 2], acc[mt][nt][half * 2 + 1]);
                    if (ap) {
                        float2 c = *(const float2*)(ap + col);
                        v.x += c.x; v.y += c.y;
                    }
                    *(float2*)(cp + col) = v;
                }
            }
        }
    }
}

// =====================================================================
// RoPE: read fp16 q,k from g_qkv16; emit fp16 q (pre-scaled 1/8), k.
// =====================================================================
__global__ void __launch_bounds__(512) rope_kernel()
{
    const int s = blockIdx.x;
    const int h = threadIdx.x >> 5;
    const int j = threadIdx.x & 31;

    const float LOG2_1E4 = 13.28771237954945f;
    float inv = exp2f(-(float)j * (LOG2_1E4 / 32.0f));
    float ang = (float)s * inv;
    float sn, cs;
    sincosf(ang, &sn, &cs);

    const size_t base = (size_t)s * 3072 + h * 64;
    const __half* qk = g_qkv16 + base;

    float q0 = __half2float(qk[j]);
    float q1 = __half2float(qk[j + 32]);
    float k0 = __half2float(qk[1024 + j]);
    float k1 = __half2float(qk[1024 + j + 32]);

    const size_t o = (size_t)s * DMODEL + h * 64 + j;
    g_q[o]      = __float2half_rn((q0 * cs - q1 * sn) * 0.125f);
    g_q[o + 32] = __float2half_rn((q1 * cs + q0 * sn) * 0.125f);
    g_k[o]      = __float2half_rn(k0 * cs - k1 * sn);
    g_k[o + 32] = __float2half_rn(k1 * cs + k0 * sn);
}

// =====================================================================
// Windowed causal flash attention, single-fp16 mma.sync.
// grid = (NHEADS, S/64), 256 threads = 8 warps (2x4).
// =====================================================================
#define AQ0 0u
#define AK0 8192u
#define AK1 16384u
#define AV0 24576u
#define ASS 32768u               // S fp32 [64][68] = 17408 B
#define APH 50176u               // P fp16 [64 rows][128B] SW128
#define AROW 58368u              // 64 floats row scales
#define ATT_SMEM 58624

__global__ void __launch_bounds__(256, 2) attn_kernel()
{
    extern __shared__ char sm[];
    const uint32_t sb = smem_u32(sm);
    float* sS   = (float*)(sm + ASS);
    float* sRow = (float*)(sm + AROW);

    const int h   = blockIdx.x;
    const int q0  = blockIdx.y * 64;
    const int tid = threadIdx.x;
    const int wid = tid >> 5, lane = tid & 31;
    const int wm = wid & 1, wn = wid >> 1;
    const int g = lane >> 2, tg = lane & 3;
    const int tx = tid & 15, ty = tid >> 4;

    const int r4 = tid >> 2;
    const int s4 = (tid & 3) * 2;
    const uint32_t tdst0 = SWZ128((uint32_t)(r4 * 128 + s4 * 16));
    const uint32_t tdst1 = SWZ128((uint32_t)(r4 * 128 + s4 * 16 + 16));

#define ATL(dstbase, srcptr)                         \
    do {                                             \
        cp16((dstbase) + tdst0, (srcptr));           \
        cp16((dstbase) + tdst1, (srcptr) + 8);       \
    } while (0)

    const int kstart = (q0 - WINDOW) < 0 ? 0 : (q0 - WINDOW);
    const int nch = (q0 - kstart) / 64 + 1;

    ATL(sb + AQ0, g_q + (size_t)(q0 + r4) * DMODEL + h * 64 + s4 * 8);
    ATL(sb + AK0, g_k + (size_t)(kstart + r4) * DMODEL + h * 64 + s4 * 8);
    cp_commit();

    float o[2][2][4];
#pragma unroll
    for (int i = 0; i < 2; i++)
#pragma unroll
        for (int j = 0; j < 2; j++)
#pragma unroll
            for (int c = 0; c < 4; c++) o[i][j][c] = 0.f;
    float m_[4], l_[4];
#pragma unroll
    for (int i = 0; i < 4; i++) { m_[i] = -1e30f; l_[i] = 0.f; }

    const int kb = (lane >> 4) * 16;
    const int aRowQ = wm * 32 + (lane & 15);
    const int bRow  = wn * 16 + (lane & 15);

    for (int it = 0; it < nch; it++) {
        const int kc = kstart + it * 64;
        const uint32_t KB  = (it & 1) ? AK1 : AK0;
        const uint32_t KBn = (it & 1) ? AK0 : AK1;
        const bool pf = (it + 1 < nch);

        cp_wait<0>();
        __syncthreads();

        ATL(sb + AV0, g_v + (size_t)(h * 64 + r4) * S_LEN + kc + s4 * 8);
        cp_commit();

        // ---- S = Q K^T ----
        float sacc[2][2][4];
#pragma unroll
        for (int i = 0; i < 2; i++)
#pragma unroll
            for (int j = 0; j < 2; j++)
#pragma unroll
                for (int c = 0; c < 4; c++) sacc[i][j][c] = 0.f;

#pragma unroll
        for (int kk = 0; kk < 4; kk++) {
            const uint32_t kby = (uint32_t)(kk * 32 + kb);
            uint32_t ah[2][4];
#pragma unroll
            for (int mt = 0; mt < 2; mt++) {
                const uint32_t row = (uint32_t)(aRowQ + mt * 16) * 128;
                ldsm_x4(ah[mt], sb + AQ0 + SWZ128(row + kby));
            }
            uint32_t bb[4];
            ldsm_x4(bb, sb + KB + SWZ128((uint32_t)bRow * 128 + kby));
#pragma unroll
            for (int nt = 0; nt < 2; nt++) {
                uint32_t bf[2] = {bb[nt], bb[nt + 2]};
#pragma unroll
                for (int mt = 0; mt < 2; mt++)
                    mma_f16(sacc[mt][nt], ah[mt], bf);
            }
        }

        if (pf) {
            ATL(sb + KBn, g_k + (size_t)(kc + 64 + r4) * DMODEL + h * 64 + s4 * 8);
            cp_commit();
        }

        // ---- S fragments -> smem ----
#pragma unroll
        for (int mt = 0; mt < 2; mt++) {
#pragma unroll
            for (int nt = 0; nt < 2; nt++) {
                const int rr = wm * 32 + mt * 16 + g;
                const int cc = wn * 16 + nt * 8 + tg * 2;
                *(float2*)&sS[rr * 68 + cc]       = make_float2(sacc[mt][nt][0], sacc[mt][nt][1]);
                *(float2*)&sS[(rr + 8) * 68 + cc] = make_float2(sacc[mt][nt][2], sacc[mt][nt][3]);
            }
        }
        __syncthreads();

        // ---- fp32 online softmax; P -> fp16 tile ----
#pragma unroll
        for (int i = 0; i < 4; i++) {
            const int q = q0 + ty * 4 + i;
            float sv[4];
            float rmax = -1e30f;
#pragma unroll
            for (int j = 0; j < 4; j++) {
                const int key = kc + tx * 4 + j;
                float v = sS[(ty * 4 + i) * 68 + tx * 4 + j];
                const bool ok = (key <= q) && (q - key <= WINDOW);
                sv[j] = ok ? v : -1e30f;
                rmax = fmaxf(rmax, sv[j]);
            }
#pragma unroll
            for (int of = 8; of >= 1; of >>= 1)
                rmax = fmaxf(rmax, __shfl_xor_sync(0xffffffffu, rmax, of));
            const float mnew = fmaxf(m_[i], rmax);
            const float scale = __expf(m_[i] - mnew);
            float p[4], rsum = 0.f;
#pragma unroll
            for (int j = 0; j < 4; j++) { p[j] = __expf(sv[j] - mnew); rsum += p[j]; }
            {
                const uint32_t off = SWZ128((uint32_t)((ty * 4 + i) * 128 + tx * 8));
                *(uint2*)(sm + APH + off) =
                    make_uint2(pack_hf2(p[0], p[1]), pack_hf2(p[2], p[3]));
            }
#pragma unroll
            for (int of = 8; of >= 1; of >>= 1)
                rsum += __shfl_xor_sync(0xffffffffu, rsum, of);
            l_[i] = l_[i] * scale + rsum;
            m_[i] = mnew;
            if (tx == 0) sRow[ty * 4 + i] = scale;
        }

        if (pf) cp_wait<1>(); else cp_wait<0>();
        __syncthreads();

        // ---- rescale O, then O += P V ----
#pragma unroll
        for (int mt = 0; mt < 2; mt++) {
            const float rs0 = sRow[wm * 32 + mt * 16 + g];
            const float rs1 = sRow[wm * 32 + mt * 16 + g + 8];
#pragma unroll
            for (int nt = 0; nt < 2; nt++) {
                o[mt][nt][0] *= rs0; o[mt][nt][1] *= rs0;
                o[mt][nt][2] *= rs1; o[mt][nt][3] *= rs1;
            }
        }
#pragma unroll
        for (int kk = 0; kk < 4; kk++) {
            const uint32_t kby = (uint32_t)(kk * 32 + kb);
            uint32_t ap[2][4];
#pragma unroll
            for (int mt = 0; mt < 2; mt++) {
                const uint32_t row = (uint32_t)(aRowQ + mt * 16) * 128;
                ldsm_x4(ap[mt], sb + APH + SWZ128(row + kby));
            }
            uint32_t bb[4];
            ldsm_x4(bb, sb + AV0 + SWZ128((uint32_t)bRow * 128 + kby));
#pragma unroll
            for (int nt = 0; nt < 2; nt++) {
                uint32_t bf[2] = {bb[nt], bb[nt + 2]};
#pragma unroll
                for (int mt = 0; mt < 2; mt++)
                    mma_f16(o[mt][nt], ap[mt], bf);
            }
        }
    }

    __syncthreads();
#pragma unroll
    for (int i = 0; i < 4; i++)
        if (tx == 0) sRow[ty * 4 + i] = 1.f / l_[i];
    __syncthreads();

    // write O (fp16) to g_a16 [s][h*64+d]
#pragma unroll
    for (int mt = 0; mt < 2; mt++) {
        const int r0 = wm * 32 + mt * 16 + g;
        const float inv0 = sRow[r0], inv1 = sRow[r0 + 8];
#pragma unroll
        for (int nt = 0; nt < 2; nt++) {
            const int col = h * 64 + wn * 16 + nt * 8 + tg * 2;
#pragma unroll
            for (int half = 0; half < 2; half++) {
                const float iv = half ? inv1 : inv0;
                const int rr = r0 + half * 8;
                *(uint32_t*)(g_a16 + (size_t)(q0 + rr) * DMODEL + col) =
                    pack_hf2(o[mt][nt][half * 2] * iv, o[mt][nt][half * 2 + 1] * iv);
            }
        }
    }
}

// =====================================================================
// LayerNorm: y = LN(res)*gamma + beta.  grid=S, block=256
// =====================================================================
__global__ void __launch_bounds__(256) ln_kernel(
    const float* __restrict__ gamma, const float* __restrict__ beta,
    float* __restrict__ y)
{
    const int s = blockIdx.x;
    const int tid = threadIdx.x;
    const size_t base = (size_t)s * DMODEL + tid * 4;

    float4 xv = *(const float4*)(g_res + base);

    float s1 = xv.x + xv.y + xv.z + xv.w;
    float s2 = xv.x * xv.x + xv.y * xv.y + xv.z * xv.z + xv.w * xv.w;
#pragma unroll
    for (int o = 16; o >= 1; o >>= 1) {
        s1 += __shfl_xor_sync(0xffffffffu, s1, o);
        s2 += __shfl_xor_sync(0xffffffffu, s2, o);
    }
    __shared__ float a1[8], a2[8];
    const int w = tid >> 5, lane = tid & 31;
    if (lane == 0) { a1[w] = s1; a2[w] = s2; }
    __syncthreads();
    float t1 = 0.f, t2 = 0.f;
#pragma unroll
    for (int i = 0; i < 8; i++) { t1 += a1[i]; t2 += a2[i]; }

    const float mu  = t1 * (1.0f / DMODEL);
    const float var = t2 * (1.0f / DMODEL) - mu * mu;
    const float rstd = rsqrtf(var + LN_EPS);

    const int c = tid * 4;
    float4 gm = *(const float4*)(gamma + c);
    float4 bt = *(const float4*)(beta + c);
    float4 o;
    o.x = (xv.x - mu) * rstd * gm.x + bt.x;
    o.y = (xv.y - mu) * rstd * gm.y + bt.y;
    o.z = (xv.z - mu) * rstd * gm.z + bt.z;
    o.w = (xv.w - mu) * rstd * gm.w + bt.w;
    *(float4*)(y + (size_t)s * DMODEL + c) = o;
}

// =====================================================================
// launch
// =====================================================================
extern "C" void kernel_launch(void* const* d_in, const int* in_sizes, int n_in,
                              void* d_out, int out_size)
{
    const float* x     = (const float*)d_in[0];
    const float* state = (const float*)d_in[1];
    const float* Wqkv  = (const float*)d_in[2];
    const float* Wout  = (const float*)d_in[3];
    const float* gamma = (const float*)d_in[4];
    const float* beta  = (const float*)d_in[5];
    float* y = (float*)d_out;

    float* res;
    __half *qkv16, *x16, *a16, *wq, *wo;
    cudaGetSymbolAddress((void**)&res,   g_res);
    cudaGetSymbolAddress((void**)&qkv16, g_qkv16);
    cudaGetSymbolAddress((void**)&x16,   g_x16);
    cudaGetSymbolAddress((void**)&a16,   g_a16);
    cudaGetSymbolAddress((void**)&wq,    g_wq);
    cudaGetSymbolAddress((void**)&wo,    g_wo);

    cudaFuncSetAttribute(gemm_f16, cudaFuncAttributeMaxDynamicSharedMemorySize, GEMM_SMEM);
    cudaFuncSetAttribute(attn_kernel, cudaFuncAttributeMaxDynamicSharedMemorySize, ATT_SMEM);

    // 0) operand prep
    tofp16_kernel<<<512, 256>>>((const float4*)x, (uint2*)x16, S_LEN * DMODEL / 4);
    wsplit_kernel<<<dim3(3 * DMODEL / 32, DMODEL / 32), 256>>>(Wqkv, wq,
                                                               DMODEL, 3 * DMODEL);
    wsplit_kernel<<<dim3(DMODEL / 32, DMODEL / 32), 256>>>(Wout, wo,
                                                           DMODEL, DMODEL);

    // 1) QKV projection -> fp16 qkv
    gemm_f16<<<dim3(3 * DMODEL / 128, S_LEN / 128), 256, GEMM_SMEM>>>(
        x16, wq, qkv16, nullptr, nullptr, 3 * DMODEL);

    // 2) RoPE -> q,k fp16 ; V transpose -> fp16
    rope_kernel<<<S_LEN, 512>>>();
    vsplit_kernel<<<dim3(DMODEL / 32, S_LEN / 32), 256>>>();

    // 3) windowed attention (fp16 tensor cores)
    attn_kernel<<<dim3(NHEADS, S_LEN / 64), 256, ATT_SMEM>>>();

    // 4) output projection + fused residual -> res (fp32)
    gemm_f16<<<dim3(DMODEL / 128, S_LEN / 128), 256, GEMM_SMEM>>>(
        a16, wo, nullptr, res, x, DMODEL);

    // 5) LayerNorm -> y
    ln_kernel<<<S_LEN, 256>>>(gamma, beta, y);

    // 6) pass-through state if the output buffer includes it
    if (out_size >= S_LEN * DMODEL + DMODEL) {
        cudaMemcpyAsync(y + (size_t)S_LEN * DMODEL, state,
                        DMODEL * sizeof(float), cudaMemcpyDeviceToDevice);
    }
}

// round 13
// speedup vs baseline: 4.3711x; 1.0447x over previous
#include <cuda_runtime.h>
#include <cuda_fp16.h>
#include <math.h>
#include <stdint.h>

#define S_LEN   2048
#define DMODEL  1024
#define NHEADS  16
#define WINDOW  256
#define LN_EPS  1e-5f

// ---------------- scratch (no allocations allowed) ----------------
__device__ float  g_o0[(size_t)S_LEN * DMODEL];        // out-proj partial 0
__device__ float  g_o1[(size_t)S_LEN * DMODEL];        // out-proj partial 1
__device__ __half g_qkv16[(size_t)S_LEN * 3 * DMODEL]; // QKV GEMM out (fp16)

// single fp16 operands
__device__ __half g_x16[(size_t)S_LEN * DMODEL];      // x fp16
__device__ __half g_a16[(size_t)S_LEN * DMODEL];      // attention out fp16
__device__ __half g_wq[(size_t)3 * DMODEL * DMODEL];  // W_qkv^T [3072,1024]
__device__ __half g_wo[(size_t)DMODEL * DMODEL];      // W_out^T [1024,1024]

// attention operands
__device__ __half g_q[(size_t)S_LEN * DMODEL];   // q (pre-scaled 1/8, roped)
__device__ __half g_k[(size_t)S_LEN * DMODEL];   // k (roped)
__device__ __half g_v[(size_t)DMODEL * S_LEN];   // V^T: [h*64+d][s]

// =====================================================================
// warp-level tensor-core helpers (sm_80+ baseline)
// =====================================================================
__device__ __forceinline__ uint32_t smem_u32(const void* p) {
    uint32_t a;
    asm("{ .reg .u64 t; cvta.to.shared.u64 t, %1; cvt.u32.u64 %0, t; }" : "=r"(a) : "l"(p));
    return a;
}
__device__ __forceinline__ void ldsm_x4(uint32_t* r, uint32_t addr) {
    asm volatile("ldmatrix.sync.aligned.m8n8.x4.shared.b16 {%0,%1,%2,%3}, [%4];"
                 : "=r"(r[0]), "=r"(r[1]), "=r"(r[2]), "=r"(r[3]) : "r"(addr));
}
__device__ __forceinline__ void mma_f16(float* d, const uint32_t* a, const uint32_t* b) {
    asm volatile(
        "mma.sync.aligned.m16n8k16.row.col.f32.f16.f16.f32 "
        "{%0,%1,%2,%3}, {%4,%5,%6,%7}, {%8,%9}, {%0,%1,%2,%3};"
        : "+f"(d[0]), "+f"(d[1]), "+f"(d[2]), "+f"(d[3])
        : "r"(a[0]), "r"(a[1]), "r"(a[2]), "r"(a[3]), "r"(b[0]), "r"(b[1]));
}
__device__ __forceinline__ void cp16(uint32_t dst, const void* src) {
    asm volatile("cp.async.cg.shared.global [%0], [%1], 16;" :: "r"(dst), "l"(src));
}
__device__ __forceinline__ void cp_commit() {
    asm volatile("cp.async.commit_group;" ::: "memory");
}
template <int N>
__device__ __forceinline__ void cp_wait() {
    asm volatile("cp.async.wait_group %0;" :: "n"(N) : "memory");
}

#define SWZ128(bo) ((bo) ^ (((bo) >> 3) & 0x70))

__device__ __forceinline__ uint32_t pack_hf2(float a, float b) {
    __half2 p = {__float2half_rn(a), __float2half_rn(b)};
    return *(uint32_t*)&p;
}

// =====================================================================
// x -> single fp16
// =====================================================================
__global__ void __launch_bounds__(256) tofp16_kernel(
    const float4* __restrict__ in, uint2* __restrict__ out, int n4)
{
    for (int i = blockIdx.x * blockDim.x + threadIdx.x; i < n4; i += gridDim.x * blockDim.x) {
        float4 v = in[i];
        out[i] = make_uint2(pack_hf2(v.x, v.y), pack_hf2(v.z, v.w));
    }
}

// =====================================================================
// transpose: W [K,N] fp32 -> W^T [N,K] single fp16
// =====================================================================
__global__ void __launch_bounds__(256) wsplit_kernel(
    const float* __restrict__ W, __half* __restrict__ out, int K, int N)
{
    __shared__ float t[32][33];
    const int tx = threadIdx.x & 31;
    const int ty = threadIdx.x >> 5;
    const int bn = blockIdx.x * 32;
    const int bk = blockIdx.y * 32;
#pragma unroll
    for (int i = 0; i < 32; i += 8)
        t[ty + i][tx] = W[(size_t)(bk + ty + i) * N + bn + tx];
    __syncthreads();
#pragma unroll
    for (int i = 0; i < 32; i += 8)
        out[(size_t)(bn + ty + i) * K + bk + tx] = __float2half_rn(t[tx][ty + i]);
}

// =====================================================================
// V transpose: g_qkv16 v region [s][c] fp16 -> g_v [c][s] fp16
// =====================================================================
__global__ void __launch_bounds__(256) vsplit_kernel()
{
    __shared__ __half t[32][34];
    const int tx = threadIdx.x & 31;
    const int ty = threadIdx.x >> 5;
    const int c0 = blockIdx.x * 32;
    const int s0 = blockIdx.y * 32;
#pragma unroll
    for (int i = 0; i < 32; i += 8)
        t[ty + i][tx] = g_qkv16[(size_t)(s0 + ty + i) * 3072 + 2048 + c0 + tx];
    __syncthreads();
#pragma unroll
    for (int i = 0; i < 32; i += 8)
        g_v[(size_t)(c0 + ty + i) * S_LEN + s0 + tx] = t[tx][ty + i];
}

// =====================================================================
// single-fp16 tensor-core GEMM.
// CTA 128x128, K-chunk 64, 2-stage cp.async.
// QKV mode: kLen=1024, gridDim.z=1, C16 output.
// Out-proj mode: kLen=512, gridDim.z=2 (split-K), fp32 C0/C1 partials.
// =====================================================================
#define STAGE_B 32768
#define GEMM_SMEM (2 * STAGE_B)

__global__ void __launch_bounds__(256, 2) gemm_f16(
    const __half* __restrict__ A, const __half* __restrict__ B,
    __half* __restrict__ C16, float* __restrict__ C0, float* __restrict__ C1,
    int ldC, int kLen)
{
    extern __shared__ char smem[];
    const uint32_t sb = smem_u32(smem);

    const int tid  = threadIdx.x;
    const int wid  = tid >> 5;
    const int lane = tid & 31;
    const int wm   = wid & 1;
    const int wn   = wid >> 1;
    const int m0 = blockIdx.y * 128;
    const int n0 = blockIdx.x * 128;
    const int kOff = blockIdx.z * kLen;

    float acc[4][4][4];
#pragma unroll
    for (int i = 0; i < 4; i++)
#pragma unroll
        for (int j = 0; j < 4; j++)
#pragma unroll
            for (int c = 0; c < 4; c++) acc[i][j][c] = 0.f;

    const int r  = tid >> 1;
    const int h2 = tid & 1;
    uint32_t dofs[4];
#pragma unroll
    for (int s = 0; s < 4; s++)
        dofs[s] = SWZ128((uint32_t)(r * 128 + h2 * 64 + s * 16));
    const __half* gA = A + (size_t)(m0 + r) * DMODEL + kOff + h2 * 32;
    const __half* gB = B + (size_t)(n0 + r) * DMODEL + kOff + h2 * 32;

    const int aRow = wm * 64 + (lane & 15);
    const int bRow = wn * 32 + (lane & 15);
    const int kb   = (lane >> 4) << 4;

    const int NCH = kLen / 64;

#define LOAD_STAGE(kc, st)                                                  \
    do {                                                                    \
        const uint32_t base = sb + (uint32_t)(st) * STAGE_B;                \
        _Pragma("unroll")                                                   \
        for (int s = 0; s < 4; s++) {                                       \
            cp16(base + dofs[s],         gA + (kc) + s * 8);                \
            cp16(base + 16384 + dofs[s], gB + (kc) + s * 8);                \
        }                                                                   \
    } while (0)

    LOAD_STAGE(0, 0);
    cp_commit();

    for (int it = 0; it < NCH; it++) {
        if (it + 1 < NCH) {
            LOAD_STAGE((it + 1) * 64, (it + 1) & 1);
            cp_commit();
            cp_wait<1>();
        } else {
            cp_wait<0>();
        }
        __syncthreads();

        const uint32_t bA = sb + (uint32_t)(it & 1) * STAGE_B;
        const uint32_t bB = bA + 16384;

#pragma unroll
        for (int kk = 0; kk < 4; kk++) {
            const uint32_t kby = (uint32_t)(kk * 32 + kb);
            uint32_t ah[4][4];
#pragma unroll
            for (int mt = 0; mt < 4; mt++) {
                const uint32_t row = (uint32_t)(aRow + mt * 16) * 128;
                ldsm_x4(ah[mt], bA + SWZ128(row + kby));
            }
#pragma unroll
            for (int ntp = 0; ntp < 2; ntp++) {
                const uint32_t row = (uint32_t)(bRow + ntp * 16) * 128;
                uint32_t bb[4];
                ldsm_x4(bb, bB + SWZ128(row + kby));
#pragma unroll
                for (int half = 0; half < 2; half++) {
                    const int nt = ntp * 2 + half;
                    uint32_t bf[2] = {bb[half], bb[half + 2]};
#pragma unroll
                    for (int mt = 0; mt < 4; mt++)
                        mma_f16(acc[mt][nt], ah[mt], bf);
                }
            }
        }
        __syncthreads();
    }

    const int g  = lane >> 2;
    const int tg = lane & 3;
    if (C16) {
#pragma unroll
        for (int mt = 0; mt < 4; mt++) {
#pragma unroll
            for (int half = 0; half < 2; half++) {
                const int m = m0 + wm * 64 + mt * 16 + g + half * 8;
                __half* cp = C16 + (size_t)m * ldC + n0 + wn * 32;
#pragma unroll
                for (int nt = 0; nt < 4; nt++) {
                    const int col = nt * 8 + tg * 2;
                    *(uint32_t*)(cp + col) =
                        pack_hf2(acc[mt][nt][half * 2], acc[mt][nt][half * 2 + 1]);
                }
            }
        }
    } else {
        float* __restrict__ C = blockIdx.z ? C1 : C0;
#pragma unroll
        for (int mt = 0; mt < 4; mt++) {
#pragma unroll
            for (int half = 0; half < 2; half++) {
                const int m = m0 + wm * 64 + mt * 16 + g + half * 8;
                float* cp = C + (size_t)m * ldC + n0 + wn * 32;
#pragma unroll
                for (int nt = 0; nt < 4; nt++) {
                    const int col = nt * 8 + tg * 2;
                    *(float2*)(cp + col) =
                        make_float2(acc[mt][nt][half * 2], acc[mt][nt][half * 2 + 1]);
                }
            }
        }
    }
}

// =====================================================================
// RoPE: read fp16 q,k from g_qkv16; emit fp16 q (pre-scaled 1/8), k.
// =====================================================================
__global__ void __launch_bounds__(512) rope_kernel()
{
    const int s = blockIdx.x;
    const int h = threadIdx.x >> 5;
    const int j = threadIdx.x & 31;

    const float LOG2_1E4 = 13.28771237954945f;
    float inv = exp2f(-(float)j * (LOG2_1E4 / 32.0f));
    float ang = (float)s * inv;
    float sn, cs;
    sincosf(ang, &sn, &cs);

    const size_t base = (size_t)s * 3072 + h * 64;
    const __half* qk = g_qkv16 + base;

    float q0 = __half2float(qk[j]);
    float q1 = __half2float(qk[j + 32]);
    float k0 = __half2float(qk[1024 + j]);
    float k1 = __half2float(qk[1024 + j + 32]);

    const size_t o = (size_t)s * DMODEL + h * 64 + j;
    g_q[o]      = __float2half_rn((q0 * cs - q1 * sn) * 0.125f);
    g_q[o + 32] = __float2half_rn((q1 * cs + q0 * sn) * 0.125f);
    g_k[o]      = __float2half_rn(k0 * cs - k1 * sn);
    g_k[o + 32] = __float2half_rn(k1 * cs + k0 * sn);
}

// =====================================================================
// Windowed causal flash attention, FA2-style register softmax.
// grid = (NHEADS, S_LEN/128), 256 threads = 8 warps.
// Each warp owns 16 q-rows x ALL 64 keys of the chunk:
//   - softmax is warp-local (quad shuffles only)
//   - P converts in-register from S C-frags to PV A-frags (no smem)
// smem: Q 16KB + K 2x8KB + V 2x8KB = 48KB.
// =====================================================================
#define AQ  0u
#define AK0 16384u
#define AK1 24576u
#define AV0 32768u
#define AV1 40960u
#define ATT_SMEM 49152

__global__ void __launch_bounds__(256, 2) attn_kernel()
{
    extern __shared__ char sm[];
    const uint32_t sb = smem_u32(sm);

    const int h   = blockIdx.x;
    const int q0  = blockIdx.y * 128;
    const int tid = threadIdx.x;
    const int wid = tid >> 5, lane = tid & 31;
    const int g = lane >> 2, tg = lane & 3;
    const int wrow = wid * 16;

    // K/V tile loader: 64 rows x 128B, 4 threads/row, 2 x 16B each
    const int r4 = tid >> 2;
    const int s4 = (tid & 3) * 2;
    const uint32_t tdst0 = SWZ128((uint32_t)(r4 * 128 + s4 * 16));
    const uint32_t tdst1 = SWZ128((uint32_t)(r4 * 128 + s4 * 16 + 16));
#define ATL(dstbase, srcptr)                         \
    do {                                             \
        cp16((dstbase) + tdst0, (srcptr));           \
        cp16((dstbase) + tdst1, (srcptr) + 8);       \
    } while (0)

    // Q tile loader: 128 rows x 128B, 2 threads/row, 4 x 16B each
    const int rq = tid >> 1;
    const int hq = tid & 1;
    uint32_t qdofs[4];
#pragma unroll
    for (int s = 0; s < 4; s++)
        qdofs[s] = SWZ128((uint32_t)(rq * 128 + hq * 64 + s * 16));
    const __half* gQ = g_q + (size_t)(q0 + rq) * DMODEL + h * 64 + hq * 32;

    const int kstart = (q0 - WINDOW) < 0 ? 0 : (q0 - WINDOW);
    const int nch = (q0 + 128 - kstart) / 64;

    // prologue: Q + K0 + V0
#pragma unroll
    for (int s = 0; s < 4; s++)
        cp16(sb + AQ + qdofs[s], gQ + s * 8);
    ATL(sb + AK0, g_k + (size_t)(kstart + r4) * DMODEL + h * 64 + s4 * 8);
    ATL(sb + AV0, g_v + (size_t)(h * 64 + r4) * S_LEN + kstart + s4 * 8);
    cp_commit();

    float o[8][4];
#pragma unroll
    for (int nt = 0; nt < 8; nt++)
#pragma unroll
        for (int c = 0; c < 4; c++) o[nt][c] = 0.f;
    float m0_ = -1e30f, m1_ = -1e30f, l0_ = 0.f, l1_ = 0.f;

    const int aRow = wrow + (lane & 15);
    const int bR15 = lane & 15;
    const int kb   = (lane >> 4) << 4;
    const int qrow0 = q0 + wrow + g;       // this thread's first row
    const int qrow1 = qrow0 + 8;

    for (int it = 0; it < nch; it++) {
        const int kc = kstart + it * 64;
        const uint32_t KB = (it & 1) ? AK1 : AK0;
        const uint32_t VB = (it & 1) ? AV1 : AV0;
        const bool pf = (it + 1 < nch);

        cp_wait<0>();
        __syncthreads();
        if (pf) {
            const uint32_t KBn = (it & 1) ? AK0 : AK1;
            const uint32_t VBn = (it & 1) ? AV0 : AV1;
            ATL(sb + KBn, g_k + (size_t)(kc + 64 + r4) * DMODEL + h * 64 + s4 * 8);
            ATL(sb + VBn, g_v + (size_t)(h * 64 + r4) * S_LEN + kc + 64 + s4 * 8);
            cp_commit();
        }

        // ---- S = Q K^T : warp computes m16 x n64 ----
        float sacc[8][4];
#pragma unroll
        for (int nt = 0; nt < 8; nt++)
#pragma unroll
            for (int c = 0; c < 4; c++) sacc[nt][c] = 0.f;

#pragma unroll
        for (int kk = 0; kk < 4; kk++) {
            const uint32_t kby = (uint32_t)(kk * 32 + kb);
            uint32_t a[4];
            ldsm_x4(a, sb + AQ + SWZ128((uint32_t)aRow * 128 + kby));
#pragma unroll
            for (int ntp = 0; ntp < 4; ntp++) {
                uint32_t bb[4];
                ldsm_x4(bb, sb + KB + SWZ128((uint32_t)(ntp * 16 + bR15) * 128 + kby));
#pragma unroll
                for (int half = 0; half < 2; half++) {
                    uint32_t bf[2] = {bb[half], bb[half + 2]};
                    mma_f16(sacc[ntp * 2 + half], a, bf);
                }
            }
        }

        // ---- warp-local online softmax (rows qrow0, qrow1) ----
        float rmax0 = -1e30f, rmax1 = -1e30f;
#pragma unroll
        for (int nt = 0; nt < 8; nt++) {
            const int key0 = kc + nt * 8 + tg * 2;
            const int key1 = key0 + 1;
            const bool ok00 = (key0 <= qrow0) && (qrow0 - key0 <= WINDOW);
            const bool ok01 = (key1 <= qrow0) && (qrow0 - key1 <= WINDOW);
            const bool ok10 = (key0 <= qrow1) && (qrow1 - key0 <= WINDOW);
            const bool ok11 = (key1 <= qrow1) && (qrow1 - key1 <= WINDOW);
            sacc[nt][0] = ok00 ? sacc[nt][0] : -1e30f;
            sacc[nt][1] = ok01 ? sacc[nt][1] : -1e30f;
            sacc[nt][2] = ok10 ? sacc[nt][2] : -1e30f;
            sacc[nt][3] = ok11 ? sacc[nt][3] : -1e30f;
            rmax0 = fmaxf(rmax0, fmaxf(sacc[nt][0], sacc[nt][1]));
            rmax1 = fmaxf(rmax1, fmaxf(sacc[nt][2], sacc[nt][3]));
        }
        rmax0 = fmaxf(rmax0, __shfl_xor_sync(0xffffffffu, rmax0, 1));
        rmax0 = fmaxf(rmax0, __shfl_xor_sync(0xffffffffu, rmax0, 2));
        rmax1 = fmaxf(rmax1, __shfl_xor_sync(0xffffffffu, rmax1, 1));
        rmax1 = fmaxf(rmax1, __shfl_xor_sync(0xffffffffu, rmax1, 2));

        const float mn0 = fmaxf(m0_, rmax0);
        const float mn1 = fmaxf(m1_, rmax1);
        const float sc0 = __expf(m0_ - mn0);
        const float sc1 = __expf(m1_ - mn1);
        float rs0 = 0.f, rs1 = 0.f;
#pragma unroll
        for (int nt = 0; nt < 8; nt++) {
            sacc[nt][0] = __expf(sacc[nt][0] - mn0);
            sacc[nt][1] = __expf(sacc[nt][1] - mn0);
            sacc[nt][2] = __expf(sacc[nt][2] - mn1);
            sacc[nt][3] = __expf(sacc[nt][3] - mn1);
            rs0 += sacc[nt][0] + sacc[nt][1];
            rs1 += sacc[nt][2] + sacc[nt][3];
        }
        rs0 += __shfl_xor_sync(0xffffffffu, rs0, 1);
        rs0 += __shfl_xor_sync(0xffffffffu, rs0, 2);
        rs1 += __shfl_xor_sync(0xffffffffu, rs1, 1);
        rs1 += __shfl_xor_sync(0xffffffffu, rs1, 2);
        l0_ = l0_ * sc0 + rs0; m0_ = mn0;
        l1_ = l1_ * sc1 + rs1; m1_ = mn1;

        // rescale O
#pragma unroll
        for (int nt = 0; nt < 8; nt++) {
            o[nt][0] *= sc0; o[nt][1] *= sc0;
            o[nt][2] *= sc1; o[nt][3] *= sc1;
        }

        // ---- O += P V  (P in-register from sacc C-frags) ----
#pragma unroll
        for (int kk = 0; kk < 4; kk++) {
            uint32_t pa[4];
            pa[0] = pack_hf2(sacc[2 * kk][0],     sacc[2 * kk][1]);
            pa[1] = pack_hf2(sacc[2 * kk][2],     sacc[2 * kk][3]);
            pa[2] = pack_hf2(sacc[2 * kk + 1][0], sacc[2 * kk + 1][1]);
            pa[3] = pack_hf2(sacc[2 * kk + 1][2], sacc[2 * kk + 1][3]);
            const uint32_t kby = (uint32_t)(kk * 32 + kb);
#pragma unroll
            for (int ntp = 0; ntp < 4; ntp++) {
                uint32_t bb[4];
                ldsm_x4(bb, sb + VB + SWZ128((uint32_t)(ntp * 16 + bR15) * 128 + kby));
#pragma unroll
                for (int half = 0; half < 2; half++) {
                    uint32_t bf[2] = {bb[half], bb[half + 2]};
                    mma_f16(o[ntp * 2 + half], pa, bf);
                }
            }
        }
    }

    // ---- write O (fp16), rows qrow0/qrow1, cols h*64 + nt*8 + tg*2 ----
    const float iv0 = 1.f / l0_;
    const float iv1 = 1.f / l1_;
#pragma unroll
    for (int nt = 0; nt < 8; nt++) {
        const int col = h * 64 + nt * 8 + tg * 2;
        *(uint32_t*)(g_a16 + (size_t)qrow0 * DMODEL + col) =
            pack_hf2(o[nt][0] * iv0, o[nt][1] * iv0);
        *(uint32_t*)(g_a16 + (size_t)qrow1 * DMODEL + col) =
            pack_hf2(o[nt][2] * iv1, o[nt][3] * iv1);
    }
}

// =====================================================================
// LayerNorm with fused residual + split-K reduce:
//   res = x + o0 + o1 ; y = LN(res)*gamma + beta.  grid=S, block=256
// =====================================================================
__global__ void __launch_bounds__(256) ln_kernel(
    const float* __restrict__ x,
    const float* __restrict__ gamma, const float* __restrict__ beta,
    float* __restrict__ y)
{
    const int s = blockIdx.x;
    const int tid = threadIdx.x;
    const size_t base = (size_t)s * DMODEL + tid * 4;

    float4 xv = *(const float4*)(x + base);
    float4 a  = *(const float4*)(g_o0 + base);
    float4 b4 = *(const float4*)(g_o1 + base);
    xv.x += a.x + b4.x;
    xv.y += a.y + b4.y;
    xv.z += a.z + b4.z;
    xv.w += a.w + b4.w;

    float s1 = xv.x + xv.y + xv.z + xv.w;
    float s2 = xv.x * xv.x + xv.y * xv.y + xv.z * xv.z + xv.w * xv.w;
#pragma unroll
    for (int o = 16; o >= 1; o >>= 1) {
        s1 += __shfl_xor_sync(0xffffffffu, s1, o);
        s2 += __shfl_xor_sync(0xffffffffu, s2, o);
    }
    __shared__ float a1[8], a2[8];
    const int w = tid >> 5, lane = tid & 31;
    if (lane == 0) { a1[w] = s1; a2[w] = s2; }
    __syncthreads();
    float t1 = 0.f, t2 = 0.f;
#pragma unroll
    for (int i = 0; i < 8; i++) { t1 += a1[i]; t2 += a2[i]; }

    const float mu  = t1 * (1.0f / DMODEL);
    const float var = t2 * (1.0f / DMODEL) - mu * mu;
    const float rstd = rsqrtf(var + LN_EPS);

    const int c = tid * 4;
    float4 gm = *(const float4*)(gamma + c);
    float4 bt = *(const float4*)(beta + c);
    float4 o;
    o.x = (xv.x - mu) * rstd * gm.x + bt.x;
    o.y = (xv.y - mu) * rstd * gm.y + bt.y;
    o.z = (xv.z - mu) * rstd * gm.z + bt.z;
    o.w = (xv.w - mu) * rstd * gm.w + bt.w;
    *(float4*)(y + (size_t)s * DMODEL + c) = o;
}

// =====================================================================
// launch
// =====================================================================
extern "C" void kernel_launch(void* const* d_in, const int* in_sizes, int n_in,
                              void* d_out, int out_size)
{
    const float* x     = (const float*)d_in[0];
    const float* state = (const float*)d_in[1];
    const float* Wqkv  = (const float*)d_in[2];
    const float* Wout  = (const float*)d_in[3];
    const float* gamma = (const float*)d_in[4];
    const float* beta  = (const float*)d_in[5];
    float* y = (float*)d_out;

    float *o0, *o1;
    __half *qkv16, *x16, *a16, *wq, *wo;
    cudaGetSymbolAddress((void**)&o0,    g_o0);
    cudaGetSymbolAddress((void**)&o1,    g_o1);
    cudaGetSymbolAddress((void**)&qkv16, g_qkv16);
    cudaGetSymbolAddress((void**)&x16,   g_x16);
    cudaGetSymbolAddress((void**)&a16,   g_a16);
    cudaGetSymbolAddress((void**)&wq,    g_wq);
    cudaGetSymbolAddress((void**)&wo,    g_wo);

    cudaFuncSetAttribute(gemm_f16, cudaFuncAttributeMaxDynamicSharedMemorySize, GEMM_SMEM);
    cudaFuncSetAttribute(attn_kernel, cudaFuncAttributeMaxDynamicSharedMemorySize, ATT_SMEM);

    // 0) operand prep
    tofp16_kernel<<<512, 256>>>((const float4*)x, (uint2*)x16, S_LEN * DMODEL / 4);
    wsplit_kernel<<<dim3(3 * DMODEL / 32, DMODEL / 32), 256>>>(Wqkv, wq,
                                                               DMODEL, 3 * DMODEL);
    wsplit_kernel<<<dim3(DMODEL / 32, DMODEL / 32), 256>>>(Wout, wo,
                                                           DMODEL, DMODEL);

    // 1) QKV projection -> fp16 qkv (full K)
    gemm_f16<<<dim3(3 * DMODEL / 128, S_LEN / 128, 1), 256, GEMM_SMEM>>>(
        x16, wq, qkv16, nullptr, nullptr, 3 * DMODEL, DMODEL);

    // 2) RoPE -> q,k fp16 ; V transpose -> fp16
    rope_kernel<<<S_LEN, 512>>>();
    vsplit_kernel<<<dim3(DMODEL / 32, S_LEN / 32), 256>>>();

    // 3) windowed attention (FA2-style, fp16 tensor cores)
    attn_kernel<<<dim3(NHEADS, S_LEN / 128), 256, ATT_SMEM>>>();

    // 4) output projection, split-K=2 -> o0, o1
    gemm_f16<<<dim3(DMODEL / 128, S_LEN / 128, 2), 256, GEMM_SMEM>>>(
        a16, wo, nullptr, o0, o1, DMODEL, DMODEL / 2);

    // 5) LayerNorm (fused residual + split-K reduce) -> y
    ln_kernel<<<S_LEN, 256>>>(x, gamma, beta, y);

    // 6) pass-through state if the output buffer includes it
    if (out_size >= S_LEN * DMODEL + DMODEL) {
        cudaMemcpyAsync(y + (size_t)S_LEN * DMODEL, state,
                        DMODEL * sizeof(float), cudaMemcpyDeviceToDevice);
    }
}

// round 15
// speedup vs baseline: 4.5918x; 1.0505x over previous
#include <cuda_runtime.h>
#include <cuda_fp16.h>
#include <math.h>
#include <stdint.h>

#define S_LEN   2048
#define DMODEL  1024
#define NHEADS  16
#define WINDOW  256
#define LN_EPS  1e-5f

// ---------------- scratch (no allocations allowed) ----------------
__device__ float  g_o0[(size_t)S_LEN * DMODEL];        // out-proj partial 0
__device__ float  g_o1[(size_t)S_LEN * DMODEL];        // out-proj partial 1
__device__ __half g_qkv16[(size_t)S_LEN * 3 * DMODEL]; // QKV GEMM out (fp16)

// single fp16 operands
__device__ __half g_x16[(size_t)S_LEN * DMODEL];      // x fp16
__device__ __half g_a16[(size_t)S_LEN * DMODEL];      // attention out fp16
__device__ __half g_wq[(size_t)3 * DMODEL * DMODEL];  // W_qkv^T [3072,1024]
__device__ __half g_wo[(size_t)DMODEL * DMODEL];      // W_out^T [1024,1024]

// attention operands
__device__ __half g_q[(size_t)S_LEN * DMODEL];   // q (pre-scaled 1/8, roped)
__device__ __half g_k[(size_t)S_LEN * DMODEL];   // k (roped)
__device__ __half g_v[(size_t)DMODEL * S_LEN];   // V^T: [h*64+d][s]

// =====================================================================
// warp-level tensor-core helpers (sm_80+ baseline)
// =====================================================================
__device__ __forceinline__ uint32_t smem_u32(const void* p) {
    uint32_t a;
    asm("{ .reg .u64 t; cvta.to.shared.u64 t, %1; cvt.u32.u64 %0, t; }" : "=r"(a) : "l"(p));
    return a;
}
__device__ __forceinline__ void ldsm_x4(uint32_t* r, uint32_t addr) {
    asm volatile("ldmatrix.sync.aligned.m8n8.x4.shared.b16 {%0,%1,%2,%3}, [%4];"
                 : "=r"(r[0]), "=r"(r[1]), "=r"(r[2]), "=r"(r[3]) : "r"(addr));
}
__device__ __forceinline__ void mma_f16(float* d, const uint32_t* a, const uint32_t* b) {
    asm volatile(
        "mma.sync.aligned.m16n8k16.row.col.f32.f16.f16.f32 "
        "{%0,%1,%2,%3}, {%4,%5,%6,%7}, {%8,%9}, {%0,%1,%2,%3};"
        : "+f"(d[0]), "+f"(d[1]), "+f"(d[2]), "+f"(d[3])
        : "r"(a[0]), "r"(a[1]), "r"(a[2]), "r"(a[3]), "r"(b[0]), "r"(b[1]));
}
__device__ __forceinline__ void cp16(uint32_t dst, const void* src) {
    asm volatile("cp.async.cg.shared.global [%0], [%1], 16;" :: "r"(dst), "l"(src));
}
__device__ __forceinline__ void cp_commit() {
    asm volatile("cp.async.commit_group;" ::: "memory");
}
template <int N>
__device__ __forceinline__ void cp_wait() {
    asm volatile("cp.async.wait_group %0;" :: "n"(N) : "memory");
}

#define SWZ128(bo) ((bo) ^ (((bo) >> 3) & 0x70))

__device__ __forceinline__ uint32_t pack_hf2(float a, float b) {
    __half2 p = {__float2half_rn(a), __float2half_rn(b)};
    return *(uint32_t*)&p;
}

// =====================================================================
// FUSED prep: [0,3072)   Wqkv transpose -> g_wq
//             [3072,4096) Wout transpose -> g_wo
//             [4096,4608) x -> fp16
// =====================================================================
__device__ __forceinline__ void wtrans_body(
    const float* __restrict__ W, __half* __restrict__ out,
    int K, int N, int bn, int bk)
{
    __shared__ float t[32][33];
    const int tx = threadIdx.x & 31;
    const int ty = threadIdx.x >> 5;
#pragma unroll
    for (int i = 0; i < 32; i += 8)
        t[ty + i][tx] = W[(size_t)(bk + ty + i) * N + bn + tx];
    __syncthreads();
#pragma unroll
    for (int i = 0; i < 32; i += 8)
        out[(size_t)(bn + ty + i) * K + bk + tx] = __float2half_rn(t[tx][ty + i]);
}

__global__ void __launch_bounds__(256) prep_kernel(
    const float* __restrict__ x, const float* __restrict__ Wqkv,
    const float* __restrict__ Wout)
{
    const int b = blockIdx.x;
    if (b < 3072) {
        // Wqkv: old grid (96, 32) -> bn = (b % 96)*32, bk = (b / 96)*32
        wtrans_body(Wqkv, g_wq, DMODEL, 3 * DMODEL, (b % 96) * 32, (b / 96) * 32);
    } else if (b < 4096) {
        const int i2 = b - 3072;   // old grid (32, 32)
        wtrans_body(Wout, g_wo, DMODEL, DMODEL, (i2 % 32) * 32, (i2 / 32) * 32);
    } else {
        const int i3 = b - 4096;   // 512 blocks, grid-stride over n4
        const int n4 = S_LEN * DMODEL / 4;
        const float4* in = (const float4*)x;
        uint2* out = (uint2*)g_x16;
        for (int i = i3 * 256 + threadIdx.x; i < n4; i += 512 * 256) {
            float4 v = in[i];
            out[i] = make_uint2(pack_hf2(v.x, v.y), pack_hf2(v.z, v.w));
        }
    }
}

// =====================================================================
// FUSED rope + V transpose:
//   [0,4096)    RoPE: s = b>>1, heads (b&1)*8 .. +8 (256 thr = 8 warps)
//   [4096,6144) V transpose: g_qkv16 v [s][c] -> g_v [c][s]
// =====================================================================
__global__ void __launch_bounds__(256) ropev_kernel()
{
    const int b = blockIdx.x;
    if (b < 4096) {
        const int s = b >> 1;
        const int h = (b & 1) * 8 + (threadIdx.x >> 5);
        const int j = threadIdx.x & 31;

        const float LOG2_1E4 = 13.28771237954945f;
        float inv = exp2f(-(float)j * (LOG2_1E4 / 32.0f));
        float ang = (float)s * inv;
        float sn, cs;
        sincosf(ang, &sn, &cs);

        const size_t base = (size_t)s * 3072 + h * 64;
        const __half* qk = g_qkv16 + base;

        float q0 = __half2float(qk[j]);
        float q1 = __half2float(qk[j + 32]);
        float k0 = __half2float(qk[1024 + j]);
        float k1 = __half2float(qk[1024 + j + 32]);

        const size_t o = (size_t)s * DMODEL + h * 64 + j;
        g_q[o]      = __float2half_rn((q0 * cs - q1 * sn) * 0.125f);
        g_q[o + 32] = __float2half_rn((q1 * cs + q0 * sn) * 0.125f);
        g_k[o]      = __float2half_rn(k0 * cs - k1 * sn);
        g_k[o + 32] = __float2half_rn(k1 * cs + k0 * sn);
    } else {
        __shared__ __half t[32][34];
        const int i2 = b - 4096;            // old grid (32, 64): x = c-blk, y = s-blk
        const int c0 = (i2 % 32) * 32;
        const int s0 = (i2 / 32) * 32;
        const int tx = threadIdx.x & 31;
        const int ty = threadIdx.x >> 5;
#pragma unroll
        for (int i = 0; i < 32; i += 8)
            t[ty + i][tx] = g_qkv16[(size_t)(s0 + ty + i) * 3072 + 2048 + c0 + tx];
        __syncthreads();
#pragma unroll
        for (int i = 0; i < 32; i += 8)
            g_v[(size_t)(c0 + ty + i) * S_LEN + s0 + tx] = t[tx][ty + i];
    }
}

// =====================================================================
// single-fp16 tensor-core GEMM.
// CTA 128x128, K-chunk 64, 2-stage cp.async.
// QKV mode: kLen=1024, gridDim.z=1, C16 output.
// Out-proj mode: kLen=512, gridDim.z=2 (split-K), fp32 C0/C1 partials.
// =====================================================================
#define STAGE_B 32768
#define GEMM_SMEM (2 * STAGE_B)

__global__ void __launch_bounds__(256, 2) gemm_f16(
    const __half* __restrict__ A, const __half* __restrict__ B,
    __half* __restrict__ C16, float* __restrict__ C0, float* __restrict__ C1,
    int ldC, int kLen)
{
    extern __shared__ char smem[];
    const uint32_t sb = smem_u32(smem);

    const int tid  = threadIdx.x;
    const int wid  = tid >> 5;
    const int lane = tid & 31;
    const int wm   = wid & 1;
    const int wn   = wid >> 1;
    const int m0 = blockIdx.y * 128;
    const int n0 = blockIdx.x * 128;
    const int kOff = blockIdx.z * kLen;

    float acc[4][4][4];
#pragma unroll
    for (int i = 0; i < 4; i++)
#pragma unroll
        for (int j = 0; j < 4; j++)
#pragma unroll
            for (int c = 0; c < 4; c++) acc[i][j][c] = 0.f;

    const int r  = tid >> 1;
    const int h2 = tid & 1;
    uint32_t dofs[4];
#pragma unroll
    for (int s = 0; s < 4; s++)
        dofs[s] = SWZ128((uint32_t)(r * 128 + h2 * 64 + s * 16));
    const __half* gA = A + (size_t)(m0 + r) * DMODEL + kOff + h2 * 32;
    const __half* gB = B + (size_t)(n0 + r) * DMODEL + kOff + h2 * 32;

    const int aRow = wm * 64 + (lane & 15);
    const int bRow = wn * 32 + (lane & 15);
    const int kb   = (lane >> 4) << 4;

    const int NCH = kLen / 64;

#define LOAD_STAGE(kc, st)                                                  \
    do {                                                                    \
        const uint32_t base = sb + (uint32_t)(st) * STAGE_B;                \
        _Pragma("unroll")                                                   \
        for (int s = 0; s < 4; s++) {                                       \
            cp16(base + dofs[s],         gA + (kc) + s * 8);                \
            cp16(base + 16384 + dofs[s], gB + (kc) + s * 8);                \
        }                                                                   \
    } while (0)

    LOAD_STAGE(0, 0);
    cp_commit();

    for (int it = 0; it < NCH; it++) {
        if (it + 1 < NCH) {
            LOAD_STAGE((it + 1) * 64, (it + 1) & 1);
            cp_commit();
            cp_wait<1>();
        } else {
            cp_wait<0>();
        }
        __syncthreads();

        const uint32_t bA = sb + (uint32_t)(it & 1) * STAGE_B;
        const uint32_t bB = bA + 16384;

#pragma unroll
        for (int kk = 0; kk < 4; kk++) {
            const uint32_t kby = (uint32_t)(kk * 32 + kb);
            uint32_t ah[4][4];
#pragma unroll
            for (int mt = 0; mt < 4; mt++) {
                const uint32_t row = (uint32_t)(aRow + mt * 16) * 128;
                ldsm_x4(ah[mt], bA + SWZ128(row + kby));
            }
#pragma unroll
            for (int ntp = 0; ntp < 2; ntp++) {
                const uint32_t row = (uint32_t)(bRow + ntp * 16) * 128;
                uint32_t bb[4];
                ldsm_x4(bb, bB + SWZ128(row + kby));
#pragma unroll
                for (int half = 0; half < 2; half++) {
                    const int nt = ntp * 2 + half;
                    uint32_t bf[2] = {bb[half], bb[half + 2]};
#pragma unroll
                    for (int mt = 0; mt < 4; mt++)
                        mma_f16(acc[mt][nt], ah[mt], bf);
                }
            }
        }
        __syncthreads();
    }

    const int g  = lane >> 2;
    const int tg = lane & 3;
    if (C16) {
#pragma unroll
        for (int mt = 0; mt < 4; mt++) {
#pragma unroll
            for (int half = 0; half < 2; half++) {
                const int m = m0 + wm * 64 + mt * 16 + g + half * 8;
                __half* cp = C16 + (size_t)m * ldC + n0 + wn * 32;
#pragma unroll
                for (int nt = 0; nt < 4; nt++) {
                    const int col = nt * 8 + tg * 2;
                    *(uint32_t*)(cp + col) =
                        pack_hf2(acc[mt][nt][half * 2], acc[mt][nt][half * 2 + 1]);
                }
            }
        }
    } else {
        float* __restrict__ C = blockIdx.z ? C1 : C0;
#pragma unroll
        for (int mt = 0; mt < 4; mt++) {
#pragma unroll
            for (int half = 0; half < 2; half++) {
                const int m = m0 + wm * 64 + mt * 16 + g + half * 8;
                float* cp = C + (size_t)m * ldC + n0 + wn * 32;
#pragma unroll
                for (int nt = 0; nt < 4; nt++) {
                    const int col = nt * 8 + tg * 2;
                    *(float2*)(cp + col) =
                        make_float2(acc[mt][nt][half * 2], acc[mt][nt][half * 2 + 1]);
                }
            }
        }
    }
}

// =====================================================================
// Windowed causal flash attention, FA2-style register softmax.
// grid = (NHEADS, S_LEN/128), 256 threads = 8 warps.
// =====================================================================
#define AQ  0u
#define AK0 16384u
#define AK1 24576u
#define AV0 32768u
#define AV1 40960u
#define ATT_SMEM 49152

__global__ void __launch_bounds__(256, 2) attn_kernel()
{
    extern __shared__ char sm[];
    const uint32_t sb = smem_u32(sm);

    const int h   = blockIdx.x;
    const int q0  = blockIdx.y * 128;
    const int tid = threadIdx.x;
    const int wid = tid >> 5, lane = tid & 31;
    const int g = lane >> 2, tg = lane & 3;
    const int wrow = wid * 16;

    const int r4 = tid >> 2;
    const int s4 = (tid & 3) * 2;
    const uint32_t tdst0 = SWZ128((uint32_t)(r4 * 128 + s4 * 16));
    const uint32_t tdst1 = SWZ128((uint32_t)(r4 * 128 + s4 * 16 + 16));
#define ATL(dstbase, srcptr)                         \
    do {                                             \
        cp16((dstbase) + tdst0, (srcptr));           \
        cp16((dstbase) + tdst1, (srcptr) + 8);       \
    } while (0)

    const int rq = tid >> 1;
    const int hq = tid & 1;
    uint32_t qdofs[4];
#pragma unroll
    for (int s = 0; s < 4; s++)
        qdofs[s] = SWZ128((uint32_t)(rq * 128 + hq * 64 + s * 16));
    const __half* gQ = g_q + (size_t)(q0 + rq) * DMODEL + h * 64 + hq * 32;

    const int kstart = (q0 - WINDOW) < 0 ? 0 : (q0 - WINDOW);
    const int nch = (q0 + 128 - kstart) / 64;

#pragma unroll
    for (int s = 0; s < 4; s++)
        cp16(sb + AQ + qdofs[s], gQ + s * 8);
    ATL(sb + AK0, g_k + (size_t)(kstart + r4) * DMODEL + h * 64 + s4 * 8);
    ATL(sb + AV0, g_v + (size_t)(h * 64 + r4) * S_LEN + kstart + s4 * 8);
    cp_commit();

    float o[8][4];
#pragma unroll
    for (int nt = 0; nt < 8; nt++)
#pragma unroll
        for (int c = 0; c < 4; c++) o[nt][c] = 0.f;
    float m0_ = -1e30f, m1_ = -1e30f, l0_ = 0.f, l1_ = 0.f;

    const int aRow = wrow + (lane & 15);
    const int bR15 = lane & 15;
    const int kb   = (lane >> 4) << 4;
    const int qrow0 = q0 + wrow + g;
    const int qrow1 = qrow0 + 8;

    for (int it = 0; it < nch; it++) {
        const int kc = kstart + it * 64;
        const uint32_t KB = (it & 1) ? AK1 : AK0;
        const uint32_t VB = (it & 1) ? AV1 : AV0;
        const bool pf = (it + 1 < nch);

        cp_wait<0>();
        __syncthreads();
        if (pf) {
            const uint32_t KBn = (it & 1) ? AK0 : AK1;
            const uint32_t VBn = (it & 1) ? AV0 : AV1;
            ATL(sb + KBn, g_k + (size_t)(kc + 64 + r4) * DMODEL + h * 64 + s4 * 8);
            ATL(sb + VBn, g_v + (size_t)(h * 64 + r4) * S_LEN + kc + 64 + s4 * 8);
            cp_commit();
        }

        // ---- S = Q K^T ----
        float sacc[8][4];
#pragma unroll
        for (int nt = 0; nt < 8; nt++)
#pragma unroll
            for (int c = 0; c < 4; c++) sacc[nt][c] = 0.f;

#pragma unroll
        for (int kk = 0; kk < 4; kk++) {
            const uint32_t kby = (uint32_t)(kk * 32 + kb);
            uint32_t a[4];
            ldsm_x4(a, sb + AQ + SWZ128((uint32_t)aRow * 128 + kby));
#pragma unroll
            for (int ntp = 0; ntp < 4; ntp++) {
                uint32_t bb[4];
                ldsm_x4(bb, sb + KB + SWZ128((uint32_t)(ntp * 16 + bR15) * 128 + kby));
#pragma unroll
                for (int half = 0; half < 2; half++) {
                    uint32_t bf[2] = {bb[half], bb[half + 2]};
                    mma_f16(sacc[ntp * 2 + half], a, bf);
                }
            }
        }

        // ---- warp-local online softmax ----
        float rmax0 = -1e30f, rmax1 = -1e30f;
#pragma unroll
        for (int nt = 0; nt < 8; nt++) {
            const int key0 = kc + nt * 8 + tg * 2;
            const int key1 = key0 + 1;
            const bool ok00 = (key0 <= qrow0) && (qrow0 - key0 <= WINDOW);
            const bool ok01 = (key1 <= qrow0) && (qrow0 - key1 <= WINDOW);
            const bool ok10 = (key0 <= qrow1) && (qrow1 - key0 <= WINDOW);
            const bool ok11 = (key1 <= qrow1) && (qrow1 - key1 <= WINDOW);
            sacc[nt][0] = ok00 ? sacc[nt][0] : -1e30f;
            sacc[nt][1] = ok01 ? sacc[nt][1] : -1e30f;
            sacc[nt][2] = ok10 ? sacc[nt][2] : -1e30f;
            sacc[nt][3] = ok11 ? sacc[nt][3] : -1e30f;
            rmax0 = fmaxf(rmax0, fmaxf(sacc[nt][0], sacc[nt][1]));
            rmax1 = fmaxf(rmax1, fmaxf(sacc[nt][2], sacc[nt][3]));
        }
        rmax0 = fmaxf(rmax0, __shfl_xor_sync(0xffffffffu, rmax0, 1));
        rmax0 = fmaxf(rmax0, __shfl_xor_sync(0xffffffffu, rmax0, 2));
        rmax1 = fmaxf(rmax1, __shfl_xor_sync(0xffffffffu, rmax1, 1));
        rmax1 = fmaxf(rmax1, __shfl_xor_sync(0xffffffffu, rmax1, 2));

        const float mn0 = fmaxf(m0_, rmax0);
        const float mn1 = fmaxf(m1_, rmax1);
        const float sc0 = __expf(m0_ - mn0);
        const float sc1 = __expf(m1_ - mn1);
        float rs0 = 0.f, rs1 = 0.f;
#pragma unroll
        for (int nt = 0; nt < 8; nt++) {
            sacc[nt][0] = __expf(sacc[nt][0] - mn0);
            sacc[nt][1] = __expf(sacc[nt][1] - mn0);
            sacc[nt][2] = __expf(sacc[nt][2] - mn1);
            sacc[nt][3] = __expf(sacc[nt][3] - mn1);
            rs0 += sacc[nt][0] + sacc[nt][1];
            rs1 += sacc[nt][2] + sacc[nt][3];
        }
        rs0 += __shfl_xor_sync(0xffffffffu, rs0, 1);
        rs0 += __shfl_xor_sync(0xffffffffu, rs0, 2);
        rs1 += __shfl_xor_sync(0xffffffffu, rs1, 1);
        rs1 += __shfl_xor_sync(0xffffffffu, rs1, 2);
        l0_ = l0_ * sc0 + rs0; m0_ = mn0;
        l1_ = l1_ * sc1 + rs1; m1_ = mn1;

#pragma unroll
        for (int nt = 0; nt < 8; nt++) {
            o[nt][0] *= sc0; o[nt][1] *= sc0;
            o[nt][2] *= sc1; o[nt][3] *= sc1;
        }

        // ---- O += P V ----
#pragma unroll
        for (int kk = 0; kk < 4; kk++) {
            uint32_t pa[4];
            pa[0] = pack_hf2(sacc[2 * kk][0],     sacc[2 * kk][1]);
            pa[1] = pack_hf2(sacc[2 * kk][2],     sacc[2 * kk][3]);
            pa[2] = pack_hf2(sacc[2 * kk + 1][0], sacc[2 * kk + 1][1]);
            pa[3] = pack_hf2(sacc[2 * kk + 1][2], sacc[2 * kk + 1][3]);
            const uint32_t kby = (uint32_t)(kk * 32 + kb);
#pragma unroll
            for (int ntp = 0; ntp < 4; ntp++) {
                uint32_t bb[4];
                ldsm_x4(bb, sb + VB + SWZ128((uint32_t)(ntp * 16 + bR15) * 128 + kby));
#pragma unroll
                for (int half = 0; half < 2; half++) {
                    uint32_t bf[2] = {bb[half], bb[half + 2]};
                    mma_f16(o[ntp * 2 + half], pa, bf);
                }
            }
        }
    }

    const float iv0 = 1.f / l0_;
    const float iv1 = 1.f / l1_;
#pragma unroll
    for (int nt = 0; nt < 8; nt++) {
        const int col = h * 64 + nt * 8 + tg * 2;
        *(uint32_t*)(g_a16 + (size_t)qrow0 * DMODEL + col) =
            pack_hf2(o[nt][0] * iv0, o[nt][1] * iv0);
        *(uint32_t*)(g_a16 + (size_t)qrow1 * DMODEL + col) =
            pack_hf2(o[nt][2] * iv1, o[nt][3] * iv1);
    }
}

// =====================================================================
// LayerNorm with fused residual + split-K reduce
// =====================================================================
__global__ void __launch_bounds__(256) ln_kernel(
    const float* __restrict__ x,
    const float* __restrict__ gamma, const float* __restrict__ beta,
    float* __restrict__ y)
{
    const int s = blockIdx.x;
    const int tid = threadIdx.x;
    const size_t base = (size_t)s * DMODEL + tid * 4;

    float4 xv = *(const float4*)(x + base);
    float4 a  = *(const float4*)(g_o0 + base);
    float4 b4 = *(const float4*)(g_o1 + base);
    xv.x += a.x + b4.x;
    xv.y += a.y + b4.y;
    xv.z += a.z + b4.z;
    xv.w += a.w + b4.w;

    float s1 = xv.x + xv.y + xv.z + xv.w;
    float s2 = xv.x * xv.x + xv.y * xv.y + xv.z * xv.z + xv.w * xv.w;
#pragma unroll
    for (int o = 16; o >= 1; o >>= 1) {
        s1 += __shfl_xor_sync(0xffffffffu, s1, o);
        s2 += __shfl_xor_sync(0xffffffffu, s2, o);
    }
    __shared__ float a1[8], a2[8];
    const int w = tid >> 5, lane = tid & 31;
    if (lane == 0) { a1[w] = s1; a2[w] = s2; }
    __syncthreads();
    float t1 = 0.f, t2 = 0.f;
#pragma unroll
    for (int i = 0; i < 8; i++) { t1 += a1[i]; t2 += a2[i]; }

    const float mu  = t1 * (1.0f / DMODEL);
    const float var = t2 * (1.0f / DMODEL) - mu * mu;
    const float rstd = rsqrtf(var + LN_EPS);

    const int c = tid * 4;
    float4 gm = *(const float4*)(gamma + c);
    float4 bt = *(const float4*)(beta + c);
    float4 o;
    o.x = (xv.x - mu) * rstd * gm.x + bt.x;
    o.y = (xv.y - mu) * rstd * gm.y + bt.y;
    o.z = (xv.z - mu) * rstd * gm.z + bt.z;
    o.w = (xv.w - mu) * rstd * gm.w + bt.w;
    *(float4*)(y + (size_t)s * DMODEL + c) = o;
}

// =====================================================================
// launch — single stream, fused prep kernels (no stream/event objects)
// =====================================================================
extern "C" void kernel_launch(void* const* d_in, const int* in_sizes, int n_in,
                              void* d_out, int out_size)
{
    const float* x     = (const float*)d_in[0];
    const float* state = (const float*)d_in[1];
    const float* Wqkv  = (const float*)d_in[2];
    const float* Wout  = (const float*)d_in[3];
    const float* gamma = (const float*)d_in[4];
    const float* beta  = (const float*)d_in[5];
    float* y = (float*)d_out;

    float *o0, *o1;
    __half *qkv16, *x16, *a16, *wq, *wo;
    cudaGetSymbolAddress((void**)&o0,    g_o0);
    cudaGetSymbolAddress((void**)&o1,    g_o1);
    cudaGetSymbolAddress((void**)&qkv16, g_qkv16);
    cudaGetSymbolAddress((void**)&x16,   g_x16);
    cudaGetSymbolAddress((void**)&a16,   g_a16);
    cudaGetSymbolAddress((void**)&wq,    g_wq);
    cudaGetSymbolAddress((void**)&wo,    g_wo);

    cudaFuncSetAttribute(gemm_f16, cudaFuncAttributeMaxDynamicSharedMemorySize, GEMM_SMEM);
    cudaFuncSetAttribute(attn_kernel, cudaFuncAttributeMaxDynamicSharedMemorySize, ATT_SMEM);

    // 0) fused prep: Wqkv^T + Wout^T + x->fp16, one launch
    prep_kernel<<<4608, 256>>>(x, Wqkv, Wout);

    // 1) QKV projection -> fp16 qkv (full K)
    gemm_f16<<<dim3(3 * DMODEL / 128, S_LEN / 128, 1), 256, GEMM_SMEM>>>(
        x16, wq, qkv16, nullptr, nullptr, 3 * DMODEL, DMODEL);

    // 2) fused RoPE + V transpose, one launch
    ropev_kernel<<<6144, 256>>>();

    // 3) windowed attention (FA2-style, fp16 tensor cores)
    attn_kernel<<<dim3(NHEADS, S_LEN / 128), 256, ATT_SMEM>>>();

    // 4) output projection, split-K=2 -> o0, o1
    gemm_f16<<<dim3(DMODEL / 128, S_LEN / 128, 2), 256, GEMM_SMEM>>>(
        a16, wo, nullptr, o0, o1, DMODEL, DMODEL / 2);

    // 5) LayerNorm (fused residual + split-K reduce) -> y
    ln_kernel<<<S_LEN, 256>>>(x, gamma, beta, y);

    // 6) pass-through state if the output buffer includes it
    if (out_size >= S_LEN * DMODEL + DMODEL) {
        cudaMemcpyAsync(y + (size_t)S_LEN * DMODEL, state,
                        DMODEL * sizeof(float), cudaMemcpyDeviceToDevice);
    }
}

// round 16
// speedup vs baseline: 4.6106x; 1.0041x over previous
#include <cuda_runtime.h>
#include <cuda_fp16.h>
#include <math.h>
#include <stdint.h>

#define S_LEN   2048
#define DMODEL  1024
#define NHEADS  16
#define WINDOW  256
#define LN_EPS  1e-5f

// ---------------- scratch (no allocations allowed) ----------------
__device__ float  g_o0[(size_t)S_LEN * DMODEL];        // out-proj partial 0
__device__ float  g_o1[(size_t)S_LEN * DMODEL];        // out-proj partial 1
__device__ __half g_qkv16[(size_t)S_LEN * 3 * DMODEL]; // QKV GEMM out (fp16)

// single fp16 operands
__device__ __half g_x16[(size_t)S_LEN * DMODEL];      // x fp16
__device__ __half g_a16[(size_t)S_LEN * DMODEL];      // attention out fp16
__device__ __half g_wq[(size_t)3 * DMODEL * DMODEL];  // W_qkv^T [3072,1024]
__device__ __half g_wo[(size_t)DMODEL * DMODEL];      // W_out^T [1024,1024]

// attention operands
__device__ __half g_q[(size_t)S_LEN * DMODEL];   // q (pre-scaled 1/8, roped)
__device__ __half g_k[(size_t)S_LEN * DMODEL];   // k (roped)
__device__ __half g_v[(size_t)DMODEL * S_LEN];   // V^T: [h*64+d][s]

// =====================================================================
// warp-level tensor-core helpers (sm_80+ baseline)
// =====================================================================
__device__ __forceinline__ uint32_t smem_u32(const void* p) {
    uint32_t a;
    asm("{ .reg .u64 t; cvta.to.shared.u64 t, %1; cvt.u32.u64 %0, t; }" : "=r"(a) : "l"(p));
    return a;
}
__device__ __forceinline__ void ldsm_x4(uint32_t* r, uint32_t addr) {
    asm volatile("ldmatrix.sync.aligned.m8n8.x4.shared.b16 {%0,%1,%2,%3}, [%4];"
                 : "=r"(r[0]), "=r"(r[1]), "=r"(r[2]), "=r"(r[3]) : "r"(addr));
}
__device__ __forceinline__ void mma_f16(float* d, const uint32_t* a, const uint32_t* b) {
    asm volatile(
        "mma.sync.aligned.m16n8k16.row.col.f32.f16.f16.f32 "
        "{%0,%1,%2,%3}, {%4,%5,%6,%7}, {%8,%9}, {%0,%1,%2,%3};"
        : "+f"(d[0]), "+f"(d[1]), "+f"(d[2]), "+f"(d[3])
        : "r"(a[0]), "r"(a[1]), "r"(a[2]), "r"(a[3]), "r"(b[0]), "r"(b[1]));
}
__device__ __forceinline__ void cp16(uint32_t dst, const void* src) {
    asm volatile("cp.async.cg.shared.global [%0], [%1], 16;" :: "r"(dst), "l"(src));
}
__device__ __forceinline__ void cp_commit() {
    asm volatile("cp.async.commit_group;" ::: "memory");
}
template <int N>
__device__ __forceinline__ void cp_wait() {
    asm volatile("cp.async.wait_group %0;" :: "n"(N) : "memory");
}

#define SWZ128(bo) ((bo) ^ (((bo) >> 3) & 0x70))

__device__ __forceinline__ uint32_t pack_hf2(float a, float b) {
    __half2 p = {__float2half_rn(a), __float2half_rn(b)};
    return *(uint32_t*)&p;
}

// =====================================================================
// FUSED prep: [0,3072)   Wqkv transpose -> g_wq
//             [3072,4096) Wout transpose -> g_wo
//             [4096,4608) x -> fp16
// =====================================================================
__device__ __forceinline__ void wtrans_body(
    const float* __restrict__ W, __half* __restrict__ out,
    int K, int N, int bn, int bk)
{
    __shared__ float t[32][33];
    const int tx = threadIdx.x & 31;
    const int ty = threadIdx.x >> 5;
#pragma unroll
    for (int i = 0; i < 32; i += 8)
        t[ty + i][tx] = W[(size_t)(bk + ty + i) * N + bn + tx];
    __syncthreads();
#pragma unroll
    for (int i = 0; i < 32; i += 8)
        out[(size_t)(bn + ty + i) * K + bk + tx] = __float2half_rn(t[tx][ty + i]);
}

__global__ void __launch_bounds__(256) prep_kernel(
    const float* __restrict__ x, const float* __restrict__ Wqkv,
    const float* __restrict__ Wout)
{
    const int b = blockIdx.x;
    if (b < 3072) {
        wtrans_body(Wqkv, g_wq, DMODEL, 3 * DMODEL, (b % 96) * 32, (b / 96) * 32);
    } else if (b < 4096) {
        const int i2 = b - 3072;
        wtrans_body(Wout, g_wo, DMODEL, DMODEL, (i2 % 32) * 32, (i2 / 32) * 32);
    } else {
        const int i3 = b - 4096;
        const int n4 = S_LEN * DMODEL / 4;
        const float4* in = (const float4*)x;
        uint2* out = (uint2*)g_x16;
        for (int i = i3 * 256 + threadIdx.x; i < n4; i += 512 * 256) {
            float4 v = in[i];
            out[i] = make_uint2(pack_hf2(v.x, v.y), pack_hf2(v.z, v.w));
        }
    }
}

// =====================================================================
// FUSED rope + V transpose
// =====================================================================
__global__ void __launch_bounds__(256) ropev_kernel()
{
    const int b = blockIdx.x;
    if (b < 4096) {
        const int s = b >> 1;
        const int h = (b & 1) * 8 + (threadIdx.x >> 5);
        const int j = threadIdx.x & 31;

        const float LOG2_1E4 = 13.28771237954945f;
        float inv = exp2f(-(float)j * (LOG2_1E4 / 32.0f));
        float ang = (float)s * inv;
        float sn, cs;
        sincosf(ang, &sn, &cs);

        const size_t base = (size_t)s * 3072 + h * 64;
        const __half* qk = g_qkv16 + base;

        float q0 = __half2float(qk[j]);
        float q1 = __half2float(qk[j + 32]);
        float k0 = __half2float(qk[1024 + j]);
        float k1 = __half2float(qk[1024 + j + 32]);

        const size_t o = (size_t)s * DMODEL + h * 64 + j;
        g_q[o]      = __float2half_rn((q0 * cs - q1 * sn) * 0.125f);
        g_q[o + 32] = __float2half_rn((q1 * cs + q0 * sn) * 0.125f);
        g_k[o]      = __float2half_rn(k0 * cs - k1 * sn);
        g_k[o + 32] = __float2half_rn(k1 * cs + k0 * sn);
    } else {
        __shared__ __half t[32][34];
        const int i2 = b - 4096;
        const int c0 = (i2 % 32) * 32;
        const int s0 = (i2 / 32) * 32;
        const int tx = threadIdx.x & 31;
        const int ty = threadIdx.x >> 5;
#pragma unroll
        for (int i = 0; i < 32; i += 8)
            t[ty + i][tx] = g_qkv16[(size_t)(s0 + ty + i) * 3072 + 2048 + c0 + tx];
        __syncthreads();
#pragma unroll
        for (int i = 0; i < 32; i += 8)
            g_v[(size_t)(c0 + ty + i) * S_LEN + s0 + tx] = t[tx][ty + i];
    }
}

// =====================================================================
// single-fp16 tensor-core GEMM.
// CTA 128x128, K-chunk 64, 2-stage cp.async.
// =====================================================================
#define STAGE_B 32768
#define GEMM_SMEM (2 * STAGE_B)

__global__ void __launch_bounds__(256, 2) gemm_f16(
    const __half* __restrict__ A, const __half* __restrict__ B,
    __half* __restrict__ C16, float* __restrict__ C0, float* __restrict__ C1,
    int ldC, int kLen)
{
    extern __shared__ char smem[];
    const uint32_t sb = smem_u32(smem);

    const int tid  = threadIdx.x;
    const int wid  = tid >> 5;
    const int lane = tid & 31;
    const int wm   = wid & 1;
    const int wn   = wid >> 1;
    const int m0 = blockIdx.y * 128;
    const int n0 = blockIdx.x * 128;
    const int kOff = blockIdx.z * kLen;

    float acc[4][4][4];
#pragma unroll
    for (int i = 0; i < 4; i++)
#pragma unroll
        for (int j = 0; j < 4; j++)
#pragma unroll
            for (int c = 0; c < 4; c++) acc[i][j][c] = 0.f;

    const int r  = tid >> 1;
    const int h2 = tid & 1;
    uint32_t dofs[4];
#pragma unroll
    for (int s = 0; s < 4; s++)
        dofs[s] = SWZ128((uint32_t)(r * 128 + h2 * 64 + s * 16));
    const __half* gA = A + (size_t)(m0 + r) * DMODEL + kOff + h2 * 32;
    const __half* gB = B + (size_t)(n0 + r) * DMODEL + kOff + h2 * 32;

    const int aRow = wm * 64 + (lane & 15);
    const int bRow = wn * 32 + (lane & 15);
    const int kb   = (lane >> 4) << 4;

    const int NCH = kLen / 64;

#define LOAD_STAGE(kc, st)                                                  \
    do {                                                                    \
        const uint32_t base = sb + (uint32_t)(st) * STAGE_B;                \
        _Pragma("unroll")                                                   \
        for (int s = 0; s < 4; s++) {                                       \
            cp16(base + dofs[s],         gA + (kc) + s * 8);                \
            cp16(base + 16384 + dofs[s], gB + (kc) + s * 8);                \
        }                                                                   \
    } while (0)

    LOAD_STAGE(0, 0);
    cp_commit();

    for (int it = 0; it < NCH; it++) {
        if (it + 1 < NCH) {
            LOAD_STAGE((it + 1) * 64, (it + 1) & 1);
            cp_commit();
            cp_wait<1>();
        } else {
            cp_wait<0>();
        }
        __syncthreads();

        const uint32_t bA = sb + (uint32_t)(it & 1) * STAGE_B;
        const uint32_t bB = bA + 16384;

#pragma unroll
        for (int kk = 0; kk < 4; kk++) {
            const uint32_t kby = (uint32_t)(kk * 32 + kb);
            uint32_t ah[4][4];
#pragma unroll
            for (int mt = 0; mt < 4; mt++) {
                const uint32_t row = (uint32_t)(aRow + mt * 16) * 128;
                ldsm_x4(ah[mt], bA + SWZ128(row + kby));
            }
#pragma unroll
            for (int ntp = 0; ntp < 2; ntp++) {
                const uint32_t row = (uint32_t)(bRow + ntp * 16) * 128;
                uint32_t bb[4];
                ldsm_x4(bb, bB + SWZ128(row + kby));
#pragma unroll
                for (int half = 0; half < 2; half++) {
                    const int nt = ntp * 2 + half;
                    uint32_t bf[2] = {bb[half], bb[half + 2]};
#pragma unroll
                    for (int mt = 0; mt < 4; mt++)
                        mma_f16(acc[mt][nt], ah[mt], bf);
                }
            }
        }
        __syncthreads();
    }

    const int g  = lane >> 2;
    const int tg = lane & 3;
    if (C16) {
#pragma unroll
        for (int mt = 0; mt < 4; mt++) {
#pragma unroll
            for (int half = 0; half < 2; half++) {
                const int m = m0 + wm * 64 + mt * 16 + g + half * 8;
                __half* cp = C16 + (size_t)m * ldC + n0 + wn * 32;
#pragma unroll
                for (int nt = 0; nt < 4; nt++) {
                    const int col = nt * 8 + tg * 2;
                    *(uint32_t*)(cp + col) =
                        pack_hf2(acc[mt][nt][half * 2], acc[mt][nt][half * 2 + 1]);
                }
            }
        }
    } else {
        float* __restrict__ C = blockIdx.z ? C1 : C0;
#pragma unroll
        for (int mt = 0; mt < 4; mt++) {
#pragma unroll
            for (int half = 0; half < 2; half++) {
                const int m = m0 + wm * 64 + mt * 16 + g + half * 8;
                float* cp = C + (size_t)m * ldC + n0 + wn * 32;
#pragma unroll
                for (int nt = 0; nt < 4; nt++) {
                    const int col = nt * 8 + tg * 2;
                    *(float2*)(cp + col) =
                        make_float2(acc[mt][nt][half * 2], acc[mt][nt][half * 2 + 1]);
                }
            }
        }
    }
}

// =====================================================================
// Windowed causal flash attention, FA2-style register softmax.
// q-tile 64, grid = (NHEADS, S_LEN/64), 128 threads = 4 warps.
// Each warp owns 16 q-rows x ALL 64 keys; interior chunks skip masking
// entirely (warp-uniform branch).
// smem: Q 8KB + K 2x8KB + V 2x8KB = 40KB -> 4 CTAs/SM.
// =====================================================================
#define AQ  0u
#define AK0 8192u
#define AK1 16384u
#define AV0 24576u
#define AV1 32768u
#define ATT_SMEM 40960

__global__ void __launch_bounds__(128, 4) attn_kernel()
{
    extern __shared__ char sm[];
    const uint32_t sb = smem_u32(sm);

    const int h   = blockIdx.x;
    const int q0  = blockIdx.y * 64;
    const int tid = threadIdx.x;
    const int wid = tid >> 5, lane = tid & 31;
    const int g = lane >> 2, tg = lane & 3;
    const int wrow = wid * 16;

    // K/V tile loader: 64 rows x 128B, 2 threads/row, 4 x 16B each
    const int r2 = tid >> 1;
    const int s2 = (tid & 1) * 4;
    uint32_t tdofs[4];
#pragma unroll
    for (int s = 0; s < 4; s++)
        tdofs[s] = SWZ128((uint32_t)(r2 * 128 + (s2 + s) * 16));
#define ATL(dstbase, srcptr)                                   \
    do {                                                       \
        _Pragma("unroll")                                      \
        for (int s = 0; s < 4; s++)                            \
            cp16((dstbase) + tdofs[s], (srcptr) + s * 8);      \
    } while (0)

    const int kstart = (q0 - WINDOW) < 0 ? 0 : (q0 - WINDOW);
    const int nch = (q0 + 64 - kstart) / 64;

    // prologue: Q + K0 + V0  (Q uses same 2-thread/row mapping)
    ATL(sb + AQ,  g_q + (size_t)(q0 + r2) * DMODEL + h * 64 + s2 * 8);
    ATL(sb + AK0, g_k + (size_t)(kstart + r2) * DMODEL + h * 64 + s2 * 8);
    ATL(sb + AV0, g_v + (size_t)(h * 64 + r2) * S_LEN + kstart + s2 * 8);
    cp_commit();

    float o[8][4];
#pragma unroll
    for (int nt = 0; nt < 8; nt++)
#pragma unroll
        for (int c = 0; c < 4; c++) o[nt][c] = 0.f;
    float m0_ = -1e30f, m1_ = -1e30f, l0_ = 0.f, l1_ = 0.f;

    const int aRow = wrow + (lane & 15);
    const int bR15 = lane & 15;
    const int kb   = (lane >> 4) << 4;
    const int qrow0 = q0 + wrow + g;
    const int qrow1 = qrow0 + 8;
    const int qlo = q0 + wrow;          // warp's lowest row
    const int qhi = qlo + 15;           // warp's highest row

    for (int it = 0; it < nch; it++) {
        const int kc = kstart + it * 64;
        const uint32_t KB = (it & 1) ? AK1 : AK0;
        const uint32_t VB = (it & 1) ? AV1 : AV0;
        const bool pf = (it + 1 < nch);

        cp_wait<0>();
        __syncthreads();
        if (pf) {
            const uint32_t KBn = (it & 1) ? AK0 : AK1;
            const uint32_t VBn = (it & 1) ? AV0 : AV1;
            ATL(sb + KBn, g_k + (size_t)(kc + 64 + r2) * DMODEL + h * 64 + s2 * 8);
            ATL(sb + VBn, g_v + (size_t)(h * 64 + r2) * S_LEN + kc + 64 + s2 * 8);
            cp_commit();
        }

        // ---- S = Q K^T : warp computes m16 x n64 ----
        float sacc[8][4];
#pragma unroll
        for (int nt = 0; nt < 8; nt++)
#pragma unroll
            for (int c = 0; c < 4; c++) sacc[nt][c] = 0.f;

#pragma unroll
        for (int kk = 0; kk < 4; kk++) {
            const uint32_t kby = (uint32_t)(kk * 32 + kb);
            uint32_t a[4];
            ldsm_x4(a, sb + AQ + SWZ128((uint32_t)aRow * 128 + kby));
#pragma unroll
            for (int ntp = 0; ntp < 4; ntp++) {
                uint32_t bb[4];
                ldsm_x4(bb, sb + KB + SWZ128((uint32_t)(ntp * 16 + bR15) * 128 + kby));
#pragma unroll
                for (int half = 0; half < 2; half++) {
                    uint32_t bf[2] = {bb[half], bb[half + 2]};
                    mma_f16(sacc[ntp * 2 + half], a, bf);
                }
            }
        }

        // ---- masking: warp-uniform skip for fully-interior chunks ----
        const bool needMask = !((kc + 63 <= qlo) && (kc >= qhi - WINDOW));
        if (needMask) {
#pragma unroll
            for (int nt = 0; nt < 8; nt++) {
                const int key0 = kc + nt * 8 + tg * 2;
                const int key1 = key0 + 1;
                const bool ok00 = (key0 <= qrow0) && (qrow0 - key0 <= WINDOW);
                const bool ok01 = (key1 <= qrow0) && (qrow0 - key1 <= WINDOW);
                const bool ok10 = (key0 <= qrow1) && (qrow1 - key0 <= WINDOW);
                const bool ok11 = (key1 <= qrow1) && (qrow1 - key1 <= WINDOW);
                sacc[nt][0] = ok00 ? sacc[nt][0] : -1e30f;
                sacc[nt][1] = ok01 ? sacc[nt][1] : -1e30f;
                sacc[nt][2] = ok10 ? sacc[nt][2] : -1e30f;
                sacc[nt][3] = ok11 ? sacc[nt][3] : -1e30f;
            }
        }

        // ---- warp-local online softmax ----
        float rmax0 = -1e30f, rmax1 = -1e30f;
#pragma unroll
        for (int nt = 0; nt < 8; nt++) {
            rmax0 = fmaxf(rmax0, fmaxf(sacc[nt][0], sacc[nt][1]));
            rmax1 = fmaxf(rmax1, fmaxf(sacc[nt][2], sacc[nt][3]));
        }
        rmax0 = fmaxf(rmax0, __shfl_xor_sync(0xffffffffu, rmax0, 1));
        rmax0 = fmaxf(rmax0, __shfl_xor_sync(0xffffffffu, rmax0, 2));
        rmax1 = fmaxf(rmax1, __shfl_xor_sync(0xffffffffu, rmax1, 1));
        rmax1 = fmaxf(rmax1, __shfl_xor_sync(0xffffffffu, rmax1, 2));

        const float mn0 = fmaxf(m0_, rmax0);
        const float mn1 = fmaxf(m1_, rmax1);
        const float sc0 = __expf(m0_ - mn0);
        const float sc1 = __expf(m1_ - mn1);
        float rs0 = 0.f, rs1 = 0.f;
#pragma unroll
        for (int nt = 0; nt < 8; nt++) {
            sacc[nt][0] = __expf(sacc[nt][0] - mn0);
            sacc[nt][1] = __expf(sacc[nt][1] - mn0);
            sacc[nt][2] = __expf(sacc[nt][2] - mn1);
            sacc[nt][3] = __expf(sacc[nt][3] - mn1);
            rs0 += sacc[nt][0] + sacc[nt][1];
            rs1 += sacc[nt][2] + sacc[nt][3];
        }
        rs0 += __shfl_xor_sync(0xffffffffu, rs0, 1);
        rs0 += __shfl_xor_sync(0xffffffffu, rs0, 2);
        rs1 += __shfl_xor_sync(0xffffffffu, rs1, 1);
        rs1 += __shfl_xor_sync(0xffffffffu, rs1, 2);
        l0_ = l0_ * sc0 + rs0; m0_ = mn0;
        l1_ = l1_ * sc1 + rs1; m1_ = mn1;

#pragma unroll
        for (int nt = 0; nt < 8; nt++) {
            o[nt][0] *= sc0; o[nt][1] *= sc0;
            o[nt][2] *= sc1; o[nt][3] *= sc1;
        }

        // ---- O += P V  (P in-register from sacc C-frags) ----
#pragma unroll
        for (int kk = 0; kk < 4; kk++) {
            uint32_t pa[4];
            pa[0] = pack_hf2(sacc[2 * kk][0],     sacc[2 * kk][1]);
            pa[1] = pack_hf2(sacc[2 * kk][2],     sacc[2 * kk][3]);
            pa[2] = pack_hf2(sacc[2 * kk + 1][0], sacc[2 * kk + 1][1]);
            pa[3] = pack_hf2(sacc[2 * kk + 1][2], sacc[2 * kk + 1][3]);
            const uint32_t kby = (uint32_t)(kk * 32 + kb);
#pragma unroll
            for (int ntp = 0; ntp < 4; ntp++) {
                uint32_t bb[4];
                ldsm_x4(bb, sb + VB + SWZ128((uint32_t)(ntp * 16 + bR15) * 128 + kby));
#pragma unroll
                for (int half = 0; half < 2; half++) {
                    uint32_t bf[2] = {bb[half], bb[half + 2]};
                    mma_f16(o[ntp * 2 + half], pa, bf);
                }
            }
        }
    }

    const float iv0 = 1.f / l0_;
    const float iv1 = 1.f / l1_;
#pragma unroll
    for (int nt = 0; nt < 8; nt++) {
        const int col = h * 64 + nt * 8 + tg * 2;
        *(uint32_t*)(g_a16 + (size_t)qrow0 * DMODEL + col) =
            pack_hf2(o[nt][0] * iv0, o[nt][1] * iv0);
        *(uint32_t*)(g_a16 + (size_t)qrow1 * DMODEL + col) =
            pack_hf2(o[nt][2] * iv1, o[nt][3] * iv1);
    }
}

// =====================================================================
// LayerNorm with fused residual + split-K reduce
// =====================================================================
__global__ void __launch_bounds__(256) ln_kernel(
    const float* __restrict__ x,
    const float* __restrict__ gamma, const float* __restrict__ beta,
    float* __restrict__ y)
{
    const int s = blockIdx.x;
    const int tid = threadIdx.x;
    const size_t base = (size_t)s * DMODEL + tid * 4;

    float4 xv = *(const float4*)(x + base);
    float4 a  = *(const float4*)(g_o0 + base);
    float4 b4 = *(const float4*)(g_o1 + base);
    xv.x += a.x + b4.x;
    xv.y += a.y + b4.y;
    xv.z += a.z + b4.z;
    xv.w += a.w + b4.w;

    float s1 = xv.x + xv.y + xv.z + xv.w;
    float s2 = xv.x * xv.x + xv.y * xv.y + xv.z * xv.z + xv.w * xv.w;
#pragma unroll
    for (int o = 16; o >= 1; o >>= 1) {
        s1 += __shfl_xor_sync(0xffffffffu, s1, o);
        s2 += __shfl_xor_sync(0xffffffffu, s2, o);
    }
    __shared__ float a1[8], a2[8];
    const int w = tid >> 5, lane = tid & 31;
    if (lane == 0) { a1[w] = s1; a2[w] = s2; }
    __syncthreads();
    float t1 = 0.f, t2 = 0.f;
#pragma unroll
    for (int i = 0; i < 8; i++) { t1 += a1[i]; t2 += a2[i]; }

    const float mu  = t1 * (1.0f / DMODEL);
    const float var = t2 * (1.0f / DMODEL) - mu * mu;
    const float rstd = rsqrtf(var + LN_EPS);

    const int c = tid * 4;
    float4 gm = *(const float4*)(gamma + c);
    float4 bt = *(const float4*)(beta + c);
    float4 o;
    o.x = (xv.x - mu) * rstd * gm.x + bt.x;
    o.y = (xv.y - mu) * rstd * gm.y + bt.y;
    o.z = (xv.z - mu) * rstd * gm.z + bt.z;
    o.w = (xv.w - mu) * rstd * gm.w + bt.w;
    *(float4*)(y + (size_t)s * DMODEL + c) = o;
}

// =====================================================================
// launch — single stream, fused prep kernels
// =====================================================================
extern "C" void kernel_launch(void* const* d_in, const int* in_sizes, int n_in,
                              void* d_out, int out_size)
{
    const float* x     = (const float*)d_in[0];
    const float* state = (const float*)d_in[1];
    const float* Wqkv  = (const float*)d_in[2];
    const float* Wout  = (const float*)d_in[3];
    const float* gamma = (const float*)d_in[4];
    const float* beta  = (const float*)d_in[5];
    float* y = (float*)d_out;

    float *o0, *o1;
    __half *qkv16, *x16, *a16, *wq, *wo;
    cudaGetSymbolAddress((void**)&o0,    g_o0);
    cudaGetSymbolAddress((void**)&o1,    g_o1);
    cudaGetSymbolAddress((void**)&qkv16, g_qkv16);
    cudaGetSymbolAddress((void**)&x16,   g_x16);
    cudaGetSymbolAddress((void**)&a16,   g_a16);
    cudaGetSymbolAddress((void**)&wq,    g_wq);
    cudaGetSymbolAddress((void**)&wo,    g_wo);

    cudaFuncSetAttribute(gemm_f16, cudaFuncAttributeMaxDynamicSharedMemorySize, GEMM_SMEM);
    cudaFuncSetAttribute(attn_kernel, cudaFuncAttributeMaxDynamicSharedMemorySize, ATT_SMEM);

    // 0) fused prep: Wqkv^T + Wout^T + x->fp16, one launch
    prep_kernel<<<4608, 256>>>(x, Wqkv, Wout);

    // 1) QKV projection -> fp16 qkv (full K)
    gemm_f16<<<dim3(3 * DMODEL / 128, S_LEN / 128, 1), 256, GEMM_SMEM>>>(
        x16, wq, qkv16, nullptr, nullptr, 3 * DMODEL, DMODEL);

    // 2) fused RoPE + V transpose, one launch
    ropev_kernel<<<6144, 256>>>();

    // 3) windowed attention (q-tile 64, 4 warps, mask-skip)
    attn_kernel<<<dim3(NHEADS, S_LEN / 64), 128, ATT_SMEM>>>();

    // 4) output projection, split-K=2 -> o0, o1
    gemm_f16<<<dim3(DMODEL / 128, S_LEN / 128, 2), 256, GEMM_SMEM>>>(
        a16, wo, nullptr, o0, o1, DMODEL, DMODEL / 2);

    // 5) LayerNorm (fused residual + split-K reduce) -> y
    ln_kernel<<<S_LEN, 256>>>(x, gamma, beta, y);

    // 6) pass-through state if the output buffer includes it
    if (out_size >= S_LEN * DMODEL + DMODEL) {
        cudaMemcpyAsync(y + (size_t)S_LEN * DMODEL, state,
                        DMODEL * sizeof(float), cudaMemcpyDeviceToDevice);
    }
}